// round 1
// baseline (speedup 1.0000x reference)
#include <cuda_runtime.h>
#include <cstdint>

#define NNODES 10000
#define FDIM   256      // input feature dim == w_h cols
#define DDIM   512      // GAT output dim (H*OUT)
#define NEDGE  160000
#define NHEAD  8
#define SEMH   128
#define OSZ    64

// ---------------- scratch (static device globals; no allocation) ----------------
__device__ float g_wh  [NNODES * FDIM];
__device__ float g_feat[NNODES * DDIM];
__device__ float g_z0  [NNODES * DDIM];
__device__ float g_z1  [NNODES * DDIM];
__device__ float g_el  [NNODES * NHEAD];
__device__ float g_er  [NNODES * NHEAD];
__device__ int   g_mx  [NNODES * NHEAD];
__device__ float g_sm  [NNODES * NHEAD];
__device__ float g_ex  [NEDGE * NHEAD];
__device__ float g_sc  [NNODES * SEMH];
__device__ float g_w0  [NNODES];
__device__ float g_w1  [NNODES];
__device__ float g_fu  [NNODES * DDIM];

// ---------------- SGEMM 128x128x8, 8x8 per thread ----------------
#define BM 128
#define BN 128
#define BK 8
#define TM 8
#define TN 8

__global__ __launch_bounds__(256) void sgemm_nn(const float* __restrict__ A,
                                                const float* __restrict__ B,
                                                float* __restrict__ C,
                                                int M, int N, int K) {
    __shared__ float As[BK][BM];
    __shared__ float Bs[BK][BN];
    int tid = threadIdx.x;
    int tx = tid & 15, ty = tid >> 4;
    int row0 = blockIdx.y * BM, col0 = blockIdx.x * BN;
    int aRow = tid >> 1, aCol = (tid & 1) * 4;   // A tile: 128 rows x 8 cols
    int bRow = tid >> 5, bCol = (tid & 31) * 4;  // B tile: 8 rows x 128 cols

    float acc[TM][TN];
#pragma unroll
    for (int i = 0; i < TM; i++)
#pragma unroll
        for (int j = 0; j < TN; j++) acc[i][j] = 0.f;

    for (int k0 = 0; k0 < K; k0 += BK) {
        float4 a4 = make_float4(0.f, 0.f, 0.f, 0.f);
        if (row0 + aRow < M)
            a4 = *(const float4*)(A + (size_t)(row0 + aRow) * K + k0 + aCol);
        As[aCol + 0][aRow] = a4.x;
        As[aCol + 1][aRow] = a4.y;
        As[aCol + 2][aRow] = a4.z;
        As[aCol + 3][aRow] = a4.w;

        float4 b4 = make_float4(0.f, 0.f, 0.f, 0.f);
        if (col0 + bCol < N)
            b4 = *(const float4*)(B + (size_t)(k0 + bRow) * N + col0 + bCol);
        *(float4*)&Bs[bRow][bCol] = b4;
        __syncthreads();

#pragma unroll
        for (int k = 0; k < BK; k++) {
            float ar_[TM], br_[TN];
#pragma unroll
            for (int i = 0; i < TM; i++) ar_[i] = As[k][ty * TM + i];
#pragma unroll
            for (int j = 0; j < TN; j++) br_[j] = Bs[k][tx * TN + j];
#pragma unroll
            for (int i = 0; i < TM; i++)
#pragma unroll
                for (int j = 0; j < TN; j++)
                    acc[i][j] = fmaf(ar_[i], br_[j], acc[i][j]);
        }
        __syncthreads();
    }

#pragma unroll
    for (int i = 0; i < TM; i++) {
        int r = row0 + ty * TM + i;
        if (r >= M) continue;
#pragma unroll
        for (int j = 0; j < TN; j += 4) {
            int c = col0 + tx * TN + j;
            if (c < N)
                *(float4*)(C + (size_t)r * N + c) =
                    make_float4(acc[i][j], acc[i][j + 1], acc[i][j + 2], acc[i][j + 3]);
        }
    }
}

// C[M,N] = A[M,K] * B[N,K]^T   (row-major A, row-major B)
__global__ __launch_bounds__(256) void sgemm_nt(const float* __restrict__ A,
                                                const float* __restrict__ B,
                                                float* __restrict__ C,
                                                int M, int N, int K) {
    __shared__ float As[BK][BM];
    __shared__ float Bs[BK][BN];
    int tid = threadIdx.x;
    int tx = tid & 15, ty = tid >> 4;
    int row0 = blockIdx.y * BM, col0 = blockIdx.x * BN;
    int aRow = tid >> 1, aCol = (tid & 1) * 4;
    int bRowN = tid >> 1, bK = (tid & 1) * 4;

    float acc[TM][TN];
#pragma unroll
    for (int i = 0; i < TM; i++)
#pragma unroll
        for (int j = 0; j < TN; j++) acc[i][j] = 0.f;

    for (int k0 = 0; k0 < K; k0 += BK) {
        float4 a4 = make_float4(0.f, 0.f, 0.f, 0.f);
        if (row0 + aRow < M)
            a4 = *(const float4*)(A + (size_t)(row0 + aRow) * K + k0 + aCol);
        As[aCol + 0][aRow] = a4.x;
        As[aCol + 1][aRow] = a4.y;
        As[aCol + 2][aRow] = a4.z;
        As[aCol + 3][aRow] = a4.w;

        float4 b4 = make_float4(0.f, 0.f, 0.f, 0.f);
        if (col0 + bRowN < N)
            b4 = *(const float4*)(B + (size_t)(col0 + bRowN) * K + k0 + bK);
        Bs[bK + 0][bRowN] = b4.x;
        Bs[bK + 1][bRowN] = b4.y;
        Bs[bK + 2][bRowN] = b4.z;
        Bs[bK + 3][bRowN] = b4.w;
        __syncthreads();

#pragma unroll
        for (int k = 0; k < BK; k++) {
            float ar_[TM], br_[TN];
#pragma unroll
            for (int i = 0; i < TM; i++) ar_[i] = As[k][ty * TM + i];
#pragma unroll
            for (int j = 0; j < TN; j++) br_[j] = Bs[k][tx * TN + j];
#pragma unroll
            for (int i = 0; i < TM; i++)
#pragma unroll
                for (int j = 0; j < TN; j++)
                    acc[i][j] = fmaf(ar_[i], br_[j], acc[i][j]);
        }
        __syncthreads();
    }

#pragma unroll
    for (int i = 0; i < TM; i++) {
        int r = row0 + ty * TM + i;
        if (r >= M) continue;
#pragma unroll
        for (int j = 0; j < TN; j += 4) {
            int c = col0 + tx * TN + j;
            if (c < N)
                *(float4*)(C + (size_t)r * N + c) =
                    make_float4(acc[i][j], acc[i][j + 1], acc[i][j + 2], acc[i][j + 3]);
        }
    }
}

// ---------------- GAT kernels ----------------

// per (node, head) warp: el/er dot products + init max/sum accumulators
__global__ void eler_kernel(const float* __restrict__ feat,
                            const float* __restrict__ al,
                            const float* __restrict__ ar,
                            float* __restrict__ el, float* __restrict__ er,
                            int* __restrict__ mx, float* __restrict__ sm) {
    int w = blockIdx.x * 8 + (threadIdx.x >> 5);
    int lane = threadIdx.x & 31;
    if (w >= NNODES * NHEAD) return;
    int n = w >> 3, h = w & 7;
    const float* f = feat + (size_t)n * DDIM + h * 64;
    float sl = f[lane] * al[h * 64 + lane] + f[lane + 32] * al[h * 64 + lane + 32];
    float sr = f[lane] * ar[h * 64 + lane] + f[lane + 32] * ar[h * 64 + lane + 32];
#pragma unroll
    for (int o = 16; o > 0; o >>= 1) {
        sl += __shfl_down_sync(0xffffffffu, sl, o);
        sr += __shfl_down_sync(0xffffffffu, sr, o);
    }
    if (lane == 0) {
        el[w] = sl;
        er[w] = sr;
        mx[w] = (int)0x80000000;  // below every order-mapped float
        sm[w] = 0.f;
    }
}

__device__ __forceinline__ int f2ord(float v) {
    int k = __float_as_int(v);
    return k >= 0 ? k : (k ^ 0x7FFFFFFF);
}
__device__ __forceinline__ float ord2f(int k) {
    return __int_as_float(k >= 0 ? k : (k ^ 0x7FFFFFFF));
}

__global__ void edge_max_kernel(const int* __restrict__ ed,
                                const float* __restrict__ el,
                                const float* __restrict__ er,
                                float* __restrict__ ex, int* __restrict__ mx) {
    int i = blockIdx.x * blockDim.x + threadIdx.x;
    if (i >= NEDGE * NHEAD) return;
    int e = i >> 3, h = i & 7;
    int s = ed[e], d = ed[NEDGE + e];
    float v = el[s * NHEAD + h] + er[d * NHEAD + h];
    v = v > 0.f ? v : 0.2f * v;  // leaky_relu 0.2
    ex[i] = v;
    atomicMax(&mx[d * NHEAD + h], f2ord(v));
}

__global__ void edge_exp_kernel(const int* __restrict__ ed,
                                float* __restrict__ ex,
                                const int* __restrict__ mx,
                                float* __restrict__ sm) {
    int i = blockIdx.x * blockDim.x + threadIdx.x;
    if (i >= NEDGE * NHEAD) return;
    int e = i >> 3, h = i & 7;
    int d = ed[NEDGE + e];
    float v = __expf(ex[i] - ord2f(mx[d * NHEAD + h]));
    ex[i] = v;
    atomicAdd(&sm[d * NHEAD + h], v);
}

__global__ void edge_norm_kernel(const int* __restrict__ ed,
                                 float* __restrict__ ex,
                                 const float* __restrict__ sm) {
    int i = blockIdx.x * blockDim.x + threadIdx.x;
    if (i >= NEDGE * NHEAD) return;
    int e = i >> 3, h = i & 7;
    int d = ed[NEDGE + e];
    ex[i] = ex[i] / sm[d * NHEAD + h];
}

// thread per (edge, 4 features): rst[dst] += feat[src] * alpha
__global__ void edge_agg_kernel(const int* __restrict__ ed,
                                const float* __restrict__ ex,
                                const float* __restrict__ feat,
                                float* __restrict__ rst) {
    int i = blockIdx.x * blockDim.x + threadIdx.x;
    if (i >= NEDGE * (DDIM / 4)) return;
    int e = i >> 7;          // DDIM/4 = 128 quads per edge
    int q = i & 127;
    int c = q * 4;
    int h = c >> 6;
    int s = ed[e], d = ed[NEDGE + e];
    float alpha = ex[e * NHEAD + h];
    float4 f = *(const float4*)(feat + (size_t)s * DDIM + c);
    float* out = rst + (size_t)d * DDIM + c;
    atomicAdd(out + 0, f.x * alpha);
    atomicAdd(out + 1, f.y * alpha);
    atomicAdd(out + 2, f.z * alpha);
    atomicAdd(out + 3, f.w * alpha);
}

__global__ void elu_bias_kernel(float* __restrict__ rst, const float* __restrict__ bias) {
    int i = blockIdx.x * blockDim.x + threadIdx.x;
    if (i >= NNODES * DDIM) return;
    float v = rst[i] + bias[i & (DDIM - 1)];
    rst[i] = v > 0.f ? v : (__expf(v) - 1.f);
}

// ---------------- semantic attention ----------------

// per node warp: w = sum_j tanh(H[n,j]+b1[j]) * W2[j]
__global__ void sem_score_kernel(const float* __restrict__ Hm,
                                 const float* __restrict__ b1,
                                 const float* __restrict__ W2,
                                 float* __restrict__ out) {
    int w = blockIdx.x * 8 + (threadIdx.x >> 5);
    int lane = threadIdx.x & 31;
    if (w >= NNODES) return;
    float t = 0.f;
#pragma unroll
    for (int q = 0; q < 4; q++) {
        int j = lane + 32 * q;
        t += tanhf(Hm[(size_t)w * SEMH + j] + b1[j]) * W2[j];
    }
#pragma unroll
    for (int o = 16; o > 0; o >>= 1) t += __shfl_down_sync(0xffffffffu, t, o);
    if (lane == 0) out[w] = t;
}

__global__ void fuse_kernel(const float* __restrict__ z0, const float* __restrict__ z1,
                            const float* __restrict__ w0, const float* __restrict__ w1,
                            float* __restrict__ fu) {
    int i = blockIdx.x * blockDim.x + threadIdx.x;
    if (i >= NNODES * DDIM) return;
    int n = i >> 9;
    float a = w0[n], b = w1[n];
    float m = fmaxf(a, b);
    float ea = __expf(a - m), eb = __expf(b - m);
    float be = ea / (ea + eb);
    fu[i] = be * z0[i] + (1.f - be) * z1[i];
}

// ---------------- host orchestration ----------------

static void gemm_nn(const float* A, const float* B, float* C, int M, int N, int K) {
    dim3 g((N + BN - 1) / BN, (M + BM - 1) / BM);
    sgemm_nn<<<g, 256>>>(A, B, C, M, N, K);
}
static void gemm_nt(const float* A, const float* B, float* C, int M, int N, int K) {
    dim3 g((N + BN - 1) / BN, (M + BM - 1) / BM);
    sgemm_nt<<<g, 256>>>(A, B, C, M, N, K);
}

struct Scratch {
    float *wh, *feat, *z0, *z1, *el, *er, *sm, *ex, *sc, *w0, *w1, *fu;
    int* mx;
};

static void run_gat(const Scratch& S, const float* fc, const float* al, const float* ar,
                    const float* bias, const int* ed, float* z) {
    // feat = wh @ fc
    gemm_nn(S.wh, fc, S.feat, NNODES, DDIM, FDIM);
    cudaMemsetAsync(z, 0, (size_t)NNODES * DDIM * sizeof(float), 0);
    eler_kernel<<<NNODES, 256>>>(S.feat, al, ar, S.el, S.er, S.mx, S.sm);
    int egrid = (NEDGE * NHEAD + 255) / 256;
    edge_max_kernel<<<egrid, 256>>>(ed, S.el, S.er, S.ex, S.mx);
    edge_exp_kernel<<<egrid, 256>>>(ed, S.ex, S.mx, S.sm);
    edge_norm_kernel<<<egrid, 256>>>(ed, S.ex, S.sm);
    int agrid = (NEDGE * (DDIM / 4) + 255) / 256;
    edge_agg_kernel<<<agrid, 256>>>(ed, S.ex, S.feat, z);
    elu_bias_kernel<<<(NNODES * DDIM + 255) / 256, 256>>>(z, bias);
}

static void run_branch(const Scratch& S, const float* x, void* const* d_in, int base,
                       const int* e0, const int* e1, float* h_out) {
    const float* w_h  = (const float*)d_in[base + 0];
    const float* fc   = (const float*)d_in[base + 1];
    const float* al   = (const float*)d_in[base + 2];
    const float* ar   = (const float*)d_in[base + 3];
    const float* bias = (const float*)d_in[base + 4];
    const float* W1   = (const float*)d_in[base + 5];
    const float* b1   = (const float*)d_in[base + 6];
    const float* W2   = (const float*)d_in[base + 7];
    const float* pred = (const float*)d_in[base + 8];

    // shared input projection
    gemm_nn(x, w_h, S.wh, NNODES, FDIM, FDIM);

    // two metapath GATs
    run_gat(S, fc,                 al,             ar,             bias,        e0, S.z0);
    run_gat(S, fc + FDIM * DDIM,   al + NHEAD*64,  ar + NHEAD*64,  bias + DDIM, e1, S.z1);

    // semantic attention
    gemm_nn(S.z0, W1, S.sc, NNODES, SEMH, DDIM);
    sem_score_kernel<<<(NNODES + 7) / 8, 256>>>(S.sc, b1, W2, S.w0);
    gemm_nn(S.z1, W1, S.sc, NNODES, SEMH, DDIM);
    sem_score_kernel<<<(NNODES + 7) / 8, 256>>>(S.sc, b1, W2, S.w1);
    fuse_kernel<<<(NNODES * DDIM + 255) / 256, 256>>>(S.z0, S.z1, S.w0, S.w1, S.fu);

    // prediction head
    gemm_nn(S.fu, pred, h_out, NNODES, OSZ, DDIM);
}

extern "C" void kernel_launch(void* const* d_in, const int* in_sizes, int n_in,
                              void* d_out, int out_size) {
    Scratch S;
    cudaGetSymbolAddress((void**)&S.wh,   g_wh);
    cudaGetSymbolAddress((void**)&S.feat, g_feat);
    cudaGetSymbolAddress((void**)&S.z0,   g_z0);
    cudaGetSymbolAddress((void**)&S.z1,   g_z1);
    cudaGetSymbolAddress((void**)&S.el,   g_el);
    cudaGetSymbolAddress((void**)&S.er,   g_er);
    cudaGetSymbolAddress((void**)&S.mx,   g_mx);
    cudaGetSymbolAddress((void**)&S.sm,   g_sm);
    cudaGetSymbolAddress((void**)&S.ex,   g_ex);
    cudaGetSymbolAddress((void**)&S.sc,   g_sc);
    cudaGetSymbolAddress((void**)&S.w0,   g_w0);
    cudaGetSymbolAddress((void**)&S.w1,   g_w1);
    cudaGetSymbolAddress((void**)&S.fu,   g_fu);

    const float* hx = (const float*)d_in[0];
    const float* tx = (const float*)d_in[1];
    const int* eh0 = (const int*)d_in[20];
    const int* eh1 = (const int*)d_in[21];
    const int* et0 = (const int*)d_in[22];
    const int* et1 = (const int*)d_in[23];

    float* out  = (float*)d_out;
    float* h1   = out;
    float* h2   = out + (size_t)NNODES * OSZ;
    float* prod = out + (size_t)2 * NNODES * OSZ;

    run_branch(S, hx, d_in, 2,  eh0, eh1, h1);
    run_branch(S, tx, d_in, 11, et0, et1, h2);

    // h1 @ h2^T
    gemm_nt(h1, h2, prod, NNODES, NNODES, OSZ);
}

// round 2
// speedup vs baseline: 1.6899x; 1.6899x over previous
#include <cuda_runtime.h>
#include <cstdint>

#define NNODES 10000
#define FDIM   256
#define DDIM   512
#define NEDGE  160000
#define NHEAD  8
#define SEMH   128
#define OSZ    64

// ---------------- scratch (static device globals; no allocation) ----------------
__device__ float g_wh  [NNODES * FDIM];
__device__ float g_feat[NNODES * DDIM];
__device__ float g_z0  [NNODES * DDIM];
__device__ float g_z1  [NNODES * DDIM];
__device__ float g_el  [NNODES * NHEAD];
__device__ float g_er  [NNODES * NHEAD];
__device__ int   g_mx  [NNODES * NHEAD];
__device__ float g_sm  [NNODES * NHEAD];
__device__ float g_ex  [NEDGE * NHEAD];
__device__ float g_sc  [NNODES * SEMH];
__device__ float g_w0  [NNODES];
__device__ float g_w1  [NNODES];
__device__ float g_fu  [NNODES * DDIM];

// ---------------- tf32 MMA GEMM: 128x128 block tile, K-tile 16 ----------------
// 256 threads = 8 warps in 2(m) x 4(n); warp tile 64x32 = 4x4 mma(16x8) tiles.
// Shared memory holds tiles pre-permuted into mma fragment order so the
// mainloop does one LDS.128 per A fragment and one LDS.64 per B fragment,
// both conflict-free.

__device__ __forceinline__ unsigned f2tf(float f) {
    unsigned r;
    asm("cvt.rna.tf32.f32 %0, %1;" : "=r"(r) : "f"(f));
    return r;
}

template<bool TRANSB>
__global__ __launch_bounds__(256, 2) void mma_gemm(const float* __restrict__ A,
                                                   const float* __restrict__ B,
                                                   float* __restrict__ C,
                                                   int M, int N, int K) {
    // [kstep][mtile][lane][reg]
    __shared__ unsigned sA[2][8][32][4];
    // [kstep][ntile][lane][reg]
    __shared__ unsigned sB[2][16][32][2];

    int tid = threadIdx.x;
    int warp = tid >> 5, lane = tid & 31;
    int wm = warp >> 2, wn = warp & 3;
    int row0 = blockIdx.y * 128, col0 = blockIdx.x * 128;

    float acc[4][4][4];
#pragma unroll
    for (int i = 0; i < 4; i++)
#pragma unroll
        for (int j = 0; j < 4; j++)
#pragma unroll
            for (int q = 0; q < 4; q++) acc[i][j][q] = 0.f;

    for (int k0 = 0; k0 < K; k0 += 16) {
        // ---- load A tile 128x16 (512 float4, 2 per thread) into frag order ----
#pragma unroll
        for (int it = 0; it < 2; it++) {
            int i = tid * 2 + it;
            int r = i >> 2, c4 = i & 3;
            float4 v = make_float4(0.f, 0.f, 0.f, 0.f);
            int gr = row0 + r;
            if (gr < M)
                v = *(const float4*)(A + (size_t)gr * K + k0 + c4 * 4);
            int ks = c4 >> 1;
            int mt = r >> 4;
            int q  = ((r >> 3) & 1) + 2 * (c4 & 1);
            int tb = (r & 7) * 4;
            sA[ks][mt][tb + 0][q] = f2tf(v.x);
            sA[ks][mt][tb + 1][q] = f2tf(v.y);
            sA[ks][mt][tb + 2][q] = f2tf(v.z);
            sA[ks][mt][tb + 3][q] = f2tf(v.w);
        }
        // ---- load B tile into frag order ----
        if (!TRANSB) {
            // B[K][N] row-major: tile 16 x 128
#pragma unroll
            for (int it = 0; it < 2; it++) {
                int i = tid * 2 + it;
                int kr = i >> 5, c4 = i & 31;
                float4 v = make_float4(0.f, 0.f, 0.f, 0.f);
                int gc = col0 + c4 * 4;
                if (gc < N)
                    v = *(const float4*)(B + (size_t)(k0 + kr) * N + gc);
                int ks = kr >> 3;
                int kk = kr & 7;
                int q  = kk >> 2;
                int nt = c4 >> 1;
                int tb = 16 * (c4 & 1) + (kk & 3);
                sB[ks][nt][tb + 0 ][q] = f2tf(v.x);
                sB[ks][nt][tb + 4 ][q] = f2tf(v.y);
                sB[ks][nt][tb + 8 ][q] = f2tf(v.z);
                sB[ks][nt][tb + 12][q] = f2tf(v.w);
            }
        } else {
            // B[N][K] row-major: tile 128 n-rows x 16 k-cols
#pragma unroll
            for (int it = 0; it < 2; it++) {
                int i = tid * 2 + it;
                int nr = i >> 2, c4 = i & 3;
                float4 v = make_float4(0.f, 0.f, 0.f, 0.f);
                int gn = col0 + nr;
                if (gn < N)
                    v = *(const float4*)(B + (size_t)gn * K + k0 + c4 * 4);
                int ks = c4 >> 1;
                int q  = c4 & 1;
                int nt = nr >> 3;
                int tb = (nr & 7) * 4;
                sB[ks][nt][tb + 0][q] = f2tf(v.x);
                sB[ks][nt][tb + 1][q] = f2tf(v.y);
                sB[ks][nt][tb + 2][q] = f2tf(v.z);
                sB[ks][nt][tb + 3][q] = f2tf(v.w);
            }
        }
        __syncthreads();

#pragma unroll
        for (int ks = 0; ks < 2; ks++) {
            uint4 af[4];
            uint2 bf[4];
#pragma unroll
            for (int mt = 0; mt < 4; mt++)
                af[mt] = *(const uint4*)&sA[ks][wm * 4 + mt][lane][0];
#pragma unroll
            for (int nt = 0; nt < 4; nt++)
                bf[nt] = *(const uint2*)&sB[ks][wn * 4 + nt][lane][0];
#pragma unroll
            for (int mt = 0; mt < 4; mt++)
#pragma unroll
                for (int nt = 0; nt < 4; nt++) {
                    asm volatile(
                        "mma.sync.aligned.m16n8k8.row.col.f32.tf32.tf32.f32 "
                        "{%0,%1,%2,%3}, {%4,%5,%6,%7}, {%8,%9}, {%0,%1,%2,%3};"
                        : "+f"(acc[mt][nt][0]), "+f"(acc[mt][nt][1]),
                          "+f"(acc[mt][nt][2]), "+f"(acc[mt][nt][3])
                        : "r"(af[mt].x), "r"(af[mt].y), "r"(af[mt].z), "r"(af[mt].w),
                          "r"(bf[nt].x), "r"(bf[nt].y));
                }
        }
        __syncthreads();
    }

    // ---- epilogue ----
#pragma unroll
    for (int mt = 0; mt < 4; mt++) {
        int r_base = row0 + wm * 64 + mt * 16 + (lane >> 2);
#pragma unroll
        for (int nt = 0; nt < 4; nt++) {
            int c = col0 + wn * 32 + nt * 8 + (lane & 3) * 2;
            if (c < N) {
                if (r_base < M) {
                    float2 v = make_float2(acc[mt][nt][0], acc[mt][nt][1]);
                    *(float2*)(C + (size_t)r_base * N + c) = v;
                }
                if (r_base + 8 < M) {
                    float2 v = make_float2(acc[mt][nt][2], acc[mt][nt][3]);
                    *(float2*)(C + (size_t)(r_base + 8) * N + c) = v;
                }
            }
        }
    }
}

// ---------------- GAT kernels ----------------

__global__ void eler_kernel(const float* __restrict__ feat,
                            const float* __restrict__ al,
                            const float* __restrict__ ar,
                            float* __restrict__ el, float* __restrict__ er,
                            int* __restrict__ mx, float* __restrict__ sm) {
    int w = blockIdx.x * 8 + (threadIdx.x >> 5);
    int lane = threadIdx.x & 31;
    if (w >= NNODES * NHEAD) return;
    int n = w >> 3, h = w & 7;
    const float* f = feat + (size_t)n * DDIM + h * 64;
    float sl = f[lane] * al[h * 64 + lane] + f[lane + 32] * al[h * 64 + lane + 32];
    float sr = f[lane] * ar[h * 64 + lane] + f[lane + 32] * ar[h * 64 + lane + 32];
#pragma unroll
    for (int o = 16; o > 0; o >>= 1) {
        sl += __shfl_down_sync(0xffffffffu, sl, o);
        sr += __shfl_down_sync(0xffffffffu, sr, o);
    }
    if (lane == 0) {
        el[w] = sl;
        er[w] = sr;
        mx[w] = (int)0x80000000;
        sm[w] = 0.f;
    }
}

__device__ __forceinline__ int f2ord(float v) {
    int k = __float_as_int(v);
    return k >= 0 ? k : (k ^ 0x7FFFFFFF);
}
__device__ __forceinline__ float ord2f(int k) {
    return __int_as_float(k >= 0 ? k : (k ^ 0x7FFFFFFF));
}

__global__ void edge_max_kernel(const int* __restrict__ ed,
                                const float* __restrict__ el,
                                const float* __restrict__ er,
                                float* __restrict__ ex, int* __restrict__ mx) {
    int i = blockIdx.x * blockDim.x + threadIdx.x;
    if (i >= NEDGE * NHEAD) return;
    int e = i >> 3, h = i & 7;
    int s = ed[e], d = ed[NEDGE + e];
    float v = el[s * NHEAD + h] + er[d * NHEAD + h];
    v = v > 0.f ? v : 0.2f * v;
    ex[i] = v;
    atomicMax(&mx[d * NHEAD + h], f2ord(v));
}

__global__ void edge_exp_kernel(const int* __restrict__ ed,
                                float* __restrict__ ex,
                                const int* __restrict__ mx,
                                float* __restrict__ sm) {
    int i = blockIdx.x * blockDim.x + threadIdx.x;
    if (i >= NEDGE * NHEAD) return;
    int e = i >> 3, h = i & 7;
    int d = ed[NEDGE + e];
    float v = __expf(ex[i] - ord2f(mx[d * NHEAD + h]));
    ex[i] = v;
    atomicAdd(&sm[d * NHEAD + h], v);
}

// one thread per (edge, 4 consecutive features); alpha normalized on the fly;
// accumulate with a single red.global.add.v4.f32.
__global__ void edge_agg_kernel(const int* __restrict__ ed,
                                const float* __restrict__ ex,
                                const float* __restrict__ sm,
                                const float* __restrict__ feat,
                                float* __restrict__ rst) {
    int i = blockIdx.x * blockDim.x + threadIdx.x;
    if (i >= NEDGE * (DDIM / 4)) return;
    int e = i >> 7;
    int q = i & 127;
    int c = q * 4;
    int h = c >> 6;
    int s = ed[e], d = ed[NEDGE + e];
    float alpha = ex[e * NHEAD + h] / sm[d * NHEAD + h];
    float4 f = *(const float4*)(feat + (size_t)s * DDIM + c);
    float* out = rst + (size_t)d * DDIM + c;
    asm volatile("red.global.add.v4.f32 [%0], {%1,%2,%3,%4};"
                 :: "l"(out), "f"(f.x * alpha), "f"(f.y * alpha),
                    "f"(f.z * alpha), "f"(f.w * alpha)
                 : "memory");
}

__global__ void elu_bias_kernel(float* __restrict__ rst, const float* __restrict__ bias) {
    int i = blockIdx.x * blockDim.x + threadIdx.x;
    if (i >= NNODES * DDIM) return;
    float v = rst[i] + bias[i & (DDIM - 1)];
    rst[i] = v > 0.f ? v : (__expf(v) - 1.f);
}

// ---------------- semantic attention ----------------

__global__ void sem_score_kernel(const float* __restrict__ Hm,
                                 const float* __restrict__ b1,
                                 const float* __restrict__ W2,
                                 float* __restrict__ out) {
    int w = blockIdx.x * 8 + (threadIdx.x >> 5);
    int lane = threadIdx.x & 31;
    if (w >= NNODES) return;
    float t = 0.f;
#pragma unroll
    for (int q = 0; q < 4; q++) {
        int j = lane + 32 * q;
        t += tanhf(Hm[(size_t)w * SEMH + j] + b1[j]) * W2[j];
    }
#pragma unroll
    for (int o = 16; o > 0; o >>= 1) t += __shfl_down_sync(0xffffffffu, t, o);
    if (lane == 0) out[w] = t;
}

__global__ void fuse_kernel(const float* __restrict__ z0, const float* __restrict__ z1,
                            const float* __restrict__ w0, const float* __restrict__ w1,
                            float* __restrict__ fu) {
    int i = blockIdx.x * blockDim.x + threadIdx.x;
    if (i >= NNODES * DDIM) return;
    int n = i >> 9;
    float a = w0[n], b = w1[n];
    float m = fmaxf(a, b);
    float ea = __expf(a - m), eb = __expf(b - m);
    float be = ea / (ea + eb);
    fu[i] = be * z0[i] + (1.f - be) * z1[i];
}

// ---------------- host orchestration ----------------

static void gemm_nn(const float* A, const float* B, float* C, int M, int N, int K) {
    dim3 g((N + 127) / 128, (M + 127) / 128);
    mma_gemm<false><<<g, 256>>>(A, B, C, M, N, K);
}
static void gemm_nt(const float* A, const float* B, float* C, int M, int N, int K) {
    dim3 g((N + 127) / 128, (M + 127) / 128);
    mma_gemm<true><<<g, 256>>>(A, B, C, M, N, K);
}

struct Scratch {
    float *wh, *feat, *z0, *z1, *el, *er, *sm, *ex, *sc, *w0, *w1, *fu;
    int* mx;
};

static void run_gat(const Scratch& S, const float* fc, const float* al, const float* ar,
                    const float* bias, const int* ed, float* z) {
    gemm_nn(S.wh, fc, S.feat, NNODES, DDIM, FDIM);
    cudaMemsetAsync(z, 0, (size_t)NNODES * DDIM * sizeof(float), 0);
    eler_kernel<<<NNODES, 256>>>(S.feat, al, ar, S.el, S.er, S.mx, S.sm);
    int egrid = (NEDGE * NHEAD + 255) / 256;
    edge_max_kernel<<<egrid, 256>>>(ed, S.el, S.er, S.ex, S.mx);
    edge_exp_kernel<<<egrid, 256>>>(ed, S.ex, S.mx, S.sm);
    int agrid = (NEDGE * (DDIM / 4) + 255) / 256;
    edge_agg_kernel<<<agrid, 256>>>(ed, S.ex, S.sm, S.feat, z);
    elu_bias_kernel<<<(NNODES * DDIM + 255) / 256, 256>>>(z, bias);
}

static void run_branch(const Scratch& S, const float* x, void* const* d_in, int base,
                       const int* e0, const int* e1, float* h_out) {
    const float* w_h  = (const float*)d_in[base + 0];
    const float* fc   = (const float*)d_in[base + 1];
    const float* al   = (const float*)d_in[base + 2];
    const float* ar   = (const float*)d_in[base + 3];
    const float* bias = (const float*)d_in[base + 4];
    const float* W1   = (const float*)d_in[base + 5];
    const float* b1   = (const float*)d_in[base + 6];
    const float* W2   = (const float*)d_in[base + 7];
    const float* pred = (const float*)d_in[base + 8];

    gemm_nn(x, w_h, S.wh, NNODES, FDIM, FDIM);

    run_gat(S, fc,               al,              ar,              bias,        e0, S.z0);
    run_gat(S, fc + FDIM * DDIM, al + NHEAD * 64, ar + NHEAD * 64, bias + DDIM, e1, S.z1);

    gemm_nn(S.z0, W1, S.sc, NNODES, SEMH, DDIM);
    sem_score_kernel<<<(NNODES + 7) / 8, 256>>>(S.sc, b1, W2, S.w0);
    gemm_nn(S.z1, W1, S.sc, NNODES, SEMH, DDIM);
    sem_score_kernel<<<(NNODES + 7) / 8, 256>>>(S.sc, b1, W2, S.w1);
    fuse_kernel<<<(NNODES * DDIM + 255) / 256, 256>>>(S.z0, S.z1, S.w0, S.w1, S.fu);

    gemm_nn(S.fu, pred, h_out, NNODES, OSZ, DDIM);
}

extern "C" void kernel_launch(void* const* d_in, const int* in_sizes, int n_in,
                              void* d_out, int out_size) {
    Scratch S;
    cudaGetSymbolAddress((void**)&S.wh,   g_wh);
    cudaGetSymbolAddress((void**)&S.feat, g_feat);
    cudaGetSymbolAddress((void**)&S.z0,   g_z0);
    cudaGetSymbolAddress((void**)&S.z1,   g_z1);
    cudaGetSymbolAddress((void**)&S.el,   g_el);
    cudaGetSymbolAddress((void**)&S.er,   g_er);
    cudaGetSymbolAddress((void**)&S.mx,   g_mx);
    cudaGetSymbolAddress((void**)&S.sm,   g_sm);
    cudaGetSymbolAddress((void**)&S.ex,   g_ex);
    cudaGetSymbolAddress((void**)&S.sc,   g_sc);
    cudaGetSymbolAddress((void**)&S.w0,   g_w0);
    cudaGetSymbolAddress((void**)&S.w1,   g_w1);
    cudaGetSymbolAddress((void**)&S.fu,   g_fu);

    const float* hx = (const float*)d_in[0];
    const float* tx = (const float*)d_in[1];
    const int* eh0 = (const int*)d_in[20];
    const int* eh1 = (const int*)d_in[21];
    const int* et0 = (const int*)d_in[22];
    const int* et1 = (const int*)d_in[23];

    float* out  = (float*)d_out;
    float* h1   = out;
    float* h2   = out + (size_t)NNODES * OSZ;
    float* prod = out + (size_t)2 * NNODES * OSZ;

    run_branch(S, hx, d_in, 2,  eh0, eh1, h1);
    run_branch(S, tx, d_in, 11, et0, et1, h2);

    gemm_nt(h1, h2, prod, NNODES, NNODES, OSZ);
}

// round 5
// speedup vs baseline: 1.8997x; 1.1242x over previous
#include <cuda_runtime.h>
#include <cstdint>

#define NNODES 10000
#define FDIM   256
#define DDIM   512
#define NEDGE  160000
#define NHEAD  8
#define SEMH   128
#define OSZ    64

// ---------------- scratch (static device globals; no allocation) ----------------
__device__ float g_wh  [NNODES * FDIM];
__device__ float g_feat[NNODES * DDIM];
__device__ float g_z0  [NNODES * DDIM];
__device__ float g_z1  [NNODES * DDIM];
__device__ float g_el  [NNODES * NHEAD];
__device__ float g_er  [NNODES * NHEAD];
__device__ int   g_mx  [NNODES * NHEAD];
__device__ float g_sm  [NNODES * NHEAD];
__device__ float g_ex  [NEDGE * NHEAD];
__device__ float g_sc  [NNODES * SEMH];
__device__ float g_w0  [NNODES];
__device__ float g_w1  [NNODES];
__device__ float g_fu  [NNODES * DDIM];
// CSR scratch
__device__ int g_off[NNODES + 1];
__device__ int g_cur[NNODES];
__device__ int g_eid[NEDGE];

// ---------------- tf32 MMA GEMM, double-buffered ----------------
// Block tile BM(=32*MT) x 128, K-tile 16. 256 threads = 8 warps in 2(m) x 4(n).
// Warp tile (MT*16) x 32 = MT x 4 mma(16x8k8) tiles. Shared tiles are stored
// pre-permuted in mma fragment order (1 LDS.128 per A frag, 1 LDS.64 per B
// frag, conflict-free). Two smem buffers; global prefetch for tile t+1 is
// issued before the mma block of tile t; single __syncthreads per K-iter.

__device__ __forceinline__ unsigned f2tf(float f) {
    unsigned r;
    asm("cvt.rna.tf32.f32 %0, %1;" : "=r"(r) : "f"(f));
    return r;
}

template<int MT, bool TRANSB>
__global__ __launch_bounds__(256, 2) void mma_gemm(const float* __restrict__ A,
                                                   const float* __restrict__ B,
                                                   float* __restrict__ C,
                                                   int M, int N, int K) {
    constexpr int BM = 32 * MT;
    constexpr int AQ = (BM * 4) / 256;  // A float4 loads per thread
    __shared__ unsigned sA[2][2][2 * MT][32][4];
    __shared__ unsigned sB[2][2][16][32][2];

    int tid = threadIdx.x;
    int warp = tid >> 5, lane = tid & 31;
    int wm = warp >> 2, wn = warp & 3;
    int row0 = blockIdx.y * BM, col0 = blockIdx.x * 128;

    float4 ra[AQ];
    float4 rb[2];

    auto loadA = [&](int k0) {
#pragma unroll
        for (int it = 0; it < AQ; it++) {
            int i = tid * AQ + it;
            int r = i >> 2, c4 = i & 3;
            float4 v = make_float4(0.f, 0.f, 0.f, 0.f);
            int gr = row0 + r;
            if (gr < M) v = *(const float4*)(A + (size_t)gr * K + k0 + c4 * 4);
            ra[it] = v;
        }
    };
    auto storeA = [&](int buf) {
#pragma unroll
        for (int it = 0; it < AQ; it++) {
            int i = tid * AQ + it;
            int r = i >> 2, c4 = i & 3;
            int ks = c4 >> 1;
            int mt = r >> 4;
            int q  = ((r >> 3) & 1) + 2 * (c4 & 1);
            int tb = (r & 7) * 4;
            sA[buf][ks][mt][tb + 0][q] = f2tf(ra[it].x);
            sA[buf][ks][mt][tb + 1][q] = f2tf(ra[it].y);
            sA[buf][ks][mt][tb + 2][q] = f2tf(ra[it].z);
            sA[buf][ks][mt][tb + 3][q] = f2tf(ra[it].w);
        }
    };
    auto loadB = [&](int k0) {
#pragma unroll
        for (int it = 0; it < 2; it++) {
            int i = tid * 2 + it;
            float4 v = make_float4(0.f, 0.f, 0.f, 0.f);
            if (!TRANSB) {
                int kr = i >> 5, c4 = i & 31;
                int gc = col0 + c4 * 4;
                if (gc < N) v = *(const float4*)(B + (size_t)(k0 + kr) * N + gc);
            } else {
                int nr = i >> 2, c4 = i & 3;
                int gn = col0 + nr;
                if (gn < N) v = *(const float4*)(B + (size_t)gn * K + k0 + c4 * 4);
            }
            rb[it] = v;
        }
    };
    auto storeB = [&](int buf) {
#pragma unroll
        for (int it = 0; it < 2; it++) {
            int i = tid * 2 + it;
            if (!TRANSB) {
                int kr = i >> 5, c4 = i & 31;
                int ks = kr >> 3;
                int kk = kr & 7;
                int q  = kk >> 2;
                int nt = c4 >> 1;
                int tb = 16 * (c4 & 1) + (kk & 3);
                sB[buf][ks][nt][tb + 0 ][q] = f2tf(rb[it].x);
                sB[buf][ks][nt][tb + 4 ][q] = f2tf(rb[it].y);
                sB[buf][ks][nt][tb + 8 ][q] = f2tf(rb[it].z);
                sB[buf][ks][nt][tb + 12][q] = f2tf(rb[it].w);
            } else {
                int nr = i >> 2, c4 = i & 3;
                int ks = c4 >> 1;
                int q  = c4 & 1;
                int nt = nr >> 3;
                int tb = (nr & 7) * 4;
                sB[buf][ks][nt][tb + 0][q] = f2tf(rb[it].x);
                sB[buf][ks][nt][tb + 1][q] = f2tf(rb[it].y);
                sB[buf][ks][nt][tb + 2][q] = f2tf(rb[it].z);
                sB[buf][ks][nt][tb + 3][q] = f2tf(rb[it].w);
            }
        }
    };

    float acc[MT][4][4];
#pragma unroll
    for (int i = 0; i < MT; i++)
#pragma unroll
        for (int j = 0; j < 4; j++)
#pragma unroll
            for (int q = 0; q < 4; q++) acc[i][j][q] = 0.f;

    int nk = K >> 4;
    loadA(0); loadB(0);
    storeA(0); storeB(0);
    __syncthreads();

    for (int t = 0; t < nk; t++) {
        int buf = t & 1;
        if (t + 1 < nk) { loadA((t + 1) * 16); loadB((t + 1) * 16); }

#pragma unroll
        for (int ks = 0; ks < 2; ks++) {
            uint4 af[MT];
            uint2 bf[4];
#pragma unroll
            for (int mt = 0; mt < MT; mt++)
                af[mt] = *(const uint4*)&sA[buf][ks][wm * MT + mt][lane][0];
#pragma unroll
            for (int nt = 0; nt < 4; nt++)
                bf[nt] = *(const uint2*)&sB[buf][ks][wn * 4 + nt][lane][0];
#pragma unroll
            for (int mt = 0; mt < MT; mt++)
#pragma unroll
                for (int nt = 0; nt < 4; nt++) {
                    asm volatile(
                        "mma.sync.aligned.m16n8k8.row.col.f32.tf32.tf32.f32 "
                        "{%0,%1,%2,%3}, {%4,%5,%6,%7}, {%8,%9}, {%0,%1,%2,%3};"
                        : "+f"(acc[mt][nt][0]), "+f"(acc[mt][nt][1]),
                          "+f"(acc[mt][nt][2]), "+f"(acc[mt][nt][3])
                        : "r"(af[mt].x), "r"(af[mt].y), "r"(af[mt].z), "r"(af[mt].w),
                          "r"(bf[nt].x), "r"(bf[nt].y));
                }
        }
        if (t + 1 < nk) { storeA(buf ^ 1); storeB(buf ^ 1); }
        __syncthreads();
    }

#pragma unroll
    for (int mt = 0; mt < MT; mt++) {
        int r_base = row0 + wm * (MT * 16) + mt * 16 + (lane >> 2);
#pragma unroll
        for (int nt = 0; nt < 4; nt++) {
            int c = col0 + wn * 32 + nt * 8 + (lane & 3) * 2;
            if (c < N) {
                if (r_base < M)
                    *(float2*)(C + (size_t)r_base * N + c) =
                        make_float2(acc[mt][nt][0], acc[mt][nt][1]);
                if (r_base + 8 < M)
                    *(float2*)(C + (size_t)(r_base + 8) * N + c) =
                        make_float2(acc[mt][nt][2], acc[mt][nt][3]);
            }
        }
    }
}

// ---------------- GAT kernels ----------------

__global__ void eler_kernel(const float* __restrict__ feat,
                            const float* __restrict__ al,
                            const float* __restrict__ ar,
                            float* __restrict__ el, float* __restrict__ er,
                            int* __restrict__ mx, float* __restrict__ sm) {
    int w = blockIdx.x * 8 + (threadIdx.x >> 5);
    int lane = threadIdx.x & 31;
    if (w >= NNODES * NHEAD) return;
    int n = w >> 3, h = w & 7;
    const float* f = feat + (size_t)n * DDIM + h * 64;
    float sl = f[lane] * al[h * 64 + lane] + f[lane + 32] * al[h * 64 + lane + 32];
    float sr = f[lane] * ar[h * 64 + lane] + f[lane + 32] * ar[h * 64 + lane + 32];
#pragma unroll
    for (int o = 16; o > 0; o >>= 1) {
        sl += __shfl_down_sync(0xffffffffu, sl, o);
        sr += __shfl_down_sync(0xffffffffu, sr, o);
    }
    if (lane == 0) {
        el[w] = sl;
        er[w] = sr;
        mx[w] = (int)0x80000000;
        sm[w] = 0.f;
    }
}

__device__ __forceinline__ int f2ord(float v) {
    int k = __float_as_int(v);
    return k >= 0 ? k : (k ^ 0x7FFFFFFF);
}
__device__ __forceinline__ float ord2f(int k) {
    return __int_as_float(k >= 0 ? k : (k ^ 0x7FFFFFFF));
}

// also builds the degree histogram (h==0 lane of each edge)
__global__ void edge_max_kernel(const int* __restrict__ ed,
                                const float* __restrict__ el,
                                const float* __restrict__ er,
                                float* __restrict__ ex, int* __restrict__ mx,
                                int* __restrict__ cnt) {
    int i = blockIdx.x * blockDim.x + threadIdx.x;
    if (i >= NEDGE * NHEAD) return;
    int e = i >> 3, h = i & 7;
    int s = ed[e], d = ed[NEDGE + e];
    float v = el[s * NHEAD + h] + er[d * NHEAD + h];
    v = v > 0.f ? v : 0.2f * v;
    ex[i] = v;
    atomicMax(&mx[d * NHEAD + h], f2ord(v));
    if (h == 0) atomicAdd(&cnt[d], 1);
}

__global__ void edge_exp_kernel(const int* __restrict__ ed,
                                float* __restrict__ ex,
                                const int* __restrict__ mx,
                                float* __restrict__ sm) {
    int i = blockIdx.x * blockDim.x + threadIdx.x;
    if (i >= NEDGE * NHEAD) return;
    int e = i >> 3, h = i & 7;
    int d = ed[NEDGE + e];
    float v = __expf(ex[i] - ord2f(mx[d * NHEAD + h]));
    ex[i] = v;
    atomicAdd(&sm[d * NHEAD + h], v);
}

// single-block exclusive scan of the degree histogram -> offsets + cursors
__global__ void scan_kernel(int* __restrict__ cur, int* __restrict__ off) {
    __shared__ int part[1024];
    int t = threadIdx.x;
    int base = t * 10;
    int v[10];
    int s = 0;
#pragma unroll
    for (int j = 0; j < 10; j++) {
        int idx = base + j;
        int c = (idx < NNODES) ? cur[idx] : 0;
        v[j] = c;
        s += c;
    }
    part[t] = s;
    __syncthreads();
    for (int o = 1; o < 1024; o <<= 1) {
        int x = (t >= o) ? part[t - o] : 0;
        __syncthreads();
        part[t] += x;
        __syncthreads();
    }
    int run = (t > 0) ? part[t - 1] : 0;
#pragma unroll
    for (int j = 0; j < 10; j++) {
        int idx = base + j;
        if (idx < NNODES) {
            off[idx] = run;
            cur[idx] = run;
            run += v[j];
        }
    }
    if (t == 0) off[NNODES] = NEDGE;
}

__global__ void scatter_kernel(const int* __restrict__ ed,
                               int* __restrict__ cur, int* __restrict__ eid) {
    int i = blockIdx.x * blockDim.x + threadIdx.x;
    if (i >= NEDGE) return;
    int d = ed[NEDGE + i];
    int p = atomicAdd(&cur[d], 1);
    eid[p] = i;
}

// gather-aggregate: one warp per (dst node, 128-col strip); bias+ELU fused.
__global__ __launch_bounds__(256) void agg_kernel(const int* __restrict__ ed,
                                                  const float* __restrict__ ex,
                                                  const float* __restrict__ sm,
                                                  const int* __restrict__ off,
                                                  const int* __restrict__ eid,
                                                  const float* __restrict__ feat,
                                                  const float* __restrict__ bias,
                                                  float* __restrict__ z) {
    int wid = blockIdx.x * 8 + (threadIdx.x >> 5);
    if (wid >= NNODES * 4) return;
    int d = wid >> 2, strip = wid & 3;
    int lane = threadIdx.x & 31;
    int col = strip * 128 + lane * 4;
    int head = col >> 6;
    float rcp = 1.f / sm[d * NHEAD + head];  // unused if degree 0

    float4 acc = make_float4(0.f, 0.f, 0.f, 0.f);
    int b = off[d], e_ = off[d + 1];
#pragma unroll 4
    for (int i = b; i < e_; i++) {
        int e = eid[i];
        int s = ed[e];
        float a = ex[e * NHEAD + head] * rcp;
        float4 f = *(const float4*)(feat + (size_t)s * DDIM + col);
        acc.x += f.x * a;
        acc.y += f.y * a;
        acc.z += f.z * a;
        acc.w += f.w * a;
    }
    float4 bb = *(const float4*)(bias + col);
    float4 v;
    v.x = acc.x + bb.x; v.x = v.x > 0.f ? v.x : (__expf(v.x) - 1.f);
    v.y = acc.y + bb.y; v.y = v.y > 0.f ? v.y : (__expf(v.y) - 1.f);
    v.z = acc.z + bb.z; v.z = v.z > 0.f ? v.z : (__expf(v.z) - 1.f);
    v.w = acc.w + bb.w; v.w = v.w > 0.f ? v.w : (__expf(v.w) - 1.f);
    *(float4*)(z + (size_t)d * DDIM + col) = v;
}

// ---------------- semantic attention ----------------

__global__ void sem_score_kernel(const float* __restrict__ Hm,
                                 const float* __restrict__ b1,
                                 const float* __restrict__ W2,
                                 float* __restrict__ out) {
    int w = blockIdx.x * 8 + (threadIdx.x >> 5);
    int lane = threadIdx.x & 31;
    if (w >= NNODES) return;
    float t = 0.f;
#pragma unroll
    for (int q = 0; q < 4; q++) {
        int j = lane + 32 * q;
        t += tanhf(Hm[(size_t)w * SEMH + j] + b1[j]) * W2[j];
    }
#pragma unroll
    for (int o = 16; o > 0; o >>= 1) t += __shfl_down_sync(0xffffffffu, t, o);
    if (lane == 0) out[w] = t;
}

__global__ void fuse_kernel(const float* __restrict__ z0, const float* __restrict__ z1,
                            const float* __restrict__ w0, const float* __restrict__ w1,
                            float* __restrict__ fu) {
    int i = blockIdx.x * blockDim.x + threadIdx.x;
    if (i >= NNODES * DDIM) return;
    int n = i >> 9;
    float a = w0[n], b = w1[n];
    float m = fmaxf(a, b);
    float ea = __expf(a - m), eb = __expf(b - m);
    float be = ea / (ea + eb);
    fu[i] = be * z0[i] + (1.f - be) * z1[i];
}

// ---------------- host orchestration ----------------

static void gemm_nn(const float* A, const float* B, float* C, int M, int N, int K) {
    dim3 g((N + 127) / 128, (M + 127) / 128);
    mma_gemm<4, false><<<g, 256>>>(A, B, C, M, N, K);
}
static void gemm_nn64(const float* A, const float* B, float* C, int M, int N, int K) {
    dim3 g((N + 127) / 128, (M + 63) / 64);
    mma_gemm<2, false><<<g, 256>>>(A, B, C, M, N, K);
}
static void gemm_nt(const float* A, const float* B, float* C, int M, int N, int K) {
    dim3 g((N + 127) / 128, (M + 127) / 128);
    mma_gemm<4, true><<<g, 256>>>(A, B, C, M, N, K);
}

struct Scratch {
    float *wh, *feat, *z0, *z1, *el, *er, *sm, *ex, *sc, *w0, *w1, *fu;
    int *mx, *off, *cur, *eid;
};

static void run_gat(const Scratch& S, const float* fc, const float* al, const float* ar,
                    const float* bias, const int* ed, float* z) {
    gemm_nn(S.wh, fc, S.feat, NNODES, DDIM, FDIM);
    cudaMemsetAsync(S.cur, 0, NNODES * sizeof(int), 0);
    eler_kernel<<<NNODES, 256>>>(S.feat, al, ar, S.el, S.er, S.mx, S.sm);
    int egrid = (NEDGE * NHEAD + 255) / 256;
    edge_max_kernel<<<egrid, 256>>>(ed, S.el, S.er, S.ex, S.mx, S.cur);
    edge_exp_kernel<<<egrid, 256>>>(ed, S.ex, S.mx, S.sm);
    scan_kernel<<<1, 1024>>>(S.cur, S.off);
    scatter_kernel<<<(NEDGE + 255) / 256, 256>>>(ed, S.cur, S.eid);
    agg_kernel<<<(NNODES * 4 + 7) / 8, 256>>>(ed, S.ex, S.sm, S.off, S.eid,
                                              S.feat, bias, z);
}

static void run_branch(const Scratch& S, const float* x, void* const* d_in, int base,
                       const int* e0, const int* e1, float* h_out) {
    const float* w_h  = (const float*)d_in[base + 0];
    const float* fc   = (const float*)d_in[base + 1];
    const float* al   = (const float*)d_in[base + 2];
    const float* ar   = (const float*)d_in[base + 3];
    const float* bias = (const float*)d_in[base + 4];
    const float* W1   = (const float*)d_in[base + 5];
    const float* b1   = (const float*)d_in[base + 6];
    const float* W2   = (const float*)d_in[base + 7];
    const float* pred = (const float*)d_in[base + 8];

    gemm_nn(x, w_h, S.wh, NNODES, FDIM, FDIM);

    run_gat(S, fc,               al,              ar,              bias,        e0, S.z0);
    run_gat(S, fc + FDIM * DDIM, al + NHEAD * 64, ar + NHEAD * 64, bias + DDIM, e1, S.z1);

    gemm_nn64(S.z0, W1, S.sc, NNODES, SEMH, DDIM);
    sem_score_kernel<<<(NNODES + 7) / 8, 256>>>(S.sc, b1, W2, S.w0);
    gemm_nn64(S.z1, W1, S.sc, NNODES, SEMH, DDIM);
    sem_score_kernel<<<(NNODES + 7) / 8, 256>>>(S.sc, b1, W2, S.w1);
    fuse_kernel<<<(NNODES * DDIM + 255) / 256, 256>>>(S.z0, S.z1, S.w0, S.w1, S.fu);

    gemm_nn64(S.fu, pred, h_out, NNODES, OSZ, DDIM);
}

extern "C" void kernel_launch(void* const* d_in, const int* in_sizes, int n_in,
                              void* d_out, int out_size) {
    Scratch S;
    cudaGetSymbolAddress((void**)&S.wh,   g_wh);
    cudaGetSymbolAddress((void**)&S.feat, g_feat);
    cudaGetSymbolAddress((void**)&S.z0,   g_z0);
    cudaGetSymbolAddress((void**)&S.z1,   g_z1);
    cudaGetSymbolAddress((void**)&S.el,   g_el);
    cudaGetSymbolAddress((void**)&S.er,   g_er);
    cudaGetSymbolAddress((void**)&S.mx,   g_mx);
    cudaGetSymbolAddress((void**)&S.sm,   g_sm);
    cudaGetSymbolAddress((void**)&S.ex,   g_ex);
    cudaGetSymbolAddress((void**)&S.sc,   g_sc);
    cudaGetSymbolAddress((void**)&S.w0,   g_w0);
    cudaGetSymbolAddress((void**)&S.w1,   g_w1);
    cudaGetSymbolAddress((void**)&S.fu,   g_fu);
    cudaGetSymbolAddress((void**)&S.off,  g_off);
    cudaGetSymbolAddress((void**)&S.cur,  g_cur);
    cudaGetSymbolAddress((void**)&S.eid,  g_eid);

    const float* hx = (const float*)d_in[0];
    const float* tx = (const float*)d_in[1];
    const int* eh0 = (const int*)d_in[20];
    const int* eh1 = (const int*)d_in[21];
    const int* et0 = (const int*)d_in[22];
    const int* et1 = (const int*)d_in[23];

    float* out  = (float*)d_out;
    float* h1   = out;
    float* h2   = out + (size_t)NNODES * OSZ;
    float* prod = out + (size_t)2 * NNODES * OSZ;

    run_branch(S, hx, d_in, 2,  eh0, eh1, h1);
    run_branch(S, tx, d_in, 11, et0, et1, h2);

    gemm_nt(h1, h2, prod, NNODES, NNODES, OSZ);
}

// round 6
// speedup vs baseline: 2.0774x; 1.0935x over previous
#include <cuda_runtime.h>
#include <cstdint>

#define NNODES 10000
#define FDIM   256
#define DDIM   512
#define NEDGE  160000
#define NHEAD  8
#define SEMH   128
#define OSZ    64

// ---------------- scratch (static device globals; no allocation) ----------------
// instance index z in [0,4): branch = z>>1 (0=herb,1=target), metapath = z&1
__device__ float g_wh  [2][NNODES * FDIM];
__device__ float g_feat[4][NNODES * DDIM];
__device__ float g_z   [4][NNODES * DDIM];
__device__ float g_el  [4][NNODES * NHEAD];
__device__ float g_er  [4][NNODES * NHEAD];
__device__ int   g_mx  [4][NNODES * NHEAD];
__device__ float g_sm  [4][NNODES * NHEAD];
__device__ float g_ex  [4][NEDGE * NHEAD];
__device__ float g_sc  [4][NNODES * SEMH];
__device__ float g_w   [4][NNODES];
__device__ float g_fu  [2][NNODES * DDIM];
__device__ int   g_off [4][NNODES + 1];
__device__ int   g_cur [4][NNODES];
__device__ int   g_eid [4][NEDGE];

struct GB   { const float* A[4]; const float* B[4]; float* C[4]; };
struct IP4  { const int*   p[4]; };
struct FP4  { const float* p[4]; };

// ---------------- tf32 MMA GEMM, double-buffered, z-batched ----------------
// Block tile BM(=32*MT) x 128, K-tile 16. 256 threads = 8 warps in 2(m) x 4(n).
// Shared tiles pre-permuted into mma fragment order (1 LDS.128 per A frag,
// 1 LDS.64 per B frag, conflict-free). Two smem buffers, register-staged
// prefetch, one __syncthreads per K-iter. blockIdx.z selects the instance.

__device__ __forceinline__ unsigned f2tf(float f) {
    unsigned r;
    asm("cvt.rna.tf32.f32 %0, %1;" : "=r"(r) : "f"(f));
    return r;
}

template<int MT, bool TRANSB>
__global__ __launch_bounds__(256, 2) void mma_gemm_b(GB gb, int M, int N, int K) {
    constexpr int BM = 32 * MT;
    constexpr int AQ = (BM * 4) / 256;
    __shared__ unsigned sA[2][2][2 * MT][32][4];
    __shared__ unsigned sB[2][2][16][32][2];

    const float* __restrict__ A = gb.A[blockIdx.z];
    const float* __restrict__ B = gb.B[blockIdx.z];
    float* __restrict__ C = gb.C[blockIdx.z];

    int tid = threadIdx.x;
    int warp = tid >> 5, lane = tid & 31;
    int wm = warp >> 2, wn = warp & 3;
    int row0 = blockIdx.y * BM, col0 = blockIdx.x * 128;

    float4 ra[AQ];
    float4 rb[2];

    auto loadA = [&](int k0) {
#pragma unroll
        for (int it = 0; it < AQ; it++) {
            int i = tid * AQ + it;
            int r = i >> 2, c4 = i & 3;
            float4 v = make_float4(0.f, 0.f, 0.f, 0.f);
            int gr = row0 + r;
            if (gr < M) v = *(const float4*)(A + (size_t)gr * K + k0 + c4 * 4);
            ra[it] = v;
        }
    };
    auto storeA = [&](int buf) {
#pragma unroll
        for (int it = 0; it < AQ; it++) {
            int i = tid * AQ + it;
            int r = i >> 2, c4 = i & 3;
            int ks = c4 >> 1;
            int mt = r >> 4;
            int q  = ((r >> 3) & 1) + 2 * (c4 & 1);
            int tb = (r & 7) * 4;
            sA[buf][ks][mt][tb + 0][q] = f2tf(ra[it].x);
            sA[buf][ks][mt][tb + 1][q] = f2tf(ra[it].y);
            sA[buf][ks][mt][tb + 2][q] = f2tf(ra[it].z);
            sA[buf][ks][mt][tb + 3][q] = f2tf(ra[it].w);
        }
    };
    auto loadB = [&](int k0) {
#pragma unroll
        for (int it = 0; it < 2; it++) {
            int i = tid * 2 + it;
            float4 v = make_float4(0.f, 0.f, 0.f, 0.f);
            if (!TRANSB) {
                int kr = i >> 5, c4 = i & 31;
                int gc = col0 + c4 * 4;
                if (gc < N) v = *(const float4*)(B + (size_t)(k0 + kr) * N + gc);
            } else {
                int nr = i >> 2, c4 = i & 3;
                int gn = col0 + nr;
                if (gn < N) v = *(const float4*)(B + (size_t)gn * K + k0 + c4 * 4);
            }
            rb[it] = v;
        }
    };
    auto storeB = [&](int buf) {
#pragma unroll
        for (int it = 0; it < 2; it++) {
            int i = tid * 2 + it;
            if (!TRANSB) {
                int kr = i >> 5, c4 = i & 31;
                int ks = kr >> 3;
                int kk = kr & 7;
                int q  = kk >> 2;
                int nt = c4 >> 1;
                int tb = 16 * (c4 & 1) + (kk & 3);
                sB[buf][ks][nt][tb + 0 ][q] = f2tf(rb[it].x);
                sB[buf][ks][nt][tb + 4 ][q] = f2tf(rb[it].y);
                sB[buf][ks][nt][tb + 8 ][q] = f2tf(rb[it].z);
                sB[buf][ks][nt][tb + 12][q] = f2tf(rb[it].w);
            } else {
                int nr = i >> 2, c4 = i & 3;
                int ks = c4 >> 1;
                int q  = c4 & 1;
                int nt = nr >> 3;
                int tb = (nr & 7) * 4;
                sB[buf][ks][nt][tb + 0][q] = f2tf(rb[it].x);
                sB[buf][ks][nt][tb + 1][q] = f2tf(rb[it].y);
                sB[buf][ks][nt][tb + 2][q] = f2tf(rb[it].z);
                sB[buf][ks][nt][tb + 3][q] = f2tf(rb[it].w);
            }
        }
    };

    float acc[MT][4][4];
#pragma unroll
    for (int i = 0; i < MT; i++)
#pragma unroll
        for (int j = 0; j < 4; j++)
#pragma unroll
            for (int q = 0; q < 4; q++) acc[i][j][q] = 0.f;

    int nk = K >> 4;
    loadA(0); loadB(0);
    storeA(0); storeB(0);
    __syncthreads();

    for (int t = 0; t < nk; t++) {
        int buf = t & 1;
        if (t + 1 < nk) { loadA((t + 1) * 16); loadB((t + 1) * 16); }

#pragma unroll
        for (int ks = 0; ks < 2; ks++) {
            uint4 af[MT];
            uint2 bf[4];
#pragma unroll
            for (int mt = 0; mt < MT; mt++)
                af[mt] = *(const uint4*)&sA[buf][ks][wm * MT + mt][lane][0];
#pragma unroll
            for (int nt = 0; nt < 4; nt++)
                bf[nt] = *(const uint2*)&sB[buf][ks][wn * 4 + nt][lane][0];
#pragma unroll
            for (int mt = 0; mt < MT; mt++)
#pragma unroll
                for (int nt = 0; nt < 4; nt++) {
                    asm volatile(
                        "mma.sync.aligned.m16n8k8.row.col.f32.tf32.tf32.f32 "
                        "{%0,%1,%2,%3}, {%4,%5,%6,%7}, {%8,%9}, {%0,%1,%2,%3};"
                        : "+f"(acc[mt][nt][0]), "+f"(acc[mt][nt][1]),
                          "+f"(acc[mt][nt][2]), "+f"(acc[mt][nt][3])
                        : "r"(af[mt].x), "r"(af[mt].y), "r"(af[mt].z), "r"(af[mt].w),
                          "r"(bf[nt].x), "r"(bf[nt].y));
                }
        }
        if (t + 1 < nk) { storeA(buf ^ 1); storeB(buf ^ 1); }
        __syncthreads();
    }

#pragma unroll
    for (int mt = 0; mt < MT; mt++) {
        int r_base = row0 + wm * (MT * 16) + mt * 16 + (lane >> 2);
#pragma unroll
        for (int nt = 0; nt < 4; nt++) {
            int c = col0 + wn * 32 + nt * 8 + (lane & 3) * 2;
            if (c < N) {
                if (r_base < M)
                    *(float2*)(C + (size_t)r_base * N + c) =
                        make_float2(acc[mt][nt][0], acc[mt][nt][1]);
                if (r_base + 8 < M)
                    *(float2*)(C + (size_t)(r_base + 8) * N + c) =
                        make_float2(acc[mt][nt][2], acc[mt][nt][3]);
            }
        }
    }
}

// ---------------- GAT kernels (grid.y = instance z) ----------------

__global__ void eler_kernel(FP4 al4, FP4 ar4) {
    int z = blockIdx.y;
    int w = blockIdx.x * 8 + (threadIdx.x >> 5);
    int lane = threadIdx.x & 31;
    if (w >= NNODES * NHEAD) return;
    int n = w >> 3, h = w & 7;
    const float* al = al4.p[z];
    const float* ar = ar4.p[z];
    const float* f = g_feat[z] + (size_t)n * DDIM + h * 64;
    float sl = f[lane] * al[h * 64 + lane] + f[lane + 32] * al[h * 64 + lane + 32];
    float sr = f[lane] * ar[h * 64 + lane] + f[lane + 32] * ar[h * 64 + lane + 32];
#pragma unroll
    for (int o = 16; o > 0; o >>= 1) {
        sl += __shfl_down_sync(0xffffffffu, sl, o);
        sr += __shfl_down_sync(0xffffffffu, sr, o);
    }
    if (lane == 0) {
        g_el[z][w] = sl;
        g_er[z][w] = sr;
        g_mx[z][w] = (int)0x80000000;
        g_sm[z][w] = 0.f;
    }
}

__device__ __forceinline__ int f2ord(float v) {
    int k = __float_as_int(v);
    return k >= 0 ? k : (k ^ 0x7FFFFFFF);
}
__device__ __forceinline__ float ord2f(int k) {
    return __int_as_float(k >= 0 ? k : (k ^ 0x7FFFFFFF));
}

// also builds the degree histogram (h==0 lane of each edge)
__global__ void edge_max_kernel(IP4 ed4) {
    int z = blockIdx.y;
    int i = blockIdx.x * blockDim.x + threadIdx.x;
    if (i >= NEDGE * NHEAD) return;
    const int* ed = ed4.p[z];
    int e = i >> 3, h = i & 7;
    int s = ed[e], d = ed[NEDGE + e];
    float v = g_el[z][s * NHEAD + h] + g_er[z][d * NHEAD + h];
    v = v > 0.f ? v : 0.2f * v;
    g_ex[z][i] = v;
    atomicMax(&g_mx[z][d * NHEAD + h], f2ord(v));
    if (h == 0) atomicAdd(&g_cur[z][d], 1);
}

__global__ void edge_exp_kernel(IP4 ed4) {
    int z = blockIdx.y;
    int i = blockIdx.x * blockDim.x + threadIdx.x;
    if (i >= NEDGE * NHEAD) return;
    const int* ed = ed4.p[z];
    int e = i >> 3, h = i & 7;
    int d = ed[NEDGE + e];
    float v = __expf(g_ex[z][i] - ord2f(g_mx[z][d * NHEAD + h]));
    g_ex[z][i] = v;
    atomicAdd(&g_sm[z][d * NHEAD + h], v);
}

// per-instance single-block exclusive scan (grid.x = instance)
__global__ void scan_kernel() {
    int z = blockIdx.x;
    int* cur = g_cur[z];
    int* off = g_off[z];
    __shared__ int part[1024];
    int t = threadIdx.x;
    int base = t * 10;
    int v[10];
    int s = 0;
#pragma unroll
    for (int j = 0; j < 10; j++) {
        int idx = base + j;
        int c = (idx < NNODES) ? cur[idx] : 0;
        v[j] = c;
        s += c;
    }
    part[t] = s;
    __syncthreads();
    for (int o = 1; o < 1024; o <<= 1) {
        int x = (t >= o) ? part[t - o] : 0;
        __syncthreads();
        part[t] += x;
        __syncthreads();
    }
    int run = (t > 0) ? part[t - 1] : 0;
#pragma unroll
    for (int j = 0; j < 10; j++) {
        int idx = base + j;
        if (idx < NNODES) {
            off[idx] = run;
            cur[idx] = run;
            run += v[j];
        }
    }
    if (t == 0) off[NNODES] = NEDGE;
}

__global__ void scatter_kernel(IP4 ed4) {
    int z = blockIdx.y;
    int i = blockIdx.x * blockDim.x + threadIdx.x;
    if (i >= NEDGE) return;
    int d = ed4.p[z][NEDGE + i];
    int p = atomicAdd(&g_cur[z][d], 1);
    g_eid[z][p] = i;
}

// gather-aggregate: one warp per (dst node, 128-col strip); bias+ELU fused.
__global__ __launch_bounds__(256) void agg_kernel(IP4 ed4, FP4 bias4) {
    int z = blockIdx.y;
    int wid = blockIdx.x * 8 + (threadIdx.x >> 5);
    if (wid >= NNODES * 4) return;
    const int* ed = ed4.p[z];
    const float* bias = bias4.p[z];
    const float* __restrict__ feat = g_feat[z];
    const float* __restrict__ ex = g_ex[z];
    const int* __restrict__ eid = g_eid[z];
    int d = wid >> 2, strip = wid & 3;
    int lane = threadIdx.x & 31;
    int col = strip * 128 + lane * 4;
    int head = col >> 6;
    float rcp = 1.f / g_sm[z][d * NHEAD + head];

    float4 acc = make_float4(0.f, 0.f, 0.f, 0.f);
    int b = g_off[z][d], e_ = g_off[z][d + 1];
#pragma unroll 4
    for (int i = b; i < e_; i++) {
        int e = eid[i];
        int s = ed[e];
        float a = ex[e * NHEAD + head] * rcp;
        float4 f = *(const float4*)(feat + (size_t)s * DDIM + col);
        acc.x += f.x * a;
        acc.y += f.y * a;
        acc.z += f.z * a;
        acc.w += f.w * a;
    }
    float4 bb = *(const float4*)(bias + col);
    float4 v;
    v.x = acc.x + bb.x; v.x = v.x > 0.f ? v.x : (__expf(v.x) - 1.f);
    v.y = acc.y + bb.y; v.y = v.y > 0.f ? v.y : (__expf(v.y) - 1.f);
    v.z = acc.z + bb.z; v.z = v.z > 0.f ? v.z : (__expf(v.z) - 1.f);
    v.w = acc.w + bb.w; v.w = v.w > 0.f ? v.w : (__expf(v.w) - 1.f);
    *(float4*)(g_z[z] + (size_t)d * DDIM + col) = v;
}

// ---------------- semantic attention ----------------

__global__ void sem_score_kernel(FP4 b14, FP4 W24) {
    int z = blockIdx.y;
    int w = blockIdx.x * 8 + (threadIdx.x >> 5);
    int lane = threadIdx.x & 31;
    if (w >= NNODES) return;
    const float* b1 = b14.p[z];
    const float* W2 = W24.p[z];
    float t = 0.f;
#pragma unroll
    for (int q = 0; q < 4; q++) {
        int j = lane + 32 * q;
        t += tanhf(g_sc[z][(size_t)w * SEMH + j] + b1[j]) * W2[j];
    }
#pragma unroll
    for (int o = 16; o > 0; o >>= 1) t += __shfl_down_sync(0xffffffffu, t, o);
    if (lane == 0) g_w[z][w] = t;
}

__global__ void fuse_kernel() {
    int b = blockIdx.y;
    int i = blockIdx.x * blockDim.x + threadIdx.x;
    if (i >= NNODES * DDIM) return;
    int n = i >> 9;
    float a = g_w[2 * b][n], c = g_w[2 * b + 1][n];
    float m = fmaxf(a, c);
    float ea = __expf(a - m), eb = __expf(c - m);
    float be = ea / (ea + eb);
    g_fu[b][i] = be * g_z[2 * b][i] + (1.f - be) * g_z[2 * b + 1][i];
}

// ---------------- host orchestration ----------------

extern "C" void kernel_launch(void* const* d_in, const int* in_sizes, int n_in,
                              void* d_out, int out_size) {
    float *p_wh0, *p_wh1, *p_feat[4], *p_z[4], *p_sc[4], *p_fu[2];
    {
        float* base;
        cudaGetSymbolAddress((void**)&base, g_wh);
        p_wh0 = base; p_wh1 = base + (size_t)NNODES * FDIM;
        cudaGetSymbolAddress((void**)&base, g_feat);
        for (int z = 0; z < 4; z++) p_feat[z] = base + (size_t)z * NNODES * DDIM;
        cudaGetSymbolAddress((void**)&base, g_z);
        for (int z = 0; z < 4; z++) p_z[z] = base + (size_t)z * NNODES * DDIM;
        cudaGetSymbolAddress((void**)&base, g_sc);
        for (int z = 0; z < 4; z++) p_sc[z] = base + (size_t)z * NNODES * SEMH;
        cudaGetSymbolAddress((void**)&base, g_fu);
        for (int b = 0; b < 2; b++) p_fu[b] = base + (size_t)b * NNODES * DDIM;
    }
    int* p_cur;
    cudaGetSymbolAddress((void**)&p_cur, g_cur);

    const float* hx = (const float*)d_in[0];
    const float* tx = (const float*)d_in[1];
    const float* w_h[2]  = {(const float*)d_in[2],  (const float*)d_in[11]};
    const float* fc[2]   = {(const float*)d_in[3],  (const float*)d_in[12]};
    const float* al[2]   = {(const float*)d_in[4],  (const float*)d_in[13]};
    const float* ar[2]   = {(const float*)d_in[5],  (const float*)d_in[14]};
    const float* bias[2] = {(const float*)d_in[6],  (const float*)d_in[15]};
    const float* W1[2]   = {(const float*)d_in[7],  (const float*)d_in[16]};
    const float* b1[2]   = {(const float*)d_in[8],  (const float*)d_in[17]};
    const float* W2[2]   = {(const float*)d_in[9],  (const float*)d_in[18]};
    const float* pred[2] = {(const float*)d_in[10], (const float*)d_in[19]};

    IP4 ed4 = {{(const int*)d_in[20], (const int*)d_in[21],
                (const int*)d_in[22], (const int*)d_in[23]}};
    FP4 al4   = {{al[0], al[0] + NHEAD * 64, al[1], al[1] + NHEAD * 64}};
    FP4 ar4   = {{ar[0], ar[0] + NHEAD * 64, ar[1], ar[1] + NHEAD * 64}};
    FP4 bias4 = {{bias[0], bias[0] + DDIM, bias[1], bias[1] + DDIM}};
    FP4 b14   = {{b1[0], b1[0], b1[1], b1[1]}};
    FP4 W24   = {{W2[0], W2[0], W2[1], W2[1]}};

    float* out  = (float*)d_out;
    float* h1   = out;
    float* h2   = out + (size_t)NNODES * OSZ;
    float* prod = out + (size_t)2 * NNODES * OSZ;

    // 0) clear all 4 degree histograms
    cudaMemsetAsync(p_cur, 0, 4 * NNODES * sizeof(int), 0);

    // 1) wh = x @ w_h   (batched x2)
    {
        GB gb = {};
        gb.A[0] = hx;     gb.B[0] = w_h[0]; gb.C[0] = p_wh0;
        gb.A[1] = tx;     gb.B[1] = w_h[1]; gb.C[1] = p_wh1;
        dim3 g(FDIM / 128, (NNODES + 127) / 128, 2);
        mma_gemm_b<4, false><<<g, 256>>>(gb, NNODES, FDIM, FDIM);
    }
    // 2) feat = wh @ fc  (batched x4)
    {
        GB gb = {};
        const float* whp[2] = {p_wh0, p_wh1};
        for (int z = 0; z < 4; z++) {
            gb.A[z] = whp[z >> 1];
            gb.B[z] = fc[z >> 1] + (size_t)(z & 1) * FDIM * DDIM;
            gb.C[z] = p_feat[z];
        }
        dim3 g(DDIM / 128, (NNODES + 127) / 128, 4);
        mma_gemm_b<4, false><<<g, 256>>>(gb, NNODES, DDIM, FDIM);
    }
    // 3) attention logits + softmax stats + CSR build + aggregate (all x4)
    eler_kernel<<<dim3(NNODES, 4), 256>>>(al4, ar4);
    {
        dim3 g((NEDGE * NHEAD + 255) / 256, 4);
        edge_max_kernel<<<g, 256>>>(ed4);
        edge_exp_kernel<<<g, 256>>>(ed4);
    }
    scan_kernel<<<4, 1024>>>();
    scatter_kernel<<<dim3((NEDGE + 255) / 256, 4), 256>>>(ed4);
    agg_kernel<<<dim3((NNODES * 4 + 7) / 8, 4), 256>>>(ed4, bias4);

    // 4) semantic attention (batched x4) + fuse (x2)
    {
        GB gb = {};
        for (int z = 0; z < 4; z++) {
            gb.A[z] = p_z[z];
            gb.B[z] = W1[z >> 1];
            gb.C[z] = p_sc[z];
        }
        dim3 g(1, (NNODES + 63) / 64, 4);
        mma_gemm_b<2, false><<<g, 256>>>(gb, NNODES, SEMH, DDIM);
    }
    sem_score_kernel<<<dim3((NNODES + 7) / 8, 4), 256>>>(b14, W24);
    fuse_kernel<<<dim3((NNODES * DDIM + 255) / 256, 2), 256>>>();

    // 5) prediction heads (batched x2)
    {
        GB gb = {};
        gb.A[0] = p_fu[0]; gb.B[0] = pred[0]; gb.C[0] = h1;
        gb.A[1] = p_fu[1]; gb.B[1] = pred[1]; gb.C[1] = h2;
        dim3 g(1, (NNODES + 63) / 64, 2);
        mma_gemm_b<2, false><<<g, 256>>>(gb, NNODES, OSZ, DDIM);
    }
    // 6) prod = h1 @ h2^T
    {
        GB gb = {};
        gb.A[0] = h1; gb.B[0] = h2; gb.C[0] = prod;
        dim3 g((NNODES + 127) / 128, (NNODES + 127) / 128, 1);
        mma_gemm_b<4, true><<<g, 256>>>(gb, NNODES, NNODES, OSZ);
    }
}

// round 7
// speedup vs baseline: 2.3877x; 1.1494x over previous
#include <cuda_runtime.h>
#include <cstdint>

#define NNODES 10000
#define FDIM   256
#define DDIM   512
#define NEDGE  160000
#define NHEAD  8
#define SEMH   128
#define OSZ    64

// ---------------- scratch (static device globals; no allocation) ----------------
// instance index z in [0,4): branch = z>>1 (0=herb,1=target), metapath = z&1
__device__ float g_wh  [2][NNODES * FDIM];
__device__ float g_feat[4][NNODES * DDIM];
__device__ float g_z   [4][NNODES * DDIM];
__device__ float g_el  [4][NNODES * NHEAD];
__device__ float g_er  [4][NNODES * NHEAD];
__device__ float g_sm  [4][NNODES * NHEAD];
__device__ float g_ex  [4][NEDGE * NHEAD];
__device__ float g_sc  [4][NNODES * SEMH];
__device__ float g_w   [4][NNODES];
__device__ float g_fu  [2][NNODES * DDIM];
__device__ int   g_off [4][NNODES + 1];
__device__ int   g_cur [4][NNODES];
__device__ int2  g_eid2[4][NEDGE];

struct GB   { const float* A[4]; const float* B[4]; float* C[4]; };
struct IP4  { const int*   p[4]; };
struct FP4  { const float* p[4]; };

// ---------------- tf32 MMA GEMM, double-buffered, z-batched ----------------
// Block tile BM(=32*MT) x 128, K-tile 16. 256 threads = 8 warps in 2(m) x 4(n).
// Shared tiles pre-permuted into mma fragment order. B fragments for adjacent
// n-tiles are interleaved so each warp fetches TWO B frags with one LDS.128.

__device__ __forceinline__ unsigned f2tf(float f) {
    unsigned r;
    asm("cvt.rna.tf32.f32 %0, %1;" : "=r"(r) : "f"(f));
    return r;
}

template<int MT, bool TRANSB>
__global__ __launch_bounds__(256, 2) void mma_gemm_b(GB gb, int M, int N, int K) {
    constexpr int BM = 32 * MT;
    constexpr int AQ = (BM * 4) / 256;
    __shared__ unsigned sA[2][2][2 * MT][32][4];
    __shared__ unsigned sB[2][2][8][32][4];   // [buf][ks][ntp][lane][r]

    const float* __restrict__ A = gb.A[blockIdx.z];
    const float* __restrict__ B = gb.B[blockIdx.z];
    float* __restrict__ C = gb.C[blockIdx.z];

    int tid = threadIdx.x;
    int warp = tid >> 5, lane = tid & 31;
    int wm = warp >> 2, wn = warp & 3;
    int row0 = blockIdx.y * BM, col0 = blockIdx.x * 128;

    float4 ra[AQ];
    float4 rb[2];

    auto loadA = [&](int k0) {
#pragma unroll
        for (int it = 0; it < AQ; it++) {
            int i = tid * AQ + it;
            int r = i >> 2, c4 = i & 3;
            float4 v = make_float4(0.f, 0.f, 0.f, 0.f);
            int gr = row0 + r;
            if (gr < M) v = *(const float4*)(A + (size_t)gr * K + k0 + c4 * 4);
            ra[it] = v;
        }
    };
    auto storeA = [&](int buf) {
#pragma unroll
        for (int it = 0; it < AQ; it++) {
            int i = tid * AQ + it;
            int r = i >> 2, c4 = i & 3;
            int ks = c4 >> 1;
            int mt = r >> 4;
            int q  = ((r >> 3) & 1) + 2 * (c4 & 1);
            int tb = (r & 7) * 4;
            sA[buf][ks][mt][tb + 0][q] = f2tf(ra[it].x);
            sA[buf][ks][mt][tb + 1][q] = f2tf(ra[it].y);
            sA[buf][ks][mt][tb + 2][q] = f2tf(ra[it].z);
            sA[buf][ks][mt][tb + 3][q] = f2tf(ra[it].w);
        }
    };
    auto loadB = [&](int k0) {
#pragma unroll
        for (int it = 0; it < 2; it++) {
            int i = tid * 2 + it;
            float4 v = make_float4(0.f, 0.f, 0.f, 0.f);
            if (!TRANSB) {
                int kr = i >> 5, c4 = i & 31;
                int gc = col0 + c4 * 4;
                if (gc < N) v = *(const float4*)(B + (size_t)(k0 + kr) * N + gc);
            } else {
                int nr = i >> 2, c4 = i & 3;
                int gn = col0 + nr;
                if (gn < N) v = *(const float4*)(B + (size_t)gn * K + k0 + c4 * 4);
            }
            rb[it] = v;
        }
    };
    auto storeB = [&](int buf) {
#pragma unroll
        for (int it = 0; it < 2; it++) {
            int i = tid * 2 + it;
            if (!TRANSB) {
                int kr = i >> 5, c4 = i & 31;
                int ks = kr >> 3;
                int kk = kr & 7;
                int ntp = c4 >> 2;
                int r  = ((c4 >> 1) & 1) * 2 + (kk >> 2);
                int tb = 16 * (c4 & 1) + (kk & 3);
                sB[buf][ks][ntp][tb + 0 ][r] = f2tf(rb[it].x);
                sB[buf][ks][ntp][tb + 4 ][r] = f2tf(rb[it].y);
                sB[buf][ks][ntp][tb + 8 ][r] = f2tf(rb[it].z);
                sB[buf][ks][ntp][tb + 12][r] = f2tf(rb[it].w);
            } else {
                int nr = i >> 2, c4 = i & 3;
                int ks = c4 >> 1;
                int ntp = nr >> 4;
                int r  = ((nr >> 3) & 1) * 2 + (c4 & 1);
                int tb = (nr & 7) * 4;
                sB[buf][ks][ntp][tb + 0][r] = f2tf(rb[it].x);
                sB[buf][ks][ntp][tb + 1][r] = f2tf(rb[it].y);
                sB[buf][ks][ntp][tb + 2][r] = f2tf(rb[it].z);
                sB[buf][ks][ntp][tb + 3][r] = f2tf(rb[it].w);
            }
        }
    };

    float acc[MT][4][4];
#pragma unroll
    for (int i = 0; i < MT; i++)
#pragma unroll
        for (int j = 0; j < 4; j++)
#pragma unroll
            for (int q = 0; q < 4; q++) acc[i][j][q] = 0.f;

    int nk = K >> 4;
    loadA(0); loadB(0);
    storeA(0); storeB(0);
    __syncthreads();

    for (int t = 0; t < nk; t++) {
        int buf = t & 1;
        if (t + 1 < nk) { loadA((t + 1) * 16); loadB((t + 1) * 16); }

#pragma unroll
        for (int ks = 0; ks < 2; ks++) {
            uint4 af[MT];
            uint2 bf[4];
#pragma unroll
            for (int mt = 0; mt < MT; mt++)
                af[mt] = *(const uint4*)&sA[buf][ks][wm * MT + mt][lane][0];
#pragma unroll
            for (int p = 0; p < 2; p++) {
                uint4 u = *(const uint4*)&sB[buf][ks][wn * 2 + p][lane][0];
                bf[2 * p + 0] = make_uint2(u.x, u.y);
                bf[2 * p + 1] = make_uint2(u.z, u.w);
            }
#pragma unroll
            for (int mt = 0; mt < MT; mt++)
#pragma unroll
                for (int nt = 0; nt < 4; nt++) {
                    asm volatile(
                        "mma.sync.aligned.m16n8k8.row.col.f32.tf32.tf32.f32 "
                        "{%0,%1,%2,%3}, {%4,%5,%6,%7}, {%8,%9}, {%0,%1,%2,%3};"
                        : "+f"(acc[mt][nt][0]), "+f"(acc[mt][nt][1]),
                          "+f"(acc[mt][nt][2]), "+f"(acc[mt][nt][3])
                        : "r"(af[mt].x), "r"(af[mt].y), "r"(af[mt].z), "r"(af[mt].w),
                          "r"(bf[nt].x), "r"(bf[nt].y));
                }
        }
        if (t + 1 < nk) { storeA(buf ^ 1); storeB(buf ^ 1); }
        __syncthreads();
    }

#pragma unroll
    for (int mt = 0; mt < MT; mt++) {
        int r_base = row0 + wm * (MT * 16) + mt * 16 + (lane >> 2);
#pragma unroll
        for (int nt = 0; nt < 4; nt++) {
            int c = col0 + wn * 32 + nt * 8 + (lane & 3) * 2;
            if (c < N) {
                if (r_base < M)
                    *(float2*)(C + (size_t)r_base * N + c) =
                        make_float2(acc[mt][nt][0], acc[mt][nt][1]);
                if (r_base + 8 < M)
                    *(float2*)(C + (size_t)(r_base + 8) * N + c) =
                        make_float2(acc[mt][nt][2], acc[mt][nt][3]);
            }
        }
    }
}

// ---------------- GAT kernels (grid.y = instance z) ----------------

__global__ void eler_kernel(FP4 al4, FP4 ar4) {
    int z = blockIdx.y;
    int w = blockIdx.x * 8 + (threadIdx.x >> 5);
    int lane = threadIdx.x & 31;
    if (w >= NNODES * NHEAD) return;
    int n = w >> 3, h = w & 7;
    const float* al = al4.p[z];
    const float* ar = ar4.p[z];
    const float* f = g_feat[z] + (size_t)n * DDIM + h * 64;
    float sl = f[lane] * al[h * 64 + lane] + f[lane + 32] * al[h * 64 + lane + 32];
    float sr = f[lane] * ar[h * 64 + lane] + f[lane + 32] * ar[h * 64 + lane + 32];
#pragma unroll
    for (int o = 16; o > 0; o >>= 1) {
        sl += __shfl_down_sync(0xffffffffu, sl, o);
        sr += __shfl_down_sync(0xffffffffu, sr, o);
    }
    if (lane == 0) {
        g_el[z][w] = sl;
        g_er[z][w] = sr;
        g_sm[z][w] = 0.f;
    }
}

// degree histogram only (per edge)
__global__ void count_kernel(IP4 ed4) {
    int z = blockIdx.y;
    int i = blockIdx.x * blockDim.x + threadIdx.x;
    if (i >= NEDGE) return;
    atomicAdd(&g_cur[z][ed4.p[z][NEDGE + i]], 1);
}

// per-instance single-block exclusive scan (grid.x = instance)
__global__ void scan_kernel() {
    int z = blockIdx.x;
    int* cur = g_cur[z];
    int* off = g_off[z];
    __shared__ int part[1024];
    int t = threadIdx.x;
    int base = t * 10;
    int v[10];
    int s = 0;
#pragma unroll
    for (int j = 0; j < 10; j++) {
        int idx = base + j;
        int c = (idx < NNODES) ? cur[idx] : 0;
        v[j] = c;
        s += c;
    }
    part[t] = s;
    __syncthreads();
    for (int o = 1; o < 1024; o <<= 1) {
        int x = (t >= o) ? part[t - o] : 0;
        __syncthreads();
        part[t] += x;
        __syncthreads();
    }
    int run = (t > 0) ? part[t - 1] : 0;
#pragma unroll
    for (int j = 0; j < 10; j++) {
        int idx = base + j;
        if (idx < NNODES) {
            off[idx] = run;
            cur[idx] = run;
            run += v[j];
        }
    }
    if (t == 0) off[NNODES] = NEDGE;
}

// fused: leaky_relu + exp (softmax is shift-invariant; logits are small so no
// max subtraction needed) + per-dst sum + CSR scatter of (edge, src) pairs.
__global__ void exp_scatter_kernel(IP4 ed4) {
    int z = blockIdx.y;
    int e = blockIdx.x * blockDim.x + threadIdx.x;
    if (e >= NEDGE) return;
    const int* ed = ed4.p[z];
    int s = ed[e], d = ed[NEDGE + e];
    float4 l0 = *(const float4*)&g_el[z][s * NHEAD];
    float4 l1 = *(const float4*)&g_el[z][s * NHEAD + 4];
    float4 r0 = *(const float4*)&g_er[z][d * NHEAD];
    float4 r1 = *(const float4*)&g_er[z][d * NHEAD + 4];
    float v[8] = {l0.x + r0.x, l0.y + r0.y, l0.z + r0.z, l0.w + r0.w,
                  l1.x + r1.x, l1.y + r1.y, l1.z + r1.z, l1.w + r1.w};
    float ex[8];
#pragma unroll
    for (int h = 0; h < 8; h++) {
        float t = v[h] > 0.f ? v[h] : 0.2f * v[h];
        ex[h] = __expf(t);
    }
    *(float4*)&g_ex[z][(size_t)e * NHEAD]     = make_float4(ex[0], ex[1], ex[2], ex[3]);
    *(float4*)&g_ex[z][(size_t)e * NHEAD + 4] = make_float4(ex[4], ex[5], ex[6], ex[7]);
#pragma unroll
    for (int h = 0; h < 8; h++) atomicAdd(&g_sm[z][d * NHEAD + h], ex[h]);
    int p = atomicAdd(&g_cur[z][d], 1);
    g_eid2[z][p] = make_int2(e, s);
}

// gather-aggregate: one warp per (dst node, 128-col strip); bias+ELU fused.
// distance-2 prefetch on the (edge,src) stream so eid2/ex/feat overlap.
__global__ __launch_bounds__(256) void agg_kernel(FP4 bias4) {
    int z = blockIdx.y;
    int wid = blockIdx.x * 8 + (threadIdx.x >> 5);
    if (wid >= NNODES * 4) return;
    const float* bias = bias4.p[z];
    const float* __restrict__ feat = g_feat[z];
    const float* __restrict__ ex = g_ex[z];
    const int2* __restrict__ eid2 = g_eid2[z];
    int d = wid >> 2, strip = wid & 3;
    int lane = threadIdx.x & 31;
    int col = strip * 128 + lane * 4;
    int head = col >> 6;
    float rcp = 1.f / g_sm[z][d * NHEAD + head];

    float4 acc = make_float4(0.f, 0.f, 0.f, 0.f);
    int b = g_off[z][d], e_ = g_off[z][d + 1];
    if (b < e_) {
        int2 peA = eid2[b];
        int2 peB = (b + 1 < e_) ? eid2[b + 1] : peA;
        float axA = ex[(size_t)peA.x * NHEAD + head];
        for (int i = b; i < e_; i++) {
            int2 peC = (i + 2 < e_) ? eid2[i + 2] : peB;
            float axB = (i + 1 < e_) ? ex[(size_t)peB.x * NHEAD + head] : 0.f;
            float4 f = *(const float4*)(feat + (size_t)peA.y * DDIM + col);
            float a = axA * rcp;
            acc.x += f.x * a;
            acc.y += f.y * a;
            acc.z += f.z * a;
            acc.w += f.w * a;
            peA = peB; peB = peC; axA = axB;
        }
    }
    float4 bb = *(const float4*)(bias + col);
    float4 v;
    v.x = acc.x + bb.x; v.x = v.x > 0.f ? v.x : (__expf(v.x) - 1.f);
    v.y = acc.y + bb.y; v.y = v.y > 0.f ? v.y : (__expf(v.y) - 1.f);
    v.z = acc.z + bb.z; v.z = v.z > 0.f ? v.z : (__expf(v.z) - 1.f);
    v.w = acc.w + bb.w; v.w = v.w > 0.f ? v.w : (__expf(v.w) - 1.f);
    *(float4*)(g_z[z] + (size_t)d * DDIM + col) = v;
}

// ---------------- semantic attention ----------------

__global__ void sem_score_kernel(FP4 b14, FP4 W24) {
    int z = blockIdx.y;
    int w = blockIdx.x * 8 + (threadIdx.x >> 5);
    int lane = threadIdx.x & 31;
    if (w >= NNODES) return;
    const float* b1 = b14.p[z];
    const float* W2 = W24.p[z];
    float t = 0.f;
#pragma unroll
    for (int q = 0; q < 4; q++) {
        int j = lane + 32 * q;
        t += tanhf(g_sc[z][(size_t)w * SEMH + j] + b1[j]) * W2[j];
    }
#pragma unroll
    for (int o = 16; o > 0; o >>= 1) t += __shfl_down_sync(0xffffffffu, t, o);
    if (lane == 0) g_w[z][w] = t;
}

__global__ void fuse_kernel() {
    int b = blockIdx.y;
    int i = blockIdx.x * blockDim.x + threadIdx.x;
    if (i >= NNODES * DDIM) return;
    int n = i >> 9;
    float a = g_w[2 * b][n], c = g_w[2 * b + 1][n];
    float m = fmaxf(a, c);
    float ea = __expf(a - m), eb = __expf(c - m);
    float be = ea / (ea + eb);
    g_fu[b][i] = be * g_z[2 * b][i] + (1.f - be) * g_z[2 * b + 1][i];
}

// ---------------- host orchestration ----------------

extern "C" void kernel_launch(void* const* d_in, const int* in_sizes, int n_in,
                              void* d_out, int out_size) {
    float *p_wh0, *p_wh1, *p_feat[4], *p_z[4], *p_sc[4], *p_fu[2];
    {
        float* base;
        cudaGetSymbolAddress((void**)&base, g_wh);
        p_wh0 = base; p_wh1 = base + (size_t)NNODES * FDIM;
        cudaGetSymbolAddress((void**)&base, g_feat);
        for (int z = 0; z < 4; z++) p_feat[z] = base + (size_t)z * NNODES * DDIM;
        cudaGetSymbolAddress((void**)&base, g_z);
        for (int z = 0; z < 4; z++) p_z[z] = base + (size_t)z * NNODES * DDIM;
        cudaGetSymbolAddress((void**)&base, g_sc);
        for (int z = 0; z < 4; z++) p_sc[z] = base + (size_t)z * NNODES * SEMH;
        cudaGetSymbolAddress((void**)&base, g_fu);
        for (int b = 0; b < 2; b++) p_fu[b] = base + (size_t)b * NNODES * DDIM;
    }
    int* p_cur;
    cudaGetSymbolAddress((void**)&p_cur, g_cur);

    const float* hx = (const float*)d_in[0];
    const float* tx = (const float*)d_in[1];
    const float* w_h[2]  = {(const float*)d_in[2],  (const float*)d_in[11]};
    const float* fc[2]   = {(const float*)d_in[3],  (const float*)d_in[12]};
    const float* al[2]   = {(const float*)d_in[4],  (const float*)d_in[13]};
    const float* ar[2]   = {(const float*)d_in[5],  (const float*)d_in[14]};
    const float* bias[2] = {(const float*)d_in[6],  (const float*)d_in[15]};
    const float* W1[2]   = {(const float*)d_in[7],  (const float*)d_in[16]};
    const float* b1[2]   = {(const float*)d_in[8],  (const float*)d_in[17]};
    const float* W2[2]   = {(const float*)d_in[9],  (const float*)d_in[18]};
    const float* pred[2] = {(const float*)d_in[10], (const float*)d_in[19]};

    IP4 ed4 = {{(const int*)d_in[20], (const int*)d_in[21],
                (const int*)d_in[22], (const int*)d_in[23]}};
    FP4 al4   = {{al[0], al[0] + NHEAD * 64, al[1], al[1] + NHEAD * 64}};
    FP4 ar4   = {{ar[0], ar[0] + NHEAD * 64, ar[1], ar[1] + NHEAD * 64}};
    FP4 bias4 = {{bias[0], bias[0] + DDIM, bias[1], bias[1] + DDIM}};
    FP4 b14   = {{b1[0], b1[0], b1[1], b1[1]}};
    FP4 W24   = {{W2[0], W2[0], W2[1], W2[1]}};

    float* out  = (float*)d_out;
    float* h1   = out;
    float* h2   = out + (size_t)NNODES * OSZ;
    float* prod = out + (size_t)2 * NNODES * OSZ;

    // 0) clear histograms, build CSR offsets (edge-only work, before GEMMs)
    cudaMemsetAsync(p_cur, 0, 4 * NNODES * sizeof(int), 0);
    count_kernel<<<dim3((NEDGE + 255) / 256, 4), 256>>>(ed4);
    scan_kernel<<<4, 1024>>>();

    // 1) wh = x @ w_h   (batched x2)
    {
        GB gb = {};
        gb.A[0] = hx;     gb.B[0] = w_h[0]; gb.C[0] = p_wh0;
        gb.A[1] = tx;     gb.B[1] = w_h[1]; gb.C[1] = p_wh1;
        dim3 g(FDIM / 128, (NNODES + 127) / 128, 2);
        mma_gemm_b<4, false><<<g, 256>>>(gb, NNODES, FDIM, FDIM);
    }
    // 2) feat = wh @ fc  (batched x4)
    {
        GB gb = {};
        const float* whp[2] = {p_wh0, p_wh1};
        for (int z = 0; z < 4; z++) {
            gb.A[z] = whp[z >> 1];
            gb.B[z] = fc[z >> 1] + (size_t)(z & 1) * FDIM * DDIM;
            gb.C[z] = p_feat[z];
        }
        dim3 g(DDIM / 128, (NNODES + 127) / 128, 4);
        mma_gemm_b<4, false><<<g, 256>>>(gb, NNODES, DDIM, FDIM);
    }
    // 3) logits + fused exp/sum/scatter + aggregate (all x4)
    eler_kernel<<<dim3(NNODES, 4), 256>>>(al4, ar4);
    exp_scatter_kernel<<<dim3((NEDGE + 255) / 256, 4), 256>>>(ed4);
    agg_kernel<<<dim3((NNODES * 4 + 7) / 8, 4), 256>>>(bias4);

    // 4) semantic attention (batched x4) + fuse (x2)
    {
        GB gb = {};
        for (int z = 0; z < 4; z++) {
            gb.A[z] = p_z[z];
            gb.B[z] = W1[z >> 1];
            gb.C[z] = p_sc[z];
        }
        dim3 g(1, (NNODES + 63) / 64, 4);
        mma_gemm_b<2, false><<<g, 256>>>(gb, NNODES, SEMH, DDIM);
    }
    sem_score_kernel<<<dim3((NNODES + 7) / 8, 4), 256>>>(b14, W24);
    fuse_kernel<<<dim3((NNODES * DDIM + 255) / 256, 2), 256>>>();

    // 5) prediction heads (batched x2)
    {
        GB gb = {};
        gb.A[0] = p_fu[0]; gb.B[0] = pred[0]; gb.C[0] = h1;
        gb.A[1] = p_fu[1]; gb.B[1] = pred[1]; gb.C[1] = h2;
        dim3 g(1, (NNODES + 63) / 64, 2);
        mma_gemm_b<2, false><<<g, 256>>>(gb, NNODES, OSZ, DDIM);
    }
    // 6) prod = h1 @ h2^T
    {
        GB gb = {};
        gb.A[0] = h1; gb.B[0] = h2; gb.C[0] = prod;
        dim3 g((NNODES + 127) / 128, (NNODES + 127) / 128, 1);
        mma_gemm_b<4, true><<<g, 256>>>(gb, NNODES, NNODES, OSZ);
    }
}

// round 8
// speedup vs baseline: 2.7041x; 1.1325x over previous
#include <cuda_runtime.h>
#include <cstdint>

#define NNODES 10000
#define FDIM   256
#define DDIM   512
#define NEDGE  160000
#define NHEAD  8
#define SEMH   128
#define OSZ    64

// ---------------- scratch (static device globals; no allocation) ----------------
// instance index z in [0,4): branch = z>>1 (0=herb,1=target), metapath = z&1
__device__ float g_wh  [2][NNODES * FDIM];
__device__ float g_feat[4][NNODES * DDIM];
__device__ float g_z   [4][NNODES * DDIM];
__device__ float g_el  [4][NNODES * NHEAD];
__device__ float g_er  [4][NNODES * NHEAD];
__device__ float g_sm  [4][NNODES * NHEAD];
__device__ float g_ex  [4][NEDGE * NHEAD];
__device__ float g_sc  [4][NNODES * SEMH];
__device__ float g_w   [4][NNODES];
__device__ float g_fu  [2][NNODES * DDIM];
__device__ int   g_off [4][NNODES + 1];
__device__ int   g_cur [4][NNODES];
__device__ int2  g_eid2[4][NEDGE];

struct GB   { const float* A[4]; const float* B[4]; float* C[4]; };
struct IP4  { const int*   p[4]; };
struct FP4  { const float* p[4]; };

// ---------------- tf32 MMA GEMM, double-buffered, z-batched ----------------
// Block tile BM(=32*MT) x 128, K-tile 16. 256 threads = 8 warps in 2(m) x 4(n).
// FRAGMENT-DIRECT staging: each thread loads the 4 scalars of one fragment
// slot straight from global (sector-coalesced LDG.32 pattern), converts to
// tf32, and writes ONE conflict-free STS.128 per slot (warp stores 512B
// contiguous). Mainloop reads are 1 LDS.128 per A frag / per B frag-pair.

__device__ __forceinline__ unsigned f2tf(float f) {
    unsigned r;
    asm("cvt.rna.tf32.f32 %0, %1;" : "=r"(r) : "f"(f));
    return r;
}

template<int MT, bool TRANSB>
__global__ __launch_bounds__(256, 2) void mma_gemm_b(GB gb, int M, int N, int K) {
    constexpr int BM = 32 * MT;
    constexpr int NSA = (MT + 1) / 2;          // A slots per thread (MT=4 ->2, MT=2 ->1)
    __shared__ unsigned sA[2][2][2 * MT][32][4];  // [buf][ks][mt][lane][q]
    __shared__ unsigned sB[2][2][8][32][4];       // [buf][ks][ntp][lane][r]

    const float* __restrict__ A = gb.A[blockIdx.z];
    const float* __restrict__ B = gb.B[blockIdx.z];
    float* __restrict__ C = gb.C[blockIdx.z];

    int tid = threadIdx.x;
    int warp = tid >> 5, lane = tid & 31;
    int wm = warp >> 2, wn = warp & 3;
    int row0 = blockIdx.y * BM, col0 = blockIdx.x * 128;

    float av[NSA][4];
    float bv[2][4];

    // A slot decode for thread slot s = tid + j*256:
    //   lane = s&31, srow = s>>5 in [0, 4MT): ks = srow/(2MT), mt = srow%(2MT)
    //   values: rows R0, R0+8 (R0 = mt*16 + lane>>2), cols C0, C0+4
    //   (C0 = ks*8 + (lane&3)); q order: (R0,C0),(R0+8,C0),(R0,C0+4),(R0+8,C0+4)
    auto loadA = [&](int k0) {
#pragma unroll
        for (int j = 0; j < NSA; j++) {
            int s = tid + j * 256;
            int ln = s & 31;
            int srow = s >> 5;
            int ks = srow / (2 * MT);
            int mt = srow % (2 * MT);
            int gr0 = row0 + mt * 16 + (ln >> 2);
            int gr1 = gr0 + 8;
            int cc = k0 + ks * 8 + (ln & 3);
            const float* p0 = A + (size_t)gr0 * K + cc;
            const float* p1 = A + (size_t)gr1 * K + cc;
            av[j][0] = (gr0 < M) ? p0[0] : 0.f;
            av[j][1] = (gr1 < M) ? p1[0] : 0.f;
            av[j][2] = (gr0 < M) ? p0[4] : 0.f;
            av[j][3] = (gr1 < M) ? p1[4] : 0.f;
        }
    };
    auto storeA = [&](int buf) {
#pragma unroll
        for (int j = 0; j < NSA; j++) {
            int s = tid + j * 256;
            int ln = s & 31;
            int srow = s >> 5;
            int ks = srow / (2 * MT);
            int mt = srow % (2 * MT);
            uint4 u = make_uint4(f2tf(av[j][0]), f2tf(av[j][1]),
                                 f2tf(av[j][2]), f2tf(av[j][3]));
            *(uint4*)&sA[buf][ks][mt][ln][0] = u;
        }
    };
    // B slot decode for s = tid + j*256: lane = s&31, srow = s>>5 in [0,16):
    //   ks = srow>>3, ntp = srow&7; nl = lane>>2 (n within octet), k3 = lane&3
    //   values (r order): (col gc0, k kk),(gc0,kk+4),(gc0+8,kk),(gc0+8,kk+4)
    auto loadB = [&](int k0) {
#pragma unroll
        for (int j = 0; j < 2; j++) {
            int s = tid + j * 256;
            int ln = s & 31;
            int srow = s >> 5;
            int ks = srow >> 3;
            int ntp = srow & 7;
            int kk = k0 + ks * 8 + (ln & 3);
            int gc0 = col0 + ntp * 16 + (ln >> 2);
            int gc1 = gc0 + 8;
            if (!TRANSB) {
                const float* pk0 = B + (size_t)kk * N;
                const float* pk4 = B + (size_t)(kk + 4) * N;
                bv[j][0] = (gc0 < N) ? pk0[gc0] : 0.f;
                bv[j][1] = (gc0 < N) ? pk4[gc0] : 0.f;
                bv[j][2] = (gc1 < N) ? pk0[gc1] : 0.f;
                bv[j][3] = (gc1 < N) ? pk4[gc1] : 0.f;
            } else {
                const float* pn0 = B + (size_t)gc0 * K + kk;
                const float* pn1 = B + (size_t)gc1 * K + kk;
                bv[j][0] = (gc0 < N) ? pn0[0] : 0.f;
                bv[j][1] = (gc0 < N) ? pn0[4] : 0.f;
                bv[j][2] = (gc1 < N) ? pn1[0] : 0.f;
                bv[j][3] = (gc1 < N) ? pn1[4] : 0.f;
            }
        }
    };
    auto storeB = [&](int buf) {
#pragma unroll
        for (int j = 0; j < 2; j++) {
            int s = tid + j * 256;
            int ln = s & 31;
            int srow = s >> 5;
            int ks = srow >> 3;
            int ntp = srow & 7;
            uint4 u = make_uint4(f2tf(bv[j][0]), f2tf(bv[j][1]),
                                 f2tf(bv[j][2]), f2tf(bv[j][3]));
            *(uint4*)&sB[buf][ks][ntp][ln][0] = u;
        }
    };

    float acc[MT][4][4];
#pragma unroll
    for (int i = 0; i < MT; i++)
#pragma unroll
        for (int j = 0; j < 4; j++)
#pragma unroll
            for (int q = 0; q < 4; q++) acc[i][j][q] = 0.f;

    int nk = K >> 4;
    loadA(0); loadB(0);
    storeA(0); storeB(0);
    __syncthreads();

    for (int t = 0; t < nk; t++) {
        int buf = t & 1;
        if (t + 1 < nk) { loadA((t + 1) * 16); loadB((t + 1) * 16); }

#pragma unroll
        for (int ks = 0; ks < 2; ks++) {
            uint4 af[MT];
            uint2 bf[4];
#pragma unroll
            for (int mt = 0; mt < MT; mt++)
                af[mt] = *(const uint4*)&sA[buf][ks][wm * MT + mt][lane][0];
#pragma unroll
            for (int p = 0; p < 2; p++) {
                uint4 u = *(const uint4*)&sB[buf][ks][wn * 2 + p][lane][0];
                bf[2 * p + 0] = make_uint2(u.x, u.y);
                bf[2 * p + 1] = make_uint2(u.z, u.w);
            }
#pragma unroll
            for (int mt = 0; mt < MT; mt++)
#pragma unroll
                for (int nt = 0; nt < 4; nt++) {
                    asm volatile(
                        "mma.sync.aligned.m16n8k8.row.col.f32.tf32.tf32.f32 "
                        "{%0,%1,%2,%3}, {%4,%5,%6,%7}, {%8,%9}, {%0,%1,%2,%3};"
                        : "+f"(acc[mt][nt][0]), "+f"(acc[mt][nt][1]),
                          "+f"(acc[mt][nt][2]), "+f"(acc[mt][nt][3])
                        : "r"(af[mt].x), "r"(af[mt].y), "r"(af[mt].z), "r"(af[mt].w),
                          "r"(bf[nt].x), "r"(bf[nt].y));
                }
        }
        if (t + 1 < nk) { storeA(buf ^ 1); storeB(buf ^ 1); }
        __syncthreads();
    }

#pragma unroll
    for (int mt = 0; mt < MT; mt++) {
        int r_base = row0 + wm * (MT * 16) + mt * 16 + (lane >> 2);
#pragma unroll
        for (int nt = 0; nt < 4; nt++) {
            int c = col0 + wn * 32 + nt * 8 + (lane & 3) * 2;
            if (c < N) {
                if (r_base < M)
                    *(float2*)(C + (size_t)r_base * N + c) =
                        make_float2(acc[mt][nt][0], acc[mt][nt][1]);
                if (r_base + 8 < M)
                    *(float2*)(C + (size_t)(r_base + 8) * N + c) =
                        make_float2(acc[mt][nt][2], acc[mt][nt][3]);
            }
        }
    }
}

// ---------------- GAT kernels (grid.y = instance z) ----------------

__global__ void eler_kernel(FP4 al4, FP4 ar4) {
    int z = blockIdx.y;
    int w = blockIdx.x * 8 + (threadIdx.x >> 5);
    int lane = threadIdx.x & 31;
    if (w >= NNODES * NHEAD) return;
    int n = w >> 3, h = w & 7;
    const float* al = al4.p[z];
    const float* ar = ar4.p[z];
    const float* f = g_feat[z] + (size_t)n * DDIM + h * 64;
    float sl = f[lane] * al[h * 64 + lane] + f[lane + 32] * al[h * 64 + lane + 32];
    float sr = f[lane] * ar[h * 64 + lane] + f[lane + 32] * ar[h * 64 + lane + 32];
#pragma unroll
    for (int o = 16; o > 0; o >>= 1) {
        sl += __shfl_down_sync(0xffffffffu, sl, o);
        sr += __shfl_down_sync(0xffffffffu, sr, o);
    }
    if (lane == 0) {
        g_el[z][w] = sl;
        g_er[z][w] = sr;
        g_sm[z][w] = 0.f;
    }
}

// degree histogram only (per edge)
__global__ void count_kernel(IP4 ed4) {
    int z = blockIdx.y;
    int i = blockIdx.x * blockDim.x + threadIdx.x;
    if (i >= NEDGE) return;
    atomicAdd(&g_cur[z][ed4.p[z][NEDGE + i]], 1);
}

// per-instance single-block exclusive scan (grid.x = instance)
__global__ void scan_kernel() {
    int z = blockIdx.x;
    int* cur = g_cur[z];
    int* off = g_off[z];
    __shared__ int part[1024];
    int t = threadIdx.x;
    int base = t * 10;
    int v[10];
    int s = 0;
#pragma unroll
    for (int j = 0; j < 10; j++) {
        int idx = base + j;
        int c = (idx < NNODES) ? cur[idx] : 0;
        v[j] = c;
        s += c;
    }
    part[t] = s;
    __syncthreads();
    for (int o = 1; o < 1024; o <<= 1) {
        int x = (t >= o) ? part[t - o] : 0;
        __syncthreads();
        part[t] += x;
        __syncthreads();
    }
    int run = (t > 0) ? part[t - 1] : 0;
#pragma unroll
    for (int j = 0; j < 10; j++) {
        int idx = base + j;
        if (idx < NNODES) {
            off[idx] = run;
            cur[idx] = run;
            run += v[j];
        }
    }
    if (t == 0) off[NNODES] = NEDGE;
}

// fused: leaky_relu + exp (softmax is shift-invariant; logits are small so no
// max subtraction needed) + per-dst sum + CSR scatter of (edge, src) pairs.
__global__ void exp_scatter_kernel(IP4 ed4) {
    int z = blockIdx.y;
    int e = blockIdx.x * blockDim.x + threadIdx.x;
    if (e >= NEDGE) return;
    const int* ed = ed4.p[z];
    int s = ed[e], d = ed[NEDGE + e];
    float4 l0 = *(const float4*)&g_el[z][s * NHEAD];
    float4 l1 = *(const float4*)&g_el[z][s * NHEAD + 4];
    float4 r0 = *(const float4*)&g_er[z][d * NHEAD];
    float4 r1 = *(const float4*)&g_er[z][d * NHEAD + 4];
    float v[8] = {l0.x + r0.x, l0.y + r0.y, l0.z + r0.z, l0.w + r0.w,
                  l1.x + r1.x, l1.y + r1.y, l1.z + r1.z, l1.w + r1.w};
    float ex[8];
#pragma unroll
    for (int h = 0; h < 8; h++) {
        float t = v[h] > 0.f ? v[h] : 0.2f * v[h];
        ex[h] = __expf(t);
    }
    *(float4*)&g_ex[z][(size_t)e * NHEAD]     = make_float4(ex[0], ex[1], ex[2], ex[3]);
    *(float4*)&g_ex[z][(size_t)e * NHEAD + 4] = make_float4(ex[4], ex[5], ex[6], ex[7]);
#pragma unroll
    for (int h = 0; h < 8; h++) atomicAdd(&g_sm[z][d * NHEAD + h], ex[h]);
    int p = atomicAdd(&g_cur[z][d], 1);
    g_eid2[z][p] = make_int2(e, s);
}

// gather-aggregate: one warp per (dst node, 128-col strip); bias+ELU fused.
// distance-2 prefetch on the (edge,src) stream so eid2/ex/feat overlap.
__global__ __launch_bounds__(256) void agg_kernel(FP4 bias4) {
    int z = blockIdx.y;
    int wid = blockIdx.x * 8 + (threadIdx.x >> 5);
    if (wid >= NNODES * 4) return;
    const float* bias = bias4.p[z];
    const float* __restrict__ feat = g_feat[z];
    const float* __restrict__ ex = g_ex[z];
    const int2* __restrict__ eid2 = g_eid2[z];
    int d = wid >> 2, strip = wid & 3;
    int lane = threadIdx.x & 31;
    int col = strip * 128 + lane * 4;
    int head = col >> 6;
    float rcp = 1.f / g_sm[z][d * NHEAD + head];

    float4 acc = make_float4(0.f, 0.f, 0.f, 0.f);
    int b = g_off[z][d], e_ = g_off[z][d + 1];
    if (b < e_) {
        int2 peA = eid2[b];
        int2 peB = (b + 1 < e_) ? eid2[b + 1] : peA;
        float axA = ex[(size_t)peA.x * NHEAD + head];
        for (int i = b; i < e_; i++) {
            int2 peC = (i + 2 < e_) ? eid2[i + 2] : peB;
            float axB = (i + 1 < e_) ? ex[(size_t)peB.x * NHEAD + head] : 0.f;
            float4 f = *(const float4*)(feat + (size_t)peA.y * DDIM + col);
            float a = axA * rcp;
            acc.x += f.x * a;
            acc.y += f.y * a;
            acc.z += f.z * a;
            acc.w += f.w * a;
            peA = peB; peB = peC; axA = axB;
        }
    }
    float4 bb = *(const float4*)(bias + col);
    float4 v;
    v.x = acc.x + bb.x; v.x = v.x > 0.f ? v.x : (__expf(v.x) - 1.f);
    v.y = acc.y + bb.y; v.y = v.y > 0.f ? v.y : (__expf(v.y) - 1.f);
    v.z = acc.z + bb.z; v.z = v.z > 0.f ? v.z : (__expf(v.z) - 1.f);
    v.w = acc.w + bb.w; v.w = v.w > 0.f ? v.w : (__expf(v.w) - 1.f);
    *(float4*)(g_z[z] + (size_t)d * DDIM + col) = v;
}

// ---------------- semantic attention ----------------

__global__ void sem_score_kernel(FP4 b14, FP4 W24) {
    int z = blockIdx.y;
    int w = blockIdx.x * 8 + (threadIdx.x >> 5);
    int lane = threadIdx.x & 31;
    if (w >= NNODES) return;
    const float* b1 = b14.p[z];
    const float* W2 = W24.p[z];
    float t = 0.f;
#pragma unroll
    for (int q = 0; q < 4; q++) {
        int j = lane + 32 * q;
        t += tanhf(g_sc[z][(size_t)w * SEMH + j] + b1[j]) * W2[j];
    }
#pragma unroll
    for (int o = 16; o > 0; o >>= 1) t += __shfl_down_sync(0xffffffffu, t, o);
    if (lane == 0) g_w[z][w] = t;
}

__global__ void fuse_kernel() {
    int b = blockIdx.y;
    int i = blockIdx.x * blockDim.x + threadIdx.x;
    if (i >= NNODES * DDIM) return;
    int n = i >> 9;
    float a = g_w[2 * b][n], c = g_w[2 * b + 1][n];
    float m = fmaxf(a, c);
    float ea = __expf(a - m), eb = __expf(c - m);
    float be = ea / (ea + eb);
    g_fu[b][i] = be * g_z[2 * b][i] + (1.f - be) * g_z[2 * b + 1][i];
}

// ---------------- host orchestration ----------------

extern "C" void kernel_launch(void* const* d_in, const int* in_sizes, int n_in,
                              void* d_out, int out_size) {
    float *p_wh0, *p_wh1, *p_feat[4], *p_z[4], *p_sc[4], *p_fu[2];
    {
        float* base;
        cudaGetSymbolAddress((void**)&base, g_wh);
        p_wh0 = base; p_wh1 = base + (size_t)NNODES * FDIM;
        cudaGetSymbolAddress((void**)&base, g_feat);
        for (int z = 0; z < 4; z++) p_feat[z] = base + (size_t)z * NNODES * DDIM;
        cudaGetSymbolAddress((void**)&base, g_z);
        for (int z = 0; z < 4; z++) p_z[z] = base + (size_t)z * NNODES * DDIM;
        cudaGetSymbolAddress((void**)&base, g_sc);
        for (int z = 0; z < 4; z++) p_sc[z] = base + (size_t)z * NNODES * SEMH;
        cudaGetSymbolAddress((void**)&base, g_fu);
        for (int b = 0; b < 2; b++) p_fu[b] = base + (size_t)b * NNODES * DDIM;
    }
    int* p_cur;
    cudaGetSymbolAddress((void**)&p_cur, g_cur);

    const float* hx = (const float*)d_in[0];
    const float* tx = (const float*)d_in[1];
    const float* w_h[2]  = {(const float*)d_in[2],  (const float*)d_in[11]};
    const float* fc[2]   = {(const float*)d_in[3],  (const float*)d_in[12]};
    const float* al[2]   = {(const float*)d_in[4],  (const float*)d_in[13]};
    const float* ar[2]   = {(const float*)d_in[5],  (const float*)d_in[14]};
    const float* bias[2] = {(const float*)d_in[6],  (const float*)d_in[15]};
    const float* W1[2]   = {(const float*)d_in[7],  (const float*)d_in[16]};
    const float* b1[2]   = {(const float*)d_in[8],  (const float*)d_in[17]};
    const float* W2[2]   = {(const float*)d_in[9],  (const float*)d_in[18]};
    const float* pred[2] = {(const float*)d_in[10], (const float*)d_in[19]};

    IP4 ed4 = {{(const int*)d_in[20], (const int*)d_in[21],
                (const int*)d_in[22], (const int*)d_in[23]}};
    FP4 al4   = {{al[0], al[0] + NHEAD * 64, al[1], al[1] + NHEAD * 64}};
    FP4 ar4   = {{ar[0], ar[0] + NHEAD * 64, ar[1], ar[1] + NHEAD * 64}};
    FP4 bias4 = {{bias[0], bias[0] + DDIM, bias[1], bias[1] + DDIM}};
    FP4 b14   = {{b1[0], b1[0], b1[1], b1[1]}};
    FP4 W24   = {{W2[0], W2[0], W2[1], W2[1]}};

    float* out  = (float*)d_out;
    float* h1   = out;
    float* h2   = out + (size_t)NNODES * OSZ;
    float* prod = out + (size_t)2 * NNODES * OSZ;

    // 0) clear histograms, build CSR offsets (edge-only work, before GEMMs)
    cudaMemsetAsync(p_cur, 0, 4 * NNODES * sizeof(int), 0);
    count_kernel<<<dim3((NEDGE + 255) / 256, 4), 256>>>(ed4);
    scan_kernel<<<4, 1024>>>();

    // 1) wh = x @ w_h   (batched x2)
    {
        GB gb = {};
        gb.A[0] = hx;     gb.B[0] = w_h[0]; gb.C[0] = p_wh0;
        gb.A[1] = tx;     gb.B[1] = w_h[1]; gb.C[1] = p_wh1;
        dim3 g(FDIM / 128, (NNODES + 127) / 128, 2);
        mma_gemm_b<4, false><<<g, 256>>>(gb, NNODES, FDIM, FDIM);
    }
    // 2) feat = wh @ fc  (batched x4)
    {
        GB gb = {};
        const float* whp[2] = {p_wh0, p_wh1};
        for (int z = 0; z < 4; z++) {
            gb.A[z] = whp[z >> 1];
            gb.B[z] = fc[z >> 1] + (size_t)(z & 1) * FDIM * DDIM;
            gb.C[z] = p_feat[z];
        }
        dim3 g(DDIM / 128, (NNODES + 127) / 128, 4);
        mma_gemm_b<4, false><<<g, 256>>>(gb, NNODES, DDIM, FDIM);
    }
    // 3) logits + fused exp/sum/scatter + aggregate (all x4)
    eler_kernel<<<dim3(NNODES, 4), 256>>>(al4, ar4);
    exp_scatter_kernel<<<dim3((NEDGE + 255) / 256, 4), 256>>>(ed4);
    agg_kernel<<<dim3((NNODES * 4 + 7) / 8, 4), 256>>>(bias4);

    // 4) semantic attention (batched x4) + fuse (x2)
    {
        GB gb = {};
        for (int z = 0; z < 4; z++) {
            gb.A[z] = p_z[z];
            gb.B[z] = W1[z >> 1];
            gb.C[z] = p_sc[z];
        }
        dim3 g(1, (NNODES + 63) / 64, 4);
        mma_gemm_b<2, false><<<g, 256>>>(gb, NNODES, SEMH, DDIM);
    }
    sem_score_kernel<<<dim3((NNODES + 7) / 8, 4), 256>>>(b14, W24);
    fuse_kernel<<<dim3((NNODES * DDIM + 255) / 256, 2), 256>>>();

    // 5) prediction heads (batched x2)
    {
        GB gb = {};
        gb.A[0] = p_fu[0]; gb.B[0] = pred[0]; gb.C[0] = h1;
        gb.A[1] = p_fu[1]; gb.B[1] = pred[1]; gb.C[1] = h2;
        dim3 g(1, (NNODES + 63) / 64, 2);
        mma_gemm_b<2, false><<<g, 256>>>(gb, NNODES, OSZ, DDIM);
    }
    // 6) prod = h1 @ h2^T
    {
        GB gb = {};
        gb.A[0] = h1; gb.B[0] = h2; gb.C[0] = prod;
        dim3 g((NNODES + 127) / 128, (NNODES + 127) / 128, 1);
        mma_gemm_b<4, true><<<g, 256>>>(gb, NNODES, NNODES, OSZ);
    }
}

// round 9
// speedup vs baseline: 3.0613x; 1.1321x over previous
#include <cuda_runtime.h>
#include <cstdint>

#define NNODES 10000
#define FDIM   256
#define DDIM   512
#define NEDGE  160000
#define NHEAD  8
#define SEMH   128
#define OSZ    64

// ---------------- scratch (static device globals; no allocation) ----------------
// instance index z in [0,4): branch = z>>1 (0=herb,1=target), metapath = z&1
__device__ float g_wh  [2][NNODES * FDIM];
__device__ float g_feat[4][NNODES * DDIM];
__device__ float g_z   [4][NNODES * DDIM];
__device__ float g_el  [4][NNODES * NHEAD];
__device__ float g_er  [4][NNODES * NHEAD];
__device__ float g_sm  [4][NNODES * NHEAD];
__device__ float g_ex  [4][NEDGE * NHEAD];
__device__ float g_sc  [4][NNODES * SEMH];
__device__ float g_w   [4][NNODES];
__device__ float g_fu  [2][NNODES * DDIM];
__device__ int   g_off [4][NNODES + 1];
__device__ int   g_cur [4][NNODES];
__device__ int2  g_eid2[4][NEDGE];

struct GB   { const float* A[4]; const float* B[4]; float* C[4]; };
struct IP4  { const int*   p[4]; };
struct FP4  { const float* p[4]; };

// ---------------- tf32 MMA GEMM, double-buffered, z-batched ----------------
// Block tile BM(=32*MT) x 128, K-tile 16. 256 threads = 8 warps in 2(m) x 4(n).
// RAW smem tiles with conflict-breaking pitches:
//   A: row-major [BM][16] at pitch 20 words  -> frag reads (8 rows x 4 cols per
//      instr) hit banks 20*(l>>2)+(l&3) mod 32 = all 32 distinct. LDS.32, 0-conflict.
//   B (NN): [16][128] pitch 136 -> banks 8*(l&3)+(l>>2): distinct.
//   B (NT): [128][16] pitch 20 (same as A pattern).
// Staging: fully coalesced float4 LDG + contiguous STS.128 (A 2-way worst case).

__device__ __forceinline__ unsigned f2tf(float f) {
    unsigned r;
    asm("cvt.rna.tf32.f32 %0, %1;" : "=r"(r) : "f"(f));
    return r;
}

template<int MT, bool TRANSB>
__global__ __launch_bounds__(256, 2) void mma_gemm_b(GB gb, int M, int N, int K) {
    constexpr int BM = 32 * MT;
    constexpr int AQ = BM / 64;                 // A float4 loads per thread
    constexpr int PA = 20;
    constexpr int PB = TRANSB ? 20 : 136;
    constexpr int BWORDS = TRANSB ? 128 * PB : 16 * PB;
    __shared__ unsigned sA[2][BM * PA];
    __shared__ unsigned sB[2][BWORDS];

    const float* __restrict__ A = gb.A[blockIdx.z];
    const float* __restrict__ B = gb.B[blockIdx.z];
    float* __restrict__ C = gb.C[blockIdx.z];

    int tid = threadIdx.x;
    int warp = tid >> 5, lane = tid & 31;
    int wm = warp >> 2, wn = warp & 3;
    int row0 = blockIdx.y * BM, col0 = blockIdx.x * 128;

    float4 ra[AQ], rb[2];

    auto loadA = [&](int k0) {
#pragma unroll
        for (int j = 0; j < AQ; j++) {
            int i = tid + j * 256;
            int r = i >> 2, c4 = i & 3;
            float4 v = make_float4(0.f, 0.f, 0.f, 0.f);
            if (row0 + r < M)
                v = *(const float4*)(A + (size_t)(row0 + r) * K + k0 + c4 * 4);
            ra[j] = v;
        }
    };
    auto storeA = [&](int buf) {
#pragma unroll
        for (int j = 0; j < AQ; j++) {
            int i = tid + j * 256;
            int r = i >> 2, c4 = i & 3;
            uint4 u = make_uint4(f2tf(ra[j].x), f2tf(ra[j].y),
                                 f2tf(ra[j].z), f2tf(ra[j].w));
            *(uint4*)&sA[buf][r * PA + c4 * 4] = u;
        }
    };
    auto loadB = [&](int k0) {
#pragma unroll
        for (int j = 0; j < 2; j++) {
            int i = tid + j * 256;
            float4 v = make_float4(0.f, 0.f, 0.f, 0.f);
            if (!TRANSB) {
                int k = i >> 5, c4 = i & 31;
                int gc = col0 + c4 * 4;
                if (gc < N) v = *(const float4*)(B + (size_t)(k0 + k) * N + gc);
            } else {
                int n = i >> 2, c4 = i & 3;
                int gn = col0 + n;
                if (gn < N) v = *(const float4*)(B + (size_t)gn * K + k0 + c4 * 4);
            }
            rb[j] = v;
        }
    };
    auto storeB = [&](int buf) {
#pragma unroll
        for (int j = 0; j < 2; j++) {
            int i = tid + j * 256;
            uint4 u = make_uint4(f2tf(rb[j].x), f2tf(rb[j].y),
                                 f2tf(rb[j].z), f2tf(rb[j].w));
            if (!TRANSB) {
                int k = i >> 5, c4 = i & 31;
                *(uint4*)&sB[buf][k * PB + c4 * 4] = u;
            } else {
                int n = i >> 2, c4 = i & 3;
                *(uint4*)&sB[buf][n * PB + c4 * 4] = u;
            }
        }
    };

    float acc[MT][4][4];
#pragma unroll
    for (int i = 0; i < MT; i++)
#pragma unroll
        for (int j = 0; j < 4; j++)
#pragma unroll
            for (int q = 0; q < 4; q++) acc[i][j][q] = 0.f;

    // per-thread base word offsets for fragment reads
    const int aBase = (wm * MT * 16 + (lane >> 2)) * PA + (lane & 3);
    const int bBase = TRANSB ? (wn * 32 + (lane >> 2)) * PB + (lane & 3)
                             : (lane & 3) * PB + wn * 32 + (lane >> 2);

    int nk = K >> 4;
    loadA(0); loadB(0);
    storeA(0); storeB(0);
    __syncthreads();

    for (int t = 0; t < nk; t++) {
        int buf = t & 1;
        if (t + 1 < nk) { loadA((t + 1) * 16); loadB((t + 1) * 16); }

        const unsigned* __restrict__ ap = &sA[buf][aBase];
        const unsigned* __restrict__ bp = &sB[buf][bBase];
#pragma unroll
        for (int ks = 0; ks < 2; ks++) {
            unsigned af[MT][4];
            unsigned bf[4][2];
#pragma unroll
            for (int mt = 0; mt < MT; mt++) {
                const unsigned* p = ap + mt * (16 * PA) + ks * 8;
                af[mt][0] = p[0];
                af[mt][1] = p[8 * PA];
                af[mt][2] = p[4];
                af[mt][3] = p[8 * PA + 4];
            }
#pragma unroll
            for (int nt = 0; nt < 4; nt++) {
                if (!TRANSB) {
                    const unsigned* p = bp + ks * 8 * PB + nt * 8;
                    bf[nt][0] = p[0];
                    bf[nt][1] = p[4 * PB];
                } else {
                    const unsigned* p = bp + nt * 8 * PB + ks * 8;
                    bf[nt][0] = p[0];
                    bf[nt][1] = p[4];
                }
            }
#pragma unroll
            for (int mt = 0; mt < MT; mt++)
#pragma unroll
                for (int nt = 0; nt < 4; nt++) {
                    asm volatile(
                        "mma.sync.aligned.m16n8k8.row.col.f32.tf32.tf32.f32 "
                        "{%0,%1,%2,%3}, {%4,%5,%6,%7}, {%8,%9}, {%0,%1,%2,%3};"
                        : "+f"(acc[mt][nt][0]), "+f"(acc[mt][nt][1]),
                          "+f"(acc[mt][nt][2]), "+f"(acc[mt][nt][3])
                        : "r"(af[mt][0]), "r"(af[mt][1]), "r"(af[mt][2]), "r"(af[mt][3]),
                          "r"(bf[nt][0]), "r"(bf[nt][1]));
                }
        }
        if (t + 1 < nk) { storeA(buf ^ 1); storeB(buf ^ 1); }
        __syncthreads();
    }

#pragma unroll
    for (int mt = 0; mt < MT; mt++) {
        int r_base = row0 + wm * (MT * 16) + mt * 16 + (lane >> 2);
#pragma unroll
        for (int nt = 0; nt < 4; nt++) {
            int c = col0 + wn * 32 + nt * 8 + (lane & 3) * 2;
            if (c < N) {
                if (r_base < M)
                    *(float2*)(C + (size_t)r_base * N + c) =
                        make_float2(acc[mt][nt][0], acc[mt][nt][1]);
                if (r_base + 8 < M)
                    *(float2*)(C + (size_t)(r_base + 8) * N + c) =
                        make_float2(acc[mt][nt][2], acc[mt][nt][3]);
            }
        }
    }
}

// ---------------- GAT kernels (grid.y = instance z) ----------------

__global__ void eler_kernel(FP4 al4, FP4 ar4) {
    int z = blockIdx.y;
    int w = blockIdx.x * 8 + (threadIdx.x >> 5);
    int lane = threadIdx.x & 31;
    if (w >= NNODES * NHEAD) return;
    int n = w >> 3, h = w & 7;
    const float* al = al4.p[z];
    const float* ar = ar4.p[z];
    const float* f = g_feat[z] + (size_t)n * DDIM + h * 64;
    float sl = f[lane] * al[h * 64 + lane] + f[lane + 32] * al[h * 64 + lane + 32];
    float sr = f[lane] * ar[h * 64 + lane] + f[lane + 32] * ar[h * 64 + lane + 32];
#pragma unroll
    for (int o = 16; o > 0; o >>= 1) {
        sl += __shfl_down_sync(0xffffffffu, sl, o);
        sr += __shfl_down_sync(0xffffffffu, sr, o);
    }
    if (lane == 0) {
        g_el[z][w] = sl;
        g_er[z][w] = sr;
        g_sm[z][w] = 0.f;
    }
}

// degree histogram only (per edge)
__global__ void count_kernel(IP4 ed4) {
    int z = blockIdx.y;
    int i = blockIdx.x * blockDim.x + threadIdx.x;
    if (i >= NEDGE) return;
    atomicAdd(&g_cur[z][ed4.p[z][NEDGE + i]], 1);
}

// per-instance single-block exclusive scan (grid.x = instance)
__global__ void scan_kernel() {
    int z = blockIdx.x;
    int* cur = g_cur[z];
    int* off = g_off[z];
    __shared__ int part[1024];
    int t = threadIdx.x;
    int base = t * 10;
    int v[10];
    int s = 0;
#pragma unroll
    for (int j = 0; j < 10; j++) {
        int idx = base + j;
        int c = (idx < NNODES) ? cur[idx] : 0;
        v[j] = c;
        s += c;
    }
    part[t] = s;
    __syncthreads();
    for (int o = 1; o < 1024; o <<= 1) {
        int x = (t >= o) ? part[t - o] : 0;
        __syncthreads();
        part[t] += x;
        __syncthreads();
    }
    int run = (t > 0) ? part[t - 1] : 0;
#pragma unroll
    for (int j = 0; j < 10; j++) {
        int idx = base + j;
        if (idx < NNODES) {
            off[idx] = run;
            cur[idx] = run;
            run += v[j];
        }
    }
    if (t == 0) off[NNODES] = NEDGE;
}

// fused: leaky_relu + exp (softmax is shift-invariant; logits are small so no
// max subtraction needed) + per-dst sum + CSR scatter of (edge, src) pairs.
__global__ void exp_scatter_kernel(IP4 ed4) {
    int z = blockIdx.y;
    int e = blockIdx.x * blockDim.x + threadIdx.x;
    if (e >= NEDGE) return;
    const int* ed = ed4.p[z];
    int s = ed[e], d = ed[NEDGE + e];
    float4 l0 = *(const float4*)&g_el[z][s * NHEAD];
    float4 l1 = *(const float4*)&g_el[z][s * NHEAD + 4];
    float4 r0 = *(const float4*)&g_er[z][d * NHEAD];
    float4 r1 = *(const float4*)&g_er[z][d * NHEAD + 4];
    float v[8] = {l0.x + r0.x, l0.y + r0.y, l0.z + r0.z, l0.w + r0.w,
                  l1.x + r1.x, l1.y + r1.y, l1.z + r1.z, l1.w + r1.w};
    float ex[8];
#pragma unroll
    for (int h = 0; h < 8; h++) {
        float t = v[h] > 0.f ? v[h] : 0.2f * v[h];
        ex[h] = __expf(t);
    }
    *(float4*)&g_ex[z][(size_t)e * NHEAD]     = make_float4(ex[0], ex[1], ex[2], ex[3]);
    *(float4*)&g_ex[z][(size_t)e * NHEAD + 4] = make_float4(ex[4], ex[5], ex[6], ex[7]);
#pragma unroll
    for (int h = 0; h < 8; h++) atomicAdd(&g_sm[z][d * NHEAD + h], ex[h]);
    int p = atomicAdd(&g_cur[z][d], 1);
    g_eid2[z][p] = make_int2(e, s);
}

// gather-aggregate: one warp per (dst node, 128-col strip); bias+ELU fused.
// distance-2 prefetch on the (edge,src) stream so eid2/ex/feat overlap.
__global__ __launch_bounds__(256) void agg_kernel(FP4 bias4) {
    int z = blockIdx.y;
    int wid = blockIdx.x * 8 + (threadIdx.x >> 5);
    if (wid >= NNODES * 4) return;
    const float* bias = bias4.p[z];
    const float* __restrict__ feat = g_feat[z];
    const float* __restrict__ ex = g_ex[z];
    const int2* __restrict__ eid2 = g_eid2[z];
    int d = wid >> 2, strip = wid & 3;
    int lane = threadIdx.x & 31;
    int col = strip * 128 + lane * 4;
    int head = col >> 6;
    float rcp = 1.f / g_sm[z][d * NHEAD + head];

    float4 acc = make_float4(0.f, 0.f, 0.f, 0.f);
    int b = g_off[z][d], e_ = g_off[z][d + 1];
    if (b < e_) {
        int2 peA = eid2[b];
        int2 peB = (b + 1 < e_) ? eid2[b + 1] : peA;
        float axA = ex[(size_t)peA.x * NHEAD + head];
        for (int i = b; i < e_; i++) {
            int2 peC = (i + 2 < e_) ? eid2[i + 2] : peB;
            float axB = (i + 1 < e_) ? ex[(size_t)peB.x * NHEAD + head] : 0.f;
            float4 f = *(const float4*)(feat + (size_t)peA.y * DDIM + col);
            float a = axA * rcp;
            acc.x += f.x * a;
            acc.y += f.y * a;
            acc.z += f.z * a;
            acc.w += f.w * a;
            peA = peB; peB = peC; axA = axB;
        }
    }
    float4 bb = *(const float4*)(bias + col);
    float4 v;
    v.x = acc.x + bb.x; v.x = v.x > 0.f ? v.x : (__expf(v.x) - 1.f);
    v.y = acc.y + bb.y; v.y = v.y > 0.f ? v.y : (__expf(v.y) - 1.f);
    v.z = acc.z + bb.z; v.z = v.z > 0.f ? v.z : (__expf(v.z) - 1.f);
    v.w = acc.w + bb.w; v.w = v.w > 0.f ? v.w : (__expf(v.w) - 1.f);
    *(float4*)(g_z[z] + (size_t)d * DDIM + col) = v;
}

// ---------------- semantic attention ----------------

__global__ void sem_score_kernel(FP4 b14, FP4 W24) {
    int z = blockIdx.y;
    int w = blockIdx.x * 8 + (threadIdx.x >> 5);
    int lane = threadIdx.x & 31;
    if (w >= NNODES) return;
    const float* b1 = b14.p[z];
    const float* W2 = W24.p[z];
    float t = 0.f;
#pragma unroll
    for (int q = 0; q < 4; q++) {
        int j = lane + 32 * q;
        t += tanhf(g_sc[z][(size_t)w * SEMH + j] + b1[j]) * W2[j];
    }
#pragma unroll
    for (int o = 16; o > 0; o >>= 1) t += __shfl_down_sync(0xffffffffu, t, o);
    if (lane == 0) g_w[z][w] = t;
}

__global__ void fuse_kernel() {
    int b = blockIdx.y;
    int i = blockIdx.x * blockDim.x + threadIdx.x;
    if (i >= NNODES * DDIM) return;
    int n = i >> 9;
    float a = g_w[2 * b][n], c = g_w[2 * b + 1][n];
    float m = fmaxf(a, c);
    float ea = __expf(a - m), eb = __expf(c - m);
    float be = ea / (ea + eb);
    g_fu[b][i] = be * g_z[2 * b][i] + (1.f - be) * g_z[2 * b + 1][i];
}

// ---------------- host orchestration ----------------

extern "C" void kernel_launch(void* const* d_in, const int* in_sizes, int n_in,
                              void* d_out, int out_size) {
    float *p_wh0, *p_wh1, *p_feat[4], *p_z[4], *p_sc[4], *p_fu[2];
    {
        float* base;
        cudaGetSymbolAddress((void**)&base, g_wh);
        p_wh0 = base; p_wh1 = base + (size_t)NNODES * FDIM;
        cudaGetSymbolAddress((void**)&base, g_feat);
        for (int z = 0; z < 4; z++) p_feat[z] = base + (size_t)z * NNODES * DDIM;
        cudaGetSymbolAddress((void**)&base, g_z);
        for (int z = 0; z < 4; z++) p_z[z] = base + (size_t)z * NNODES * DDIM;
        cudaGetSymbolAddress((void**)&base, g_sc);
        for (int z = 0; z < 4; z++) p_sc[z] = base + (size_t)z * NNODES * SEMH;
        cudaGetSymbolAddress((void**)&base, g_fu);
        for (int b = 0; b < 2; b++) p_fu[b] = base + (size_t)b * NNODES * DDIM;
    }
    int* p_cur;
    cudaGetSymbolAddress((void**)&p_cur, g_cur);

    const float* hx = (const float*)d_in[0];
    const float* tx = (const float*)d_in[1];
    const float* w_h[2]  = {(const float*)d_in[2],  (const float*)d_in[11]};
    const float* fc[2]   = {(const float*)d_in[3],  (const float*)d_in[12]};
    const float* al[2]   = {(const float*)d_in[4],  (const float*)d_in[13]};
    const float* ar[2]   = {(const float*)d_in[5],  (const float*)d_in[14]};
    const float* bias[2] = {(const float*)d_in[6],  (const float*)d_in[15]};
    const float* W1[2]   = {(const float*)d_in[7],  (const float*)d_in[16]};
    const float* b1[2]   = {(const float*)d_in[8],  (const float*)d_in[17]};
    const float* W2[2]   = {(const float*)d_in[9],  (const float*)d_in[18]};
    const float* pred[2] = {(const float*)d_in[10], (const float*)d_in[19]};

    IP4 ed4 = {{(const int*)d_in[20], (const int*)d_in[21],
                (const int*)d_in[22], (const int*)d_in[23]}};
    FP4 al4   = {{al[0], al[0] + NHEAD * 64, al[1], al[1] + NHEAD * 64}};
    FP4 ar4   = {{ar[0], ar[0] + NHEAD * 64, ar[1], ar[1] + NHEAD * 64}};
    FP4 bias4 = {{bias[0], bias[0] + DDIM, bias[1], bias[1] + DDIM}};
    FP4 b14   = {{b1[0], b1[0], b1[1], b1[1]}};
    FP4 W24   = {{W2[0], W2[0], W2[1], W2[1]}};

    float* out  = (float*)d_out;
    float* h1   = out;
    float* h2   = out + (size_t)NNODES * OSZ;
    float* prod = out + (size_t)2 * NNODES * OSZ;

    // 0) clear histograms, build CSR offsets (edge-only work, before GEMMs)
    cudaMemsetAsync(p_cur, 0, 4 * NNODES * sizeof(int), 0);
    count_kernel<<<dim3((NEDGE + 255) / 256, 4), 256>>>(ed4);
    scan_kernel<<<4, 1024>>>();

    // 1) wh = x @ w_h   (batched x2)
    {
        GB gb = {};
        gb.A[0] = hx;     gb.B[0] = w_h[0]; gb.C[0] = p_wh0;
        gb.A[1] = tx;     gb.B[1] = w_h[1]; gb.C[1] = p_wh1;
        dim3 g(FDIM / 128, (NNODES + 127) / 128, 2);
        mma_gemm_b<4, false><<<g, 256>>>(gb, NNODES, FDIM, FDIM);
    }
    // 2) feat = wh @ fc  (batched x4)
    {
        GB gb = {};
        const float* whp[2] = {p_wh0, p_wh1};
        for (int z = 0; z < 4; z++) {
            gb.A[z] = whp[z >> 1];
            gb.B[z] = fc[z >> 1] + (size_t)(z & 1) * FDIM * DDIM;
            gb.C[z] = p_feat[z];
        }
        dim3 g(DDIM / 128, (NNODES + 127) / 128, 4);
        mma_gemm_b<4, false><<<g, 256>>>(gb, NNODES, DDIM, FDIM);
    }
    // 3) logits + fused exp/sum/scatter + aggregate (all x4)
    eler_kernel<<<dim3(NNODES, 4), 256>>>(al4, ar4);
    exp_scatter_kernel<<<dim3((NEDGE + 255) / 256, 4), 256>>>(ed4);
    agg_kernel<<<dim3((NNODES * 4 + 7) / 8, 4), 256>>>(bias4);

    // 4) semantic attention (batched x4) + fuse (x2)
    {
        GB gb = {};
        for (int z = 0; z < 4; z++) {
            gb.A[z] = p_z[z];
            gb.B[z] = W1[z >> 1];
            gb.C[z] = p_sc[z];
        }
        dim3 g(1, (NNODES + 63) / 64, 4);
        mma_gemm_b<2, false><<<g, 256>>>(gb, NNODES, SEMH, DDIM);
    }
    sem_score_kernel<<<dim3((NNODES + 7) / 8, 4), 256>>>(b14, W24);
    fuse_kernel<<<dim3((NNODES * DDIM + 255) / 256, 2), 256>>>();

    // 5) prediction heads (batched x2)
    {
        GB gb = {};
        gb.A[0] = p_fu[0]; gb.B[0] = pred[0]; gb.C[0] = h1;
        gb.A[1] = p_fu[1]; gb.B[1] = pred[1]; gb.C[1] = h2;
        dim3 g(1, (NNODES + 63) / 64, 2);
        mma_gemm_b<2, false><<<g, 256>>>(gb, NNODES, OSZ, DDIM);
    }
    // 6) prod = h1 @ h2^T
    {
        GB gb = {};
        gb.A[0] = h1; gb.B[0] = h2; gb.C[0] = prod;
        dim3 g((NNODES + 127) / 128, (NNODES + 127) / 128, 1);
        mma_gemm_b<4, true><<<g, 256>>>(gb, NNODES, NNODES, OSZ);
    }
}

// round 10
// speedup vs baseline: 3.2772x; 1.0705x over previous
#include <cuda_runtime.h>
#include <cstdint>

#define NNODES 10000
#define FDIM   256
#define DDIM   512
#define NEDGE  160000
#define NHEAD  8
#define SEMH   128
#define OSZ    64

// ---------------- scratch (static device globals; no allocation) ----------------
// instance index z in [0,4): branch = z>>1 (0=herb,1=target), metapath = z&1
__device__ float g_feat[4][NNODES * DDIM];
__device__ float g_z   [4][NNODES * DDIM];
__device__ float g_el  [4][NNODES * NHEAD];
__device__ float g_er  [4][NNODES * NHEAD];
__device__ float g_sm  [4][NNODES * NHEAD];
__device__ float g_ex  [4][NEDGE * NHEAD];
__device__ float g_sc  [4][NNODES * SEMH];
__device__ float g_w   [4][NNODES];
__device__ int   g_off [4][NNODES + 1];
__device__ int   g_cur [4][NNODES];
__device__ int2  g_eid2[4][NEDGE];
// tf32-at-rest operands (bits stored as unsigned)
__device__ unsigned t_x   [2][NNODES * FDIM];
__device__ unsigned t_whw [2][FDIM * FDIM];
__device__ unsigned t_fc  [2][2 * FDIM * DDIM];
__device__ unsigned t_pred[2][DDIM * OSZ];
__device__ unsigned t_who [2][NNODES * FDIM];
__device__ unsigned t_fu  [2][NNODES * DDIM];
__device__ unsigned t_h   [2][NNODES * OSZ];

struct GB   { const void* A[4]; const void* B[4]; void* C[4]; void* C2[4]; };
struct IP4  { const int*   p[4]; };
struct FP4  { const float* p[4]; };
struct CVT  { const float* src[8]; unsigned* dst[8]; int n4[8]; };

__device__ __forceinline__ unsigned f2tf(float f) {
    unsigned r;
    asm("cvt.rna.tf32.f32 %0, %1;" : "=r"(r) : "f"(f));
    return r;
}

// ---------------- one-shot f32 -> tf32 conversion (weights + inputs) ----------
__global__ void cvt_kernel(CVT c) {
    int seg = blockIdx.y;
    int n4 = c.n4[seg];
    const float4* s = (const float4*)c.src[seg];
    uint4* d = (uint4*)c.dst[seg];
    for (int i = blockIdx.x * 256 + threadIdx.x; i < n4; i += gridDim.x * 256) {
        float4 v = s[i];
        d[i] = make_uint4(f2tf(v.x), f2tf(v.y), f2tf(v.z), f2tf(v.w));
    }
}

// ---------------- async tf32 MMA GEMM: cp.async 4-stage, z-batched -----------
// Block tile BM(=32*MT) x 128, K-tile 16. 256 threads = 8 warps 2(m) x 4(n).
// Operands already tf32 bits -> staging is pure cp.async.cg 16B copies into
// pitched raw tiles (pitch 20 / 136 words: conflict-free LDS.32 frag reads).
// EPI: 0 = f32 C, 1 = tf32 C, 2 = f32 C + tf32 C2.

template<int MT, bool TRANSB, int EPI>
__global__ __launch_bounds__(256, 2) void mma_gemm_async(GB gb, int M, int N, int K) {
    constexpr int S  = 4;
    constexpr int BM = 32 * MT;
    constexpr int PA = 20;
    constexpr int PB = TRANSB ? 20 : 136;
    constexpr int AW = BM * PA;
    constexpr int BW = TRANSB ? 128 * PB : 16 * PB;
    constexpr int AQ = BM / 64;
    extern __shared__ unsigned smem[];
    unsigned* sA = smem;            // S * AW
    unsigned* sB = smem + S * AW;   // S * BW

    const unsigned* __restrict__ A = (const unsigned*)gb.A[blockIdx.z];
    const unsigned* __restrict__ B = (const unsigned*)gb.B[blockIdx.z];
    float* C = (float*)gb.C[blockIdx.z];
    unsigned* C2 = (unsigned*)gb.C2[blockIdx.z];

    int tid = threadIdx.x, warp = tid >> 5, lane = tid & 31;
    int wm = warp >> 2, wn = warp & 3;
    int row0 = blockIdx.y * BM, col0 = blockIdx.x * 128;
    int nk = K >> 4;

    auto issue = [&](int t) {
        int k0 = t * 16, buf = t & (S - 1);
#pragma unroll
        for (int j = 0; j < AQ; j++) {
            int i = tid + j * 256;
            int r = i >> 2, c4 = i & 3;
            int gr = row0 + r;
            int sz = 16;
            if (gr >= M) { sz = 0; gr = row0; }
            unsigned sd = (unsigned)__cvta_generic_to_shared(sA + buf * AW + r * PA + c4 * 4);
            asm volatile("cp.async.cg.shared.global [%0], [%1], 16, %2;"
                         :: "r"(sd), "l"(A + (size_t)gr * K + k0 + c4 * 4), "r"(sz));
        }
#pragma unroll
        for (int j = 0; j < 2; j++) {
            int i = tid + j * 256;
            const unsigned* src;
            int dstw, sz = 16;
            if (!TRANSB) {
                int k = i >> 5, c4 = i & 31;
                int gc = col0 + c4 * 4;
                if (gc >= N) { sz = 0; gc = col0; }
                src = B + (size_t)(k0 + k) * N + gc;
                dstw = k * PB + c4 * 4;
            } else {
                int n = i >> 2, c4 = i & 3;
                int gn = col0 + n;
                if (gn >= N) { sz = 0; gn = col0; }
                src = B + (size_t)gn * K + k0 + c4 * 4;
                dstw = n * PB + c4 * 4;
            }
            unsigned sd = (unsigned)__cvta_generic_to_shared(sB + buf * BW + dstw);
            asm volatile("cp.async.cg.shared.global [%0], [%1], 16, %2;"
                         :: "r"(sd), "l"(src), "r"(sz));
        }
    };

    float acc[MT][4][4];
#pragma unroll
    for (int i = 0; i < MT; i++)
#pragma unroll
        for (int j = 0; j < 4; j++)
#pragma unroll
            for (int q = 0; q < 4; q++) acc[i][j][q] = 0.f;

#pragma unroll
    for (int t = 0; t < S - 1; t++) {
        if (t < nk) issue(t);
        asm volatile("cp.async.commit_group;");
    }

    const int aB0 = (wm * MT * 16 + (lane >> 2)) * PA + (lane & 3);
    const int bB0 = TRANSB ? (wn * 32 + (lane >> 2)) * PB + (lane & 3)
                           : (lane & 3) * PB + wn * 32 + (lane >> 2);

    for (int t = 0; t < nk; t++) {
        int buf = t & (S - 1);
        asm volatile("cp.async.wait_group %0;" :: "n"(S - 2));
        __syncthreads();
        if (t + S - 1 < nk) issue(t + S - 1);
        asm volatile("cp.async.commit_group;");

        const unsigned* __restrict__ ap = sA + buf * AW + aB0;
        const unsigned* __restrict__ bp = sB + buf * BW + bB0;
#pragma unroll
        for (int ks = 0; ks < 2; ks++) {
            unsigned af[MT][4];
            unsigned bf[4][2];
#pragma unroll
            for (int mt = 0; mt < MT; mt++) {
                const unsigned* p = ap + mt * (16 * PA) + ks * 8;
                af[mt][0] = p[0];
                af[mt][1] = p[8 * PA];
                af[mt][2] = p[4];
                af[mt][3] = p[8 * PA + 4];
            }
#pragma unroll
            for (int nt = 0; nt < 4; nt++) {
                if (!TRANSB) {
                    const unsigned* p = bp + ks * 8 * PB + nt * 8;
                    bf[nt][0] = p[0];
                    bf[nt][1] = p[4 * PB];
                } else {
                    const unsigned* p = bp + nt * 8 * PB + ks * 8;
                    bf[nt][0] = p[0];
                    bf[nt][1] = p[4];
                }
            }
#pragma unroll
            for (int mt = 0; mt < MT; mt++)
#pragma unroll
                for (int nt = 0; nt < 4; nt++) {
                    asm volatile(
                        "mma.sync.aligned.m16n8k8.row.col.f32.tf32.tf32.f32 "
                        "{%0,%1,%2,%3}, {%4,%5,%6,%7}, {%8,%9}, {%0,%1,%2,%3};"
                        : "+f"(acc[mt][nt][0]), "+f"(acc[mt][nt][1]),
                          "+f"(acc[mt][nt][2]), "+f"(acc[mt][nt][3])
                        : "r"(af[mt][0]), "r"(af[mt][1]), "r"(af[mt][2]), "r"(af[mt][3]),
                          "r"(bf[nt][0]), "r"(bf[nt][1]));
                }
        }
    }

#pragma unroll
    for (int mt = 0; mt < MT; mt++) {
        int r0 = row0 + wm * (MT * 16) + mt * 16 + (lane >> 2);
#pragma unroll
        for (int nt = 0; nt < 4; nt++) {
            int c = col0 + wn * 32 + nt * 8 + (lane & 3) * 2;
            if (c < N) {
#pragma unroll
                for (int h = 0; h < 2; h++) {
                    int r = r0 + h * 8;
                    if (r < M) {
                        float v0 = acc[mt][nt][2 * h], v1 = acc[mt][nt][2 * h + 1];
                        if (EPI != 1)
                            *(float2*)(C + (size_t)r * N + c) = make_float2(v0, v1);
                        if (EPI == 1)
                            *(uint2*)((unsigned*)C + (size_t)r * N + c) =
                                make_uint2(f2tf(v0), f2tf(v1));
                        if (EPI == 2)
                            *(uint2*)(C2 + (size_t)r * N + c) =
                                make_uint2(f2tf(v0), f2tf(v1));
                    }
                }
            }
        }
    }
}

// ---------------- cvt-staging tf32 GEMM (R9 path) — used for sem only --------
template<int MT, bool TRANSB>
__global__ __launch_bounds__(256, 2) void mma_gemm_cvt(GB gb, int M, int N, int K) {
    constexpr int BM = 32 * MT;
    constexpr int AQ = BM / 64;
    constexpr int PA = 20;
    constexpr int PB = TRANSB ? 20 : 136;
    constexpr int BWORDS = TRANSB ? 128 * PB : 16 * PB;
    __shared__ unsigned sA[2][BM * PA];
    __shared__ unsigned sB[2][BWORDS];

    const float* __restrict__ A = (const float*)gb.A[blockIdx.z];
    const float* __restrict__ B = (const float*)gb.B[blockIdx.z];
    float* __restrict__ C = (float*)gb.C[blockIdx.z];

    int tid = threadIdx.x;
    int warp = tid >> 5, lane = tid & 31;
    int wm = warp >> 2, wn = warp & 3;
    int row0 = blockIdx.y * BM, col0 = blockIdx.x * 128;

    float4 ra[AQ], rb[2];

    auto loadA = [&](int k0) {
#pragma unroll
        for (int j = 0; j < AQ; j++) {
            int i = tid + j * 256;
            int r = i >> 2, c4 = i & 3;
            float4 v = make_float4(0.f, 0.f, 0.f, 0.f);
            if (row0 + r < M)
                v = *(const float4*)(A + (size_t)(row0 + r) * K + k0 + c4 * 4);
            ra[j] = v;
        }
    };
    auto storeA = [&](int buf) {
#pragma unroll
        for (int j = 0; j < AQ; j++) {
            int i = tid + j * 256;
            int r = i >> 2, c4 = i & 3;
            *(uint4*)&sA[buf][r * PA + c4 * 4] =
                make_uint4(f2tf(ra[j].x), f2tf(ra[j].y), f2tf(ra[j].z), f2tf(ra[j].w));
        }
    };
    auto loadB = [&](int k0) {
#pragma unroll
        for (int j = 0; j < 2; j++) {
            int i = tid + j * 256;
            float4 v = make_float4(0.f, 0.f, 0.f, 0.f);
            if (!TRANSB) {
                int k = i >> 5, c4 = i & 31;
                int gc = col0 + c4 * 4;
                if (gc < N) v = *(const float4*)(B + (size_t)(k0 + k) * N + gc);
            } else {
                int n = i >> 2, c4 = i & 3;
                int gn = col0 + n;
                if (gn < N) v = *(const float4*)(B + (size_t)gn * K + k0 + c4 * 4);
            }
            rb[j] = v;
        }
    };
    auto storeB = [&](int buf) {
#pragma unroll
        for (int j = 0; j < 2; j++) {
            int i = tid + j * 256;
            uint4 u = make_uint4(f2tf(rb[j].x), f2tf(rb[j].y),
                                 f2tf(rb[j].z), f2tf(rb[j].w));
            if (!TRANSB) {
                int k = i >> 5, c4 = i & 31;
                *(uint4*)&sB[buf][k * PB + c4 * 4] = u;
            } else {
                int n = i >> 2, c4 = i & 3;
                *(uint4*)&sB[buf][n * PB + c4 * 4] = u;
            }
        }
    };

    float acc[MT][4][4];
#pragma unroll
    for (int i = 0; i < MT; i++)
#pragma unroll
        for (int j = 0; j < 4; j++)
#pragma unroll
            for (int q = 0; q < 4; q++) acc[i][j][q] = 0.f;

    const int aBase = (wm * MT * 16 + (lane >> 2)) * PA + (lane & 3);
    const int bBase = TRANSB ? (wn * 32 + (lane >> 2)) * PB + (lane & 3)
                             : (lane & 3) * PB + wn * 32 + (lane >> 2);

    int nk = K >> 4;
    loadA(0); loadB(0);
    storeA(0); storeB(0);
    __syncthreads();

    for (int t = 0; t < nk; t++) {
        int buf = t & 1;
        if (t + 1 < nk) { loadA((t + 1) * 16); loadB((t + 1) * 16); }

        const unsigned* __restrict__ ap = &sA[buf][aBase];
        const unsigned* __restrict__ bp = &sB[buf][bBase];
#pragma unroll
        for (int ks = 0; ks < 2; ks++) {
            unsigned af[MT][4];
            unsigned bf[4][2];
#pragma unroll
            for (int mt = 0; mt < MT; mt++) {
                const unsigned* p = ap + mt * (16 * PA) + ks * 8;
                af[mt][0] = p[0];
                af[mt][1] = p[8 * PA];
                af[mt][2] = p[4];
                af[mt][3] = p[8 * PA + 4];
            }
#pragma unroll
            for (int nt = 0; nt < 4; nt++) {
                if (!TRANSB) {
                    const unsigned* p = bp + ks * 8 * PB + nt * 8;
                    bf[nt][0] = p[0];
                    bf[nt][1] = p[4 * PB];
                } else {
                    const unsigned* p = bp + nt * 8 * PB + ks * 8;
                    bf[nt][0] = p[0];
                    bf[nt][1] = p[4];
                }
            }
#pragma unroll
            for (int mt = 0; mt < MT; mt++)
#pragma unroll
                for (int nt = 0; nt < 4; nt++) {
                    asm volatile(
                        "mma.sync.aligned.m16n8k8.row.col.f32.tf32.tf32.f32 "
                        "{%0,%1,%2,%3}, {%4,%5,%6,%7}, {%8,%9}, {%0,%1,%2,%3};"
                        : "+f"(acc[mt][nt][0]), "+f"(acc[mt][nt][1]),
                          "+f"(acc[mt][nt][2]), "+f"(acc[mt][nt][3])
                        : "r"(af[mt][0]), "r"(af[mt][1]), "r"(af[mt][2]), "r"(af[mt][3]),
                          "r"(bf[nt][0]), "r"(bf[nt][1]));
                }
        }
        if (t + 1 < nk) { storeA(buf ^ 1); storeB(buf ^ 1); }
        __syncthreads();
    }

#pragma unroll
    for (int mt = 0; mt < MT; mt++) {
        int r_base = row0 + wm * (MT * 16) + mt * 16 + (lane >> 2);
#pragma unroll
        for (int nt = 0; nt < 4; nt++) {
            int c = col0 + wn * 32 + nt * 8 + (lane & 3) * 2;
            if (c < N) {
                if (r_base < M)
                    *(float2*)(C + (size_t)r_base * N + c) =
                        make_float2(acc[mt][nt][0], acc[mt][nt][1]);
                if (r_base + 8 < M)
                    *(float2*)(C + (size_t)(r_base + 8) * N + c) =
                        make_float2(acc[mt][nt][2], acc[mt][nt][3]);
            }
        }
    }
}

// ---------------- GAT kernels (grid.y = instance z) ----------------

__global__ void eler_kernel(FP4 al4, FP4 ar4) {
    int z = blockIdx.y;
    int w = blockIdx.x * 8 + (threadIdx.x >> 5);
    int lane = threadIdx.x & 31;
    if (w >= NNODES * NHEAD) return;
    int n = w >> 3, h = w & 7;
    const float* al = al4.p[z];
    const float* ar = ar4.p[z];
    const float* f = g_feat[z] + (size_t)n * DDIM + h * 64;
    float sl = f[lane] * al[h * 64 + lane] + f[lane + 32] * al[h * 64 + lane + 32];
    float sr = f[lane] * ar[h * 64 + lane] + f[lane + 32] * ar[h * 64 + lane + 32];
#pragma unroll
    for (int o = 16; o > 0; o >>= 1) {
        sl += __shfl_down_sync(0xffffffffu, sl, o);
        sr += __shfl_down_sync(0xffffffffu, sr, o);
    }
    if (lane == 0) {
        g_el[z][w] = sl;
        g_er[z][w] = sr;
        g_sm[z][w] = 0.f;
    }
}

__global__ void count_kernel(IP4 ed4) {
    int z = blockIdx.y;
    int i = blockIdx.x * blockDim.x + threadIdx.x;
    if (i >= NEDGE) return;
    atomicAdd(&g_cur[z][ed4.p[z][NEDGE + i]], 1);
}

__global__ void scan_kernel() {
    int z = blockIdx.x;
    int* cur = g_cur[z];
    int* off = g_off[z];
    __shared__ int part[1024];
    int t = threadIdx.x;
    int base = t * 10;
    int v[10];
    int s = 0;
#pragma unroll
    for (int j = 0; j < 10; j++) {
        int idx = base + j;
        int c = (idx < NNODES) ? cur[idx] : 0;
        v[j] = c;
        s += c;
    }
    part[t] = s;
    __syncthreads();
    for (int o = 1; o < 1024; o <<= 1) {
        int x = (t >= o) ? part[t - o] : 0;
        __syncthreads();
        part[t] += x;
        __syncthreads();
    }
    int run = (t > 0) ? part[t - 1] : 0;
#pragma unroll
    for (int j = 0; j < 10; j++) {
        int idx = base + j;
        if (idx < NNODES) {
            off[idx] = run;
            cur[idx] = run;
            run += v[j];
        }
    }
    if (t == 0) off[NNODES] = NEDGE;
}

__global__ void exp_scatter_kernel(IP4 ed4) {
    int z = blockIdx.y;
    int e = blockIdx.x * blockDim.x + threadIdx.x;
    if (e >= NEDGE) return;
    const int* ed = ed4.p[z];
    int s = ed[e], d = ed[NEDGE + e];
    float4 l0 = *(const float4*)&g_el[z][s * NHEAD];
    float4 l1 = *(const float4*)&g_el[z][s * NHEAD + 4];
    float4 r0 = *(const float4*)&g_er[z][d * NHEAD];
    float4 r1 = *(const float4*)&g_er[z][d * NHEAD + 4];
    float v[8] = {l0.x + r0.x, l0.y + r0.y, l0.z + r0.z, l0.w + r0.w,
                  l1.x + r1.x, l1.y + r1.y, l1.z + r1.z, l1.w + r1.w};
    float ex[8];
#pragma unroll
    for (int h = 0; h < 8; h++) {
        float t = v[h] > 0.f ? v[h] : 0.2f * v[h];
        ex[h] = __expf(t);
    }
    *(float4*)&g_ex[z][(size_t)e * NHEAD]     = make_float4(ex[0], ex[1], ex[2], ex[3]);
    *(float4*)&g_ex[z][(size_t)e * NHEAD + 4] = make_float4(ex[4], ex[5], ex[6], ex[7]);
#pragma unroll
    for (int h = 0; h < 8; h++) atomicAdd(&g_sm[z][d * NHEAD + h], ex[h]);
    int p = atomicAdd(&g_cur[z][d], 1);
    g_eid2[z][p] = make_int2(e, s);
}

__global__ __launch_bounds__(256) void agg_kernel(FP4 bias4) {
    int z = blockIdx.y;
    int wid = blockIdx.x * 8 + (threadIdx.x >> 5);
    if (wid >= NNODES * 4) return;
    const float* bias = bias4.p[z];
    const float* __restrict__ feat = g_feat[z];
    const float* __restrict__ ex = g_ex[z];
    const int2* __restrict__ eid2 = g_eid2[z];
    int d = wid >> 2, strip = wid & 3;
    int lane = threadIdx.x & 31;
    int col = strip * 128 + lane * 4;
    int head = col >> 6;
    float rcp = 1.f / g_sm[z][d * NHEAD + head];

    float4 acc = make_float4(0.f, 0.f, 0.f, 0.f);
    int b = g_off[z][d], e_ = g_off[z][d + 1];
    if (b < e_) {
        int2 peA = eid2[b];
        int2 peB = (b + 1 < e_) ? eid2[b + 1] : peA;
        float axA = ex[(size_t)peA.x * NHEAD + head];
        for (int i = b; i < e_; i++) {
            int2 peC = (i + 2 < e_) ? eid2[i + 2] : peB;
            float axB = (i + 1 < e_) ? ex[(size_t)peB.x * NHEAD + head] : 0.f;
            float4 f = *(const float4*)(feat + (size_t)peA.y * DDIM + col);
            float a = axA * rcp;
            acc.x += f.x * a;
            acc.y += f.y * a;
            acc.z += f.z * a;
            acc.w += f.w * a;
            peA = peB; peB = peC; axA = axB;
        }
    }
    float4 bb = *(const float4*)(bias + col);
    float4 v;
    v.x = acc.x + bb.x; v.x = v.x > 0.f ? v.x : (__expf(v.x) - 1.f);
    v.y = acc.y + bb.y; v.y = v.y > 0.f ? v.y : (__expf(v.y) - 1.f);
    v.z = acc.z + bb.z; v.z = v.z > 0.f ? v.z : (__expf(v.z) - 1.f);
    v.w = acc.w + bb.w; v.w = v.w > 0.f ? v.w : (__expf(v.w) - 1.f);
    *(float4*)(g_z[z] + (size_t)d * DDIM + col) = v;
}

// ---------------- semantic attention ----------------

__global__ void sem_score_kernel(FP4 b14, FP4 W24) {
    int z = blockIdx.y;
    int w = blockIdx.x * 8 + (threadIdx.x >> 5);
    int lane = threadIdx.x & 31;
    if (w >= NNODES) return;
    const float* b1 = b14.p[z];
    const float* W2 = W24.p[z];
    float t = 0.f;
#pragma unroll
    for (int q = 0; q < 4; q++) {
        int j = lane + 32 * q;
        t += tanhf(g_sc[z][(size_t)w * SEMH + j] + b1[j]) * W2[j];
    }
#pragma unroll
    for (int o = 16; o > 0; o >>= 1) t += __shfl_down_sync(0xffffffffu, t, o);
    if (lane == 0) g_w[z][w] = t;
}

// fuse writes tf32 bits directly (fu only feeds the pred GEMM)
__global__ void fuse_kernel() {
    int b = blockIdx.y;
    int i = blockIdx.x * blockDim.x + threadIdx.x;
    if (i >= NNODES * DDIM) return;
    int n = i >> 9;
    float a = g_w[2 * b][n], c = g_w[2 * b + 1][n];
    float m = fmaxf(a, c);
    float ea = __expf(a - m), eb = __expf(c - m);
    float be = ea / (ea + eb);
    t_fu[b][i] = f2tf(be * g_z[2 * b][i] + (1.f - be) * g_z[2 * b + 1][i]);
}

// ---------------- host orchestration ----------------

extern "C" void kernel_launch(void* const* d_in, const int* in_sizes, int n_in,
                              void* d_out, int out_size) {
    float *p_feat[4], *p_z[4], *p_sc[4];
    unsigned *p_tx[2], *p_twhw[2], *p_tfc[2], *p_tpred[2], *p_two[2], *p_tfu[2], *p_th[2];
    {
        float* base;
        cudaGetSymbolAddress((void**)&base, g_feat);
        for (int z = 0; z < 4; z++) p_feat[z] = base + (size_t)z * NNODES * DDIM;
        cudaGetSymbolAddress((void**)&base, g_z);
        for (int z = 0; z < 4; z++) p_z[z] = base + (size_t)z * NNODES * DDIM;
        cudaGetSymbolAddress((void**)&base, g_sc);
        for (int z = 0; z < 4; z++) p_sc[z] = base + (size_t)z * NNODES * SEMH;
        unsigned* ub;
        cudaGetSymbolAddress((void**)&ub, t_x);
        for (int b = 0; b < 2; b++) p_tx[b] = ub + (size_t)b * NNODES * FDIM;
        cudaGetSymbolAddress((void**)&ub, t_whw);
        for (int b = 0; b < 2; b++) p_twhw[b] = ub + (size_t)b * FDIM * FDIM;
        cudaGetSymbolAddress((void**)&ub, t_fc);
        for (int b = 0; b < 2; b++) p_tfc[b] = ub + (size_t)b * 2 * FDIM * DDIM;
        cudaGetSymbolAddress((void**)&ub, t_pred);
        for (int b = 0; b < 2; b++) p_tpred[b] = ub + (size_t)b * DDIM * OSZ;
        cudaGetSymbolAddress((void**)&ub, t_who);
        for (int b = 0; b < 2; b++) p_two[b] = ub + (size_t)b * NNODES * FDIM;
        cudaGetSymbolAddress((void**)&ub, t_fu);
        for (int b = 0; b < 2; b++) p_tfu[b] = ub + (size_t)b * NNODES * DDIM;
        cudaGetSymbolAddress((void**)&ub, t_h);
        for (int b = 0; b < 2; b++) p_th[b] = ub + (size_t)b * NNODES * OSZ;
    }
    int* p_cur;
    cudaGetSymbolAddress((void**)&p_cur, g_cur);

    const float* hx = (const float*)d_in[0];
    const float* tx = (const float*)d_in[1];
    const float* w_h[2]  = {(const float*)d_in[2],  (const float*)d_in[11]};
    const float* fc[2]   = {(const float*)d_in[3],  (const float*)d_in[12]};
    const float* al[2]   = {(const float*)d_in[4],  (const float*)d_in[13]};
    const float* ar[2]   = {(const float*)d_in[5],  (const float*)d_in[14]};
    const float* bias[2] = {(const float*)d_in[6],  (const float*)d_in[15]};
    const float* W1[2]   = {(const float*)d_in[7],  (const float*)d_in[16]};
    const float* b1[2]   = {(const float*)d_in[8],  (const float*)d_in[17]};
    const float* W2[2]   = {(const float*)d_in[9],  (const float*)d_in[18]};
    const float* pred[2] = {(const float*)d_in[10], (const float*)d_in[19]};

    IP4 ed4 = {{(const int*)d_in[20], (const int*)d_in[21],
                (const int*)d_in[22], (const int*)d_in[23]}};
    FP4 al4   = {{al[0], al[0] + NHEAD * 64, al[1], al[1] + NHEAD * 64}};
    FP4 ar4   = {{ar[0], ar[0] + NHEAD * 64, ar[1], ar[1] + NHEAD * 64}};
    FP4 bias4 = {{bias[0], bias[0] + DDIM, bias[1], bias[1] + DDIM}};
    FP4 b14   = {{b1[0], b1[0], b1[1], b1[1]}};
    FP4 W24   = {{W2[0], W2[0], W2[1], W2[1]}};

    float* out  = (float*)d_out;
    float* h1   = out;
    float* h2   = out + (size_t)NNODES * OSZ;
    float* prod = out + (size_t)2 * NNODES * OSZ;

    // smem sizes for async GEMM instantiations
    const int SM_WH   = 4 * (128 * 20 + 16 * 136) * 4;   // 75776
    const int SM_FEAT = SM_WH;
    const int SM_PRED = 4 * (64 * 20 + 16 * 136) * 4;    // 55296
    const int SM_NT   = 4 * (128 * 20 + 128 * 20) * 4;   // 81920
    cudaFuncSetAttribute(mma_gemm_async<4, false, 1>,
                         cudaFuncAttributeMaxDynamicSharedMemorySize, SM_WH);
    cudaFuncSetAttribute(mma_gemm_async<4, false, 0>,
                         cudaFuncAttributeMaxDynamicSharedMemorySize, SM_FEAT);
    cudaFuncSetAttribute(mma_gemm_async<2, false, 2>,
                         cudaFuncAttributeMaxDynamicSharedMemorySize, SM_PRED);
    cudaFuncSetAttribute(mma_gemm_async<4, true, 0>,
                         cudaFuncAttributeMaxDynamicSharedMemorySize, SM_NT);

    // 0) clear histograms, CSR offsets, and one-shot tf32 conversion
    cudaMemsetAsync(p_cur, 0, 4 * NNODES * sizeof(int), 0);
    count_kernel<<<dim3((NEDGE + 255) / 256, 4), 256>>>(ed4);
    scan_kernel<<<4, 1024>>>();
    {
        CVT c = {};
        c.src[0] = hx;      c.dst[0] = p_tx[0];    c.n4[0] = NNODES * FDIM / 4;
        c.src[1] = tx;      c.dst[1] = p_tx[1];    c.n4[1] = NNODES * FDIM / 4;
        c.src[2] = w_h[0];  c.dst[2] = p_twhw[0];  c.n4[2] = FDIM * FDIM / 4;
        c.src[3] = w_h[1];  c.dst[3] = p_twhw[1];  c.n4[3] = FDIM * FDIM / 4;
        c.src[4] = fc[0];   c.dst[4] = p_tfc[0];   c.n4[4] = 2 * FDIM * DDIM / 4;
        c.src[5] = fc[1];   c.dst[5] = p_tfc[1];   c.n4[5] = 2 * FDIM * DDIM / 4;
        c.src[6] = pred[0]; c.dst[6] = p_tpred[0]; c.n4[6] = DDIM * OSZ / 4;
        c.src[7] = pred[1]; c.dst[7] = p_tpred[1]; c.n4[7] = DDIM * OSZ / 4;
        cvt_kernel<<<dim3(640, 8), 256>>>(c);
    }

    // 1) wh = x @ w_h (batched x2, tf32-out epilogue)
    {
        GB gb = {};
        gb.A[0] = p_tx[0]; gb.B[0] = p_twhw[0]; gb.C[0] = p_two[0];
        gb.A[1] = p_tx[1]; gb.B[1] = p_twhw[1]; gb.C[1] = p_two[1];
        dim3 g(FDIM / 128, (NNODES + 127) / 128, 2);
        mma_gemm_async<4, false, 1><<<g, 256, SM_WH>>>(gb, NNODES, FDIM, FDIM);
    }
    // 2) feat = wh @ fc (batched x4)
    {
        GB gb = {};
        for (int z = 0; z < 4; z++) {
            gb.A[z] = p_two[z >> 1];
            gb.B[z] = p_tfc[z >> 1] + (size_t)(z & 1) * FDIM * DDIM;
            gb.C[z] = p_feat[z];
        }
        dim3 g(DDIM / 128, (NNODES + 127) / 128, 4);
        mma_gemm_async<4, false, 0><<<g, 256, SM_FEAT>>>(gb, NNODES, DDIM, FDIM);
    }
    // 3) logits + fused exp/sum/scatter + aggregate (all x4)
    eler_kernel<<<dim3(NNODES, 4), 256>>>(al4, ar4);
    exp_scatter_kernel<<<dim3((NEDGE + 255) / 256, 4), 256>>>(ed4);
    agg_kernel<<<dim3((NNODES * 4 + 7) / 8, 4), 256>>>(bias4);

    // 4) semantic attention (cvt-staging GEMM, x4) + fuse (x2, tf32-out)
    {
        GB gb = {};
        for (int z = 0; z < 4; z++) {
            gb.A[z] = p_z[z];
            gb.B[z] = W1[z >> 1];
            gb.C[z] = p_sc[z];
        }
        dim3 g(1, (NNODES + 63) / 64, 4);
        mma_gemm_cvt<2, false><<<g, 256>>>(gb, NNODES, SEMH, DDIM);
    }
    sem_score_kernel<<<dim3((NNODES + 7) / 8, 4), 256>>>(b14, W24);
    fuse_kernel<<<dim3((NNODES * DDIM + 255) / 256, 2), 256>>>();

    // 5) prediction heads (batched x2, dual f32 + tf32 epilogue)
    {
        GB gb = {};
        gb.A[0] = p_tfu[0]; gb.B[0] = p_tpred[0]; gb.C[0] = h1; gb.C2[0] = p_th[0];
        gb.A[1] = p_tfu[1]; gb.B[1] = p_tpred[1]; gb.C[1] = h2; gb.C2[1] = p_th[1];
        dim3 g(1, (NNODES + 63) / 64, 2);
        mma_gemm_async<2, false, 2><<<g, 256, SM_PRED>>>(gb, NNODES, OSZ, DDIM);
    }
    // 6) prod = h1 @ h2^T (tf32 copies)
    {
        GB gb = {};
        gb.A[0] = p_th[0]; gb.B[0] = p_th[1]; gb.C[0] = prod;
        dim3 g((NNODES + 127) / 128, (NNODES + 127) / 128, 1);
        mma_gemm_async<4, true, 0><<<g, 256, SM_NT>>>(gb, NNODES, NNODES, OSZ);
    }
}

// round 11
// speedup vs baseline: 3.5204x; 1.0742x over previous
#include <cuda_runtime.h>
#include <cstdint>

#define NNODES 10000
#define FDIM   256
#define DDIM   512
#define NEDGE  160000
#define NHEAD  8
#define SEMH   128
#define OSZ    64

// ---------------- scratch (static device globals; no allocation) ----------------
// instance index z in [0,4): branch = z>>1 (0=herb,1=target), metapath = z&1
__device__ float g_feat[4][NNODES * DDIM];
__device__ float g_z   [4][NNODES * DDIM];
__device__ float g_el  [4][NNODES * NHEAD];
__device__ float g_er  [4][NNODES * NHEAD];
__device__ float g_sm  [4][NNODES * NHEAD];
__device__ float g_ex  [4][NEDGE * NHEAD];
__device__ float g_sc  [4][NNODES * SEMH];
__device__ float g_w   [4][NNODES];
__device__ int   g_off [4][NNODES + 1];
__device__ int   g_cur [4][NNODES];
__device__ int2  g_eid2[4][NEDGE];
// tf32-at-rest operands (bits stored as unsigned)
__device__ unsigned t_x   [2][NNODES * FDIM];
__device__ unsigned t_whw [2][FDIM * FDIM];
__device__ unsigned t_fc  [2][2 * FDIM * DDIM];
__device__ unsigned t_pred[2][DDIM * OSZ];
__device__ unsigned t_W1  [2][DDIM * SEMH];
__device__ unsigned t_W   [4][FDIM * DDIM];      // combined w_h @ fc
__device__ unsigned t_z   [4][NNODES * DDIM];    // tf32 copy of z (for sem GEMM)
__device__ unsigned t_fu  [2][NNODES * DDIM];
__device__ unsigned t_h   [2][NNODES * OSZ];

struct GB   { const void* A[4]; const void* B[4]; void* C[4]; void* C2[4]; };
struct IP4  { const int*   p[4]; };
struct FP4  { const float* p[4]; };
struct CVT  { const float* src[10]; unsigned* dst[10]; int n4[10]; };

__device__ __forceinline__ unsigned f2tf(float f) {
    unsigned r;
    asm("cvt.rna.tf32.f32 %0, %1;" : "=r"(r) : "f"(f));
    return r;
}

// ---------------- one-shot f32 -> tf32 conversion (weights + inputs) ----------
__global__ void cvt_kernel(CVT c) {
    int seg = blockIdx.y;
    int n4 = c.n4[seg];
    const float4* s = (const float4*)c.src[seg];
    uint4* d = (uint4*)c.dst[seg];
    for (int i = blockIdx.x * 256 + threadIdx.x; i < n4; i += gridDim.x * 256) {
        float4 v = s[i];
        d[i] = make_uint4(f2tf(v.x), f2tf(v.y), f2tf(v.z), f2tf(v.w));
    }
}

// ---------------- async tf32 MMA GEMM: cp.async 4-stage, z-batched -----------
// Block tile BM(=32*MT) x 128, K-tile 16. 256 threads = 8 warps 2(m) x 4(n).
// Operands already tf32 bits -> staging is pure cp.async.cg 16B copies into
// pitched raw tiles (pitch 20 / 136 words: conflict-free LDS.32 frag reads).
// EPI: 0 = f32 C, 1 = tf32 C, 2 = f32 C + tf32 C2, 3 = f32 C streaming (.cs).

template<int MT, bool TRANSB, int EPI>
__global__ __launch_bounds__(256, 2) void mma_gemm_async(GB gb, int M, int N, int K) {
    constexpr int S  = 4;
    constexpr int BM = 32 * MT;
    constexpr int PA = 20;
    constexpr int PB = TRANSB ? 20 : 136;
    constexpr int AW = BM * PA;
    constexpr int BW = TRANSB ? 128 * PB : 16 * PB;
    constexpr int AQ = BM / 64;
    extern __shared__ unsigned smem[];
    unsigned* sA = smem;            // S * AW
    unsigned* sB = smem + S * AW;   // S * BW

    const unsigned* __restrict__ A = (const unsigned*)gb.A[blockIdx.z];
    const unsigned* __restrict__ B = (const unsigned*)gb.B[blockIdx.z];
    float* C = (float*)gb.C[blockIdx.z];
    unsigned* C2 = (unsigned*)gb.C2[blockIdx.z];

    int tid = threadIdx.x, warp = tid >> 5, lane = tid & 31;
    int wm = warp >> 2, wn = warp & 3;
    int row0 = blockIdx.y * BM, col0 = blockIdx.x * 128;
    int nk = K >> 4;

    auto issue = [&](int t) {
        int k0 = t * 16, buf = t & (S - 1);
#pragma unroll
        for (int j = 0; j < AQ; j++) {
            int i = tid + j * 256;
            int r = i >> 2, c4 = i & 3;
            int gr = row0 + r;
            int sz = 16;
            if (gr >= M) { sz = 0; gr = row0; }
            unsigned sd = (unsigned)__cvta_generic_to_shared(sA + buf * AW + r * PA + c4 * 4);
            asm volatile("cp.async.cg.shared.global [%0], [%1], 16, %2;"
                         :: "r"(sd), "l"(A + (size_t)gr * K + k0 + c4 * 4), "r"(sz));
        }
#pragma unroll
        for (int j = 0; j < 2; j++) {
            int i = tid + j * 256;
            const unsigned* src;
            int dstw, sz = 16;
            if (!TRANSB) {
                int k = i >> 5, c4 = i & 31;
                int gc = col0 + c4 * 4;
                if (gc >= N) { sz = 0; gc = col0; }
                src = B + (size_t)(k0 + k) * N + gc;
                dstw = k * PB + c4 * 4;
            } else {
                int n = i >> 2, c4 = i & 3;
                int gn = col0 + n;
                if (gn >= N) { sz = 0; gn = col0; }
                src = B + (size_t)gn * K + k0 + c4 * 4;
                dstw = n * PB + c4 * 4;
            }
            unsigned sd = (unsigned)__cvta_generic_to_shared(sB + buf * BW + dstw);
            asm volatile("cp.async.cg.shared.global [%0], [%1], 16, %2;"
                         :: "r"(sd), "l"(src), "r"(sz));
        }
    };

    float acc[MT][4][4];
#pragma unroll
    for (int i = 0; i < MT; i++)
#pragma unroll
        for (int j = 0; j < 4; j++)
#pragma unroll
            for (int q = 0; q < 4; q++) acc[i][j][q] = 0.f;

#pragma unroll
    for (int t = 0; t < S - 1; t++) {
        if (t < nk) issue(t);
        asm volatile("cp.async.commit_group;");
    }

    const int aB0 = (wm * MT * 16 + (lane >> 2)) * PA + (lane & 3);
    const int bB0 = TRANSB ? (wn * 32 + (lane >> 2)) * PB + (lane & 3)
                           : (lane & 3) * PB + wn * 32 + (lane >> 2);

    for (int t = 0; t < nk; t++) {
        int buf = t & (S - 1);
        asm volatile("cp.async.wait_group %0;" :: "n"(S - 2));
        __syncthreads();
        if (t + S - 1 < nk) issue(t + S - 1);
        asm volatile("cp.async.commit_group;");

        const unsigned* __restrict__ ap = sA + buf * AW + aB0;
        const unsigned* __restrict__ bp = sB + buf * BW + bB0;
#pragma unroll
        for (int ks = 0; ks < 2; ks++) {
            unsigned af[MT][4];
            unsigned bf[4][2];
#pragma unroll
            for (int mt = 0; mt < MT; mt++) {
                const unsigned* p = ap + mt * (16 * PA) + ks * 8;
                af[mt][0] = p[0];
                af[mt][1] = p[8 * PA];
                af[mt][2] = p[4];
                af[mt][3] = p[8 * PA + 4];
            }
#pragma unroll
            for (int nt = 0; nt < 4; nt++) {
                if (!TRANSB) {
                    const unsigned* p = bp + ks * 8 * PB + nt * 8;
                    bf[nt][0] = p[0];
                    bf[nt][1] = p[4 * PB];
                } else {
                    const unsigned* p = bp + nt * 8 * PB + ks * 8;
                    bf[nt][0] = p[0];
                    bf[nt][1] = p[4];
                }
            }
#pragma unroll
            for (int mt = 0; mt < MT; mt++)
#pragma unroll
                for (int nt = 0; nt < 4; nt++) {
                    asm volatile(
                        "mma.sync.aligned.m16n8k8.row.col.f32.tf32.tf32.f32 "
                        "{%0,%1,%2,%3}, {%4,%5,%6,%7}, {%8,%9}, {%0,%1,%2,%3};"
                        : "+f"(acc[mt][nt][0]), "+f"(acc[mt][nt][1]),
                          "+f"(acc[mt][nt][2]), "+f"(acc[mt][nt][3])
                        : "r"(af[mt][0]), "r"(af[mt][1]), "r"(af[mt][2]), "r"(af[mt][3]),
                          "r"(bf[nt][0]), "r"(bf[nt][1]));
                }
        }
    }

#pragma unroll
    for (int mt = 0; mt < MT; mt++) {
        int r0 = row0 + wm * (MT * 16) + mt * 16 + (lane >> 2);
#pragma unroll
        for (int nt = 0; nt < 4; nt++) {
            int c = col0 + wn * 32 + nt * 8 + (lane & 3) * 2;
            if (c < N) {
#pragma unroll
                for (int h = 0; h < 2; h++) {
                    int r = r0 + h * 8;
                    if (r < M) {
                        float v0 = acc[mt][nt][2 * h], v1 = acc[mt][nt][2 * h + 1];
                        if (EPI == 0 || EPI == 2)
                            *(float2*)(C + (size_t)r * N + c) = make_float2(v0, v1);
                        if (EPI == 3)
                            asm volatile("st.global.cs.v2.f32 [%0], {%1,%2};"
                                         :: "l"(C + (size_t)r * N + c), "f"(v0), "f"(v1)
                                         : "memory");
                        if (EPI == 1)
                            *(uint2*)((unsigned*)C + (size_t)r * N + c) =
                                make_uint2(f2tf(v0), f2tf(v1));
                        if (EPI == 2)
                            *(uint2*)(C2 + (size_t)r * N + c) =
                                make_uint2(f2tf(v0), f2tf(v1));
                    }
                }
            }
        }
    }
}

// ---------------- GAT kernels (grid.y = instance z) ----------------

__global__ void eler_kernel(FP4 al4, FP4 ar4) {
    int z = blockIdx.y;
    int w = blockIdx.x * 8 + (threadIdx.x >> 5);
    int lane = threadIdx.x & 31;
    if (w >= NNODES * NHEAD) return;
    int n = w >> 3, h = w & 7;
    const float* al = al4.p[z];
    const float* ar = ar4.p[z];
    const float* f = g_feat[z] + (size_t)n * DDIM + h * 64;
    float sl = f[lane] * al[h * 64 + lane] + f[lane + 32] * al[h * 64 + lane + 32];
    float sr = f[lane] * ar[h * 64 + lane] + f[lane + 32] * ar[h * 64 + lane + 32];
#pragma unroll
    for (int o = 16; o > 0; o >>= 1) {
        sl += __shfl_down_sync(0xffffffffu, sl, o);
        sr += __shfl_down_sync(0xffffffffu, sr, o);
    }
    if (lane == 0) {
        g_el[z][w] = sl;
        g_er[z][w] = sr;
        g_sm[z][w] = 0.f;
    }
}

__global__ void count_kernel(IP4 ed4) {
    int z = blockIdx.y;
    int i = blockIdx.x * blockDim.x + threadIdx.x;
    if (i >= NEDGE) return;
    atomicAdd(&g_cur[z][ed4.p[z][NEDGE + i]], 1);
}

__global__ void scan_kernel() {
    int z = blockIdx.x;
    int* cur = g_cur[z];
    int* off = g_off[z];
    __shared__ int part[1024];
    int t = threadIdx.x;
    int base = t * 10;
    int v[10];
    int s = 0;
#pragma unroll
    for (int j = 0; j < 10; j++) {
        int idx = base + j;
        int c = (idx < NNODES) ? cur[idx] : 0;
        v[j] = c;
        s += c;
    }
    part[t] = s;
    __syncthreads();
    for (int o = 1; o < 1024; o <<= 1) {
        int x = (t >= o) ? part[t - o] : 0;
        __syncthreads();
        part[t] += x;
        __syncthreads();
    }
    int run = (t > 0) ? part[t - 1] : 0;
#pragma unroll
    for (int j = 0; j < 10; j++) {
        int idx = base + j;
        if (idx < NNODES) {
            off[idx] = run;
            cur[idx] = run;
            run += v[j];
        }
    }
    if (t == 0) off[NNODES] = NEDGE;
}

__global__ void exp_scatter_kernel(IP4 ed4) {
    int z = blockIdx.y;
    int e = blockIdx.x * blockDim.x + threadIdx.x;
    if (e >= NEDGE) return;
    const int* ed = ed4.p[z];
    int s = ed[e], d = ed[NEDGE + e];
    float4 l0 = *(const float4*)&g_el[z][s * NHEAD];
    float4 l1 = *(const float4*)&g_el[z][s * NHEAD + 4];
    float4 r0 = *(const float4*)&g_er[z][d * NHEAD];
    float4 r1 = *(const float4*)&g_er[z][d * NHEAD + 4];
    float v[8] = {l0.x + r0.x, l0.y + r0.y, l0.z + r0.z, l0.w + r0.w,
                  l1.x + r1.x, l1.y + r1.y, l1.z + r1.z, l1.w + r1.w};
    float ex[8];
#pragma unroll
    for (int h = 0; h < 8; h++) {
        float t = v[h] > 0.f ? v[h] : 0.2f * v[h];
        ex[h] = __expf(t);
    }
    *(float4*)&g_ex[z][(size_t)e * NHEAD]     = make_float4(ex[0], ex[1], ex[2], ex[3]);
    *(float4*)&g_ex[z][(size_t)e * NHEAD + 4] = make_float4(ex[4], ex[5], ex[6], ex[7]);
#pragma unroll
    for (int h = 0; h < 8; h++) atomicAdd(&g_sm[z][d * NHEAD + h], ex[h]);
    int p = atomicAdd(&g_cur[z][d], 1);
    g_eid2[z][p] = make_int2(e, s);
}

// gather-aggregate: one warp per (dst node, 128-col strip); bias+ELU fused.
// dual epilogue: f32 z (for fuse) + tf32 bits (for sem GEMM).
__global__ __launch_bounds__(256) void agg_kernel(FP4 bias4) {
    int z = blockIdx.y;
    int wid = blockIdx.x * 8 + (threadIdx.x >> 5);
    if (wid >= NNODES * 4) return;
    const float* bias = bias4.p[z];
    const float* __restrict__ feat = g_feat[z];
    const float* __restrict__ ex = g_ex[z];
    const int2* __restrict__ eid2 = g_eid2[z];
    int d = wid >> 2, strip = wid & 3;
    int lane = threadIdx.x & 31;
    int col = strip * 128 + lane * 4;
    int head = col >> 6;
    float rcp = 1.f / g_sm[z][d * NHEAD + head];

    float4 acc = make_float4(0.f, 0.f, 0.f, 0.f);
    int b = g_off[z][d], e_ = g_off[z][d + 1];
    if (b < e_) {
        int2 peA = eid2[b];
        int2 peB = (b + 1 < e_) ? eid2[b + 1] : peA;
        float axA = ex[(size_t)peA.x * NHEAD + head];
        for (int i = b; i < e_; i++) {
            int2 peC = (i + 2 < e_) ? eid2[i + 2] : peB;
            float axB = (i + 1 < e_) ? ex[(size_t)peB.x * NHEAD + head] : 0.f;
            float4 f = *(const float4*)(feat + (size_t)peA.y * DDIM + col);
            float a = axA * rcp;
            acc.x += f.x * a;
            acc.y += f.y * a;
            acc.z += f.z * a;
            acc.w += f.w * a;
            peA = peB; peB = peC; axA = axB;
        }
    }
    float4 bb = *(const float4*)(bias + col);
    float4 v;
    v.x = acc.x + bb.x; v.x = v.x > 0.f ? v.x : (__expf(v.x) - 1.f);
    v.y = acc.y + bb.y; v.y = v.y > 0.f ? v.y : (__expf(v.y) - 1.f);
    v.z = acc.z + bb.z; v.z = v.z > 0.f ? v.z : (__expf(v.z) - 1.f);
    v.w = acc.w + bb.w; v.w = v.w > 0.f ? v.w : (__expf(v.w) - 1.f);
    *(float4*)(g_z[z] + (size_t)d * DDIM + col) = v;
    *(uint4*)(&t_z[z][(size_t)d * DDIM + col]) =
        make_uint4(f2tf(v.x), f2tf(v.y), f2tf(v.z), f2tf(v.w));
}

// ---------------- semantic attention ----------------

__global__ void sem_score_kernel(FP4 b14, FP4 W24) {
    int z = blockIdx.y;
    int w = blockIdx.x * 8 + (threadIdx.x >> 5);
    int lane = threadIdx.x & 31;
    if (w >= NNODES) return;
    const float* b1 = b14.p[z];
    const float* W2 = W24.p[z];
    float t = 0.f;
#pragma unroll
    for (int q = 0; q < 4; q++) {
        int j = lane + 32 * q;
        t += tanhf(g_sc[z][(size_t)w * SEMH + j] + b1[j]) * W2[j];
    }
#pragma unroll
    for (int o = 16; o > 0; o >>= 1) t += __shfl_down_sync(0xffffffffu, t, o);
    if (lane == 0) g_w[z][w] = t;
}

// fuse writes tf32 bits directly (fu only feeds the pred GEMM)
__global__ void fuse_kernel() {
    int b = blockIdx.y;
    int i = blockIdx.x * blockDim.x + threadIdx.x;
    if (i >= NNODES * DDIM) return;
    int n = i >> 9;
    float a = g_w[2 * b][n], c = g_w[2 * b + 1][n];
    float m = fmaxf(a, c);
    float ea = __expf(a - m), eb = __expf(c - m);
    float be = ea / (ea + eb);
    t_fu[b][i] = f2tf(be * g_z[2 * b][i] + (1.f - be) * g_z[2 * b + 1][i]);
}

// ---------------- host orchestration ----------------

extern "C" void kernel_launch(void* const* d_in, const int* in_sizes, int n_in,
                              void* d_out, int out_size) {
    float *p_feat[4], *p_sc[4];
    unsigned *p_tx[2], *p_twhw[2], *p_tfc[2], *p_tpred[2], *p_tW1[2];
    unsigned *p_tW[4], *p_tz[4], *p_tfu[2], *p_th[2];
    {
        float* base;
        cudaGetSymbolAddress((void**)&base, g_feat);
        for (int z = 0; z < 4; z++) p_feat[z] = base + (size_t)z * NNODES * DDIM;
        cudaGetSymbolAddress((void**)&base, g_sc);
        for (int z = 0; z < 4; z++) p_sc[z] = base + (size_t)z * NNODES * SEMH;
        unsigned* ub;
        cudaGetSymbolAddress((void**)&ub, t_x);
        for (int b = 0; b < 2; b++) p_tx[b] = ub + (size_t)b * NNODES * FDIM;
        cudaGetSymbolAddress((void**)&ub, t_whw);
        for (int b = 0; b < 2; b++) p_twhw[b] = ub + (size_t)b * FDIM * FDIM;
        cudaGetSymbolAddress((void**)&ub, t_fc);
        for (int b = 0; b < 2; b++) p_tfc[b] = ub + (size_t)b * 2 * FDIM * DDIM;
        cudaGetSymbolAddress((void**)&ub, t_pred);
        for (int b = 0; b < 2; b++) p_tpred[b] = ub + (size_t)b * DDIM * OSZ;
        cudaGetSymbolAddress((void**)&ub, t_W1);
        for (int b = 0; b < 2; b++) p_tW1[b] = ub + (size_t)b * DDIM * SEMH;
        cudaGetSymbolAddress((void**)&ub, t_W);
        for (int z = 0; z < 4; z++) p_tW[z] = ub + (size_t)z * FDIM * DDIM;
        cudaGetSymbolAddress((void**)&ub, t_z);
        for (int z = 0; z < 4; z++) p_tz[z] = ub + (size_t)z * NNODES * DDIM;
        cudaGetSymbolAddress((void**)&ub, t_fu);
        for (int b = 0; b < 2; b++) p_tfu[b] = ub + (size_t)b * NNODES * DDIM;
        cudaGetSymbolAddress((void**)&ub, t_h);
        for (int b = 0; b < 2; b++) p_th[b] = ub + (size_t)b * NNODES * OSZ;
    }
    int* p_cur;
    cudaGetSymbolAddress((void**)&p_cur, g_cur);

    const float* hx = (const float*)d_in[0];
    const float* tx = (const float*)d_in[1];
    const float* w_h[2]  = {(const float*)d_in[2],  (const float*)d_in[11]};
    const float* fc[2]   = {(const float*)d_in[3],  (const float*)d_in[12]};
    const float* al[2]   = {(const float*)d_in[4],  (const float*)d_in[13]};
    const float* ar[2]   = {(const float*)d_in[5],  (const float*)d_in[14]};
    const float* bias[2] = {(const float*)d_in[6],  (const float*)d_in[15]};
    const float* W1[2]   = {(const float*)d_in[7],  (const float*)d_in[16]};
    const float* b1[2]   = {(const float*)d_in[8],  (const float*)d_in[17]};
    const float* W2[2]   = {(const float*)d_in[9],  (const float*)d_in[18]};
    const float* pred[2] = {(const float*)d_in[10], (const float*)d_in[19]};

    IP4 ed4 = {{(const int*)d_in[20], (const int*)d_in[21],
                (const int*)d_in[22], (const int*)d_in[23]}};
    FP4 al4   = {{al[0], al[0] + NHEAD * 64, al[1], al[1] + NHEAD * 64}};
    FP4 ar4   = {{ar[0], ar[0] + NHEAD * 64, ar[1], ar[1] + NHEAD * 64}};
    FP4 bias4 = {{bias[0], bias[0] + DDIM, bias[1], bias[1] + DDIM}};
    FP4 b14   = {{b1[0], b1[0], b1[1], b1[1]}};
    FP4 W24   = {{W2[0], W2[0], W2[1], W2[1]}};

    float* out  = (float*)d_out;
    float* h1   = out;
    float* h2   = out + (size_t)NNODES * OSZ;
    float* prod = out + (size_t)2 * NNODES * OSZ;

    const int SM_NN4 = 4 * (128 * 20 + 16 * 136) * 4;   // 75776
    const int SM_NN2 = 4 * (64 * 20 + 16 * 136) * 4;    // 55296
    const int SM_NT  = 4 * (128 * 20 + 128 * 20) * 4;   // 81920
    cudaFuncSetAttribute(mma_gemm_async<4, false, 1>,
                         cudaFuncAttributeMaxDynamicSharedMemorySize, SM_NN4);
    cudaFuncSetAttribute(mma_gemm_async<4, false, 0>,
                         cudaFuncAttributeMaxDynamicSharedMemorySize, SM_NN4);
    cudaFuncSetAttribute(mma_gemm_async<2, false, 0>,
                         cudaFuncAttributeMaxDynamicSharedMemorySize, SM_NN2);
    cudaFuncSetAttribute(mma_gemm_async<2, false, 2>,
                         cudaFuncAttributeMaxDynamicSharedMemorySize, SM_NN2);
    cudaFuncSetAttribute(mma_gemm_async<4, true, 3>,
                         cudaFuncAttributeMaxDynamicSharedMemorySize, SM_NT);

    // 0) clear histograms, CSR offsets, and one-shot tf32 conversion
    cudaMemsetAsync(p_cur, 0, 4 * NNODES * sizeof(int), 0);
    count_kernel<<<dim3((NEDGE + 255) / 256, 4), 256>>>(ed4);
    scan_kernel<<<4, 1024>>>();
    {
        CVT c = {};
        c.src[0] = hx;      c.dst[0] = p_tx[0];    c.n4[0] = NNODES * FDIM / 4;
        c.src[1] = tx;      c.dst[1] = p_tx[1];    c.n4[1] = NNODES * FDIM / 4;
        c.src[2] = w_h[0];  c.dst[2] = p_twhw[0];  c.n4[2] = FDIM * FDIM / 4;
        c.src[3] = w_h[1];  c.dst[3] = p_twhw[1];  c.n4[3] = FDIM * FDIM / 4;
        c.src[4] = fc[0];   c.dst[4] = p_tfc[0];   c.n4[4] = 2 * FDIM * DDIM / 4;
        c.src[5] = fc[1];   c.dst[5] = p_tfc[1];   c.n4[5] = 2 * FDIM * DDIM / 4;
        c.src[6] = pred[0]; c.dst[6] = p_tpred[0]; c.n4[6] = DDIM * OSZ / 4;
        c.src[7] = pred[1]; c.dst[7] = p_tpred[1]; c.n4[7] = DDIM * OSZ / 4;
        c.src[8] = W1[0];   c.dst[8] = p_tW1[0];   c.n4[8] = DDIM * SEMH / 4;
        c.src[9] = W1[1];   c.dst[9] = p_tW1[1];   c.n4[9] = DDIM * SEMH / 4;
        cvt_kernel<<<dim3(640, 10), 256>>>(c);
    }

    // 1) combined weights W[z] = w_h[b] @ fc[b][m]  (256x512, K=256, tf32-out)
    {
        GB gb = {};
        for (int z = 0; z < 4; z++) {
            gb.A[z] = p_twhw[z >> 1];
            gb.B[z] = p_tfc[z >> 1] + (size_t)(z & 1) * FDIM * DDIM;
            gb.C[z] = p_tW[z];
        }
        dim3 g(DDIM / 128, FDIM / 128, 4);
        mma_gemm_async<4, false, 1><<<g, 256, SM_NN4>>>(gb, FDIM, DDIM, FDIM);
    }
    // 2) feat = x @ W  (batched x4; wh GEMM eliminated)
    {
        GB gb = {};
        for (int z = 0; z < 4; z++) {
            gb.A[z] = p_tx[z >> 1];
            gb.B[z] = p_tW[z];
            gb.C[z] = p_feat[z];
        }
        dim3 g(DDIM / 128, (NNODES + 127) / 128, 4);
        mma_gemm_async<4, false, 0><<<g, 256, SM_NN4>>>(gb, NNODES, DDIM, FDIM);
    }
    // 3) logits + fused exp/sum/scatter + aggregate (all x4)
    eler_kernel<<<dim3(NNODES, 4), 256>>>(al4, ar4);
    exp_scatter_kernel<<<dim3((NEDGE + 255) / 256, 4), 256>>>(ed4);
    agg_kernel<<<dim3((NNODES * 4 + 7) / 8, 4), 256>>>(bias4);

    // 4) semantic attention (async GEMM on tf32 z) + fuse (x2, tf32-out)
    {
        GB gb = {};
        for (int z = 0; z < 4; z++) {
            gb.A[z] = p_tz[z];
            gb.B[z] = p_tW1[z >> 1];
            gb.C[z] = p_sc[z];
        }
        dim3 g(1, (NNODES + 63) / 64, 4);
        mma_gemm_async<2, false, 0><<<g, 256, SM_NN2>>>(gb, NNODES, SEMH, DDIM);
    }
    sem_score_kernel<<<dim3((NNODES + 7) / 8, 4), 256>>>(b14, W24);
    fuse_kernel<<<dim3((NNODES * DDIM + 255) / 256, 2), 256>>>();

    // 5) prediction heads (batched x2, dual f32 + tf32 epilogue)
    {
        GB gb = {};
        gb.A[0] = p_tfu[0]; gb.B[0] = p_tpred[0]; gb.C[0] = h1; gb.C2[0] = p_th[0];
        gb.A[1] = p_tfu[1]; gb.B[1] = p_tpred[1]; gb.C[1] = h2; gb.C2[1] = p_th[1];
        dim3 g(1, (NNODES + 63) / 64, 2);
        mma_gemm_async<2, false, 2><<<g, 256, SM_NN2>>>(gb, NNODES, OSZ, DDIM);
    }
    // 6) prod = h1 @ h2^T (tf32 copies, streaming stores)
    {
        GB gb = {};
        gb.A[0] = p_th[0]; gb.B[0] = p_th[1]; gb.C[0] = prod;
        dim3 g((NNODES + 127) / 128, (NNODES + 127) / 128, 1);
        mma_gemm_async<4, true, 3><<<g, 256, SM_NT>>>(gb, NNODES, NNODES, OSZ);
    }
}

// round 12
// speedup vs baseline: 4.0955x; 1.1634x over previous
#include <cuda_runtime.h>
#include <cstdint>

#define NNODES 10000
#define FDIM   256
#define DDIM   512
#define NEDGE  160000
#define NHEAD  8
#define SEMH   128
#define OSZ    64

// ---------------- scratch (static device globals; no allocation) ----------------
__device__ float g_feat[4][NNODES * DDIM];
__device__ float g_z   [4][NNODES * DDIM];
__device__ float g_el  [4][NNODES * NHEAD];
__device__ float g_er  [4][NNODES * NHEAD];
__device__ float g_sm  [4][NNODES * NHEAD];
__device__ float g_ex  [4][NEDGE * NHEAD];
__device__ float g_sc  [4][NNODES * SEMH];
__device__ float g_w   [4][NNODES];
__device__ int   g_off [4][NNODES + 1];
__device__ int   g_cur [4][NNODES];
__device__ int2  g_eid2[4][NEDGE];
// tf32-at-rest operands (bits stored as unsigned)
__device__ unsigned t_x   [2][NNODES * FDIM];
__device__ unsigned t_whw [2][FDIM * FDIM];
__device__ unsigned t_fc  [2][2 * FDIM * DDIM];
__device__ unsigned t_pred[2][DDIM * OSZ];
__device__ unsigned t_W1  [2][DDIM * SEMH];
__device__ unsigned t_W   [4][FDIM * DDIM];
__device__ unsigned t_z   [4][NNODES * DDIM];
__device__ unsigned t_fu  [2][NNODES * DDIM];
__device__ unsigned t_h   [2][NNODES * OSZ];

struct GB {
    const void* A[4]; const void* B[4]; void* C[4]; void* C2[4];
    const float* AL[4]; const float* AR[4]; float* EL[4]; float* ER[4];
};
struct IP4  { const int*   p[4]; };
struct FP4  { const float* p[4]; };
struct CVT  { const float* src[10]; unsigned* dst[10]; int n4[10]; };

__device__ __forceinline__ unsigned f2tf(float f) {
    unsigned r;
    asm("cvt.rna.tf32.f32 %0, %1;" : "=r"(r) : "f"(f));
    return r;
}

// ---------------- one-shot f32 -> tf32 conversion ----------
__global__ void cvt_kernel(CVT c) {
    int seg = blockIdx.y;
    int n4 = c.n4[seg];
    const float4* s = (const float4*)c.src[seg];
    uint4* d = (uint4*)c.dst[seg];
    for (int i = blockIdx.x * 256 + threadIdx.x; i < n4; i += gridDim.x * 256) {
        float4 v = s[i];
        d[i] = make_uint4(f2tf(v.x), f2tf(v.y), f2tf(v.z), f2tf(v.w));
    }
}

// ---------------- async tf32 MMA GEMM: cp.async 4-stage, z-batched -----------
// Block tile BM(=32*MT) x 128, K-tile 16. 256 threads = 8 warps 2(m) x 4(n).
// Pitched raw smem tiles (pitch 20 / 136 words); A fragments via ldmatrix.x4
// (pitch 20 puts each tile's 8 rows on all 32 banks -> conflict-free);
// B via ldmatrix.x4 (NT) or scalar LDS (NN).
// EPI: 0 = f32 C; 1 = tf32 C; 2 = f32 C + tf32 C2; 3 = f32 streaming;
//      4 = f32 C + fused el/er attention dot products (feat GEMM).

template<int MT, bool TRANSB, int EPI>
__global__ __launch_bounds__(256, 2) void mma_gemm_async(GB gb, int M, int N, int K) {
    constexpr int S  = 4;
    constexpr int BM = 32 * MT;
    constexpr int PA = 20;
    constexpr int PB = TRANSB ? 20 : 136;
    constexpr int AW = BM * PA;
    constexpr int BW = TRANSB ? 128 * PB : 16 * PB;
    constexpr int AQ = BM / 64;
    extern __shared__ unsigned smem[];
    unsigned* sA = smem;
    unsigned* sB = smem + S * AW;

    const unsigned* __restrict__ A = (const unsigned*)gb.A[blockIdx.z];
    const unsigned* __restrict__ B = (const unsigned*)gb.B[blockIdx.z];
    float* C = (float*)gb.C[blockIdx.z];
    unsigned* C2 = (unsigned*)gb.C2[blockIdx.z];

    int tid = threadIdx.x, warp = tid >> 5, lane = tid & 31;
    int wm = warp >> 2, wn = warp & 3;
    int row0 = blockIdx.y * BM, col0 = blockIdx.x * 128;
    int nk = K >> 4;
    unsigned sbase = (unsigned)__cvta_generic_to_shared(smem);

    auto issue = [&](int t) {
        int k0 = t * 16, buf = t & (S - 1);
#pragma unroll
        for (int j = 0; j < AQ; j++) {
            int i = tid + j * 256;
            int r = i >> 2, c4 = i & 3;
            int gr = row0 + r;
            int sz = 16;
            if (gr >= M) { sz = 0; gr = row0; }
            unsigned sd = sbase + ((buf * AW + r * PA + c4 * 4) << 2);
            asm volatile("cp.async.cg.shared.global [%0], [%1], 16, %2;"
                         :: "r"(sd), "l"(A + (size_t)gr * K + k0 + c4 * 4), "r"(sz));
        }
#pragma unroll
        for (int j = 0; j < 2; j++) {
            int i = tid + j * 256;
            const unsigned* src;
            int dstw, sz = 16;
            if (!TRANSB) {
                int k = i >> 5, c4 = i & 31;
                int gc = col0 + c4 * 4;
                if (gc >= N) { sz = 0; gc = col0; }
                src = B + (size_t)(k0 + k) * N + gc;
                dstw = k * PB + c4 * 4;
            } else {
                int n = i >> 2, c4 = i & 3;
                int gn = col0 + n;
                if (gn >= N) { sz = 0; gn = col0; }
                src = B + (size_t)gn * K + k0 + c4 * 4;
                dstw = n * PB + c4 * 4;
            }
            unsigned sd = sbase + ((S * AW + buf * BW + dstw) << 2);
            asm volatile("cp.async.cg.shared.global [%0], [%1], 16, %2;"
                         :: "r"(sd), "l"(src), "r"(sz));
        }
    };

    float acc[MT][4][4];
#pragma unroll
    for (int i = 0; i < MT; i++)
#pragma unroll
        for (int j = 0; j < 4; j++)
#pragma unroll
            for (int q = 0; q < 4; q++) acc[i][j][q] = 0.f;

#pragma unroll
    for (int t = 0; t < S - 1; t++) {
        if (t < nk) issue(t);
        asm volatile("cp.async.commit_group;");
    }

    // ldmatrix A thread address (within buf/ks): row = base + (lane&15), col-half = lane>>4
    const unsigned aLdm = ((wm * MT * 16 + (lane & 15)) * PA + (lane >> 4) * 4) << 2;
    // ldmatrix B (NT): row-in-pair = (lane&7) + ((lane>>4)&1)*8, col-half = (lane>>3)&1
    const unsigned bLdm = TRANSB
        ? (((wn * 32 + (lane & 7) + ((lane >> 4) & 1) * 8) * PB + ((lane >> 3) & 1) * 4) << 2)
        : 0u;
    const int bB0 = (lane & 3) * PB + wn * 32 + (lane >> 2);   // NN scalar path

    for (int t = 0; t < nk; t++) {
        int buf = t & (S - 1);
        asm volatile("cp.async.wait_group %0;" :: "n"(S - 2));
        __syncthreads();
        if (t + S - 1 < nk) issue(t + S - 1);
        asm volatile("cp.async.commit_group;");

#pragma unroll
        for (int ks = 0; ks < 2; ks++) {
            unsigned af[MT][4];
            unsigned bf[4][2];
            unsigned aAddr = sbase + ((buf * AW) << 2) + aLdm + ((ks * 8) << 2);
#pragma unroll
            for (int mt = 0; mt < MT; mt++) {
                asm volatile("ldmatrix.sync.aligned.m8n8.x4.shared.b16 "
                             "{%0,%1,%2,%3}, [%4];"
                             : "=r"(af[mt][0]), "=r"(af[mt][1]),
                               "=r"(af[mt][2]), "=r"(af[mt][3])
                             : "r"(aAddr + ((mt * 16 * PA) << 2)));
            }
            if (TRANSB) {
                unsigned bAddr = sbase + ((S * AW + buf * BW) << 2) + bLdm + ((ks * 8) << 2);
#pragma unroll
                for (int p = 0; p < 2; p++) {
                    asm volatile("ldmatrix.sync.aligned.m8n8.x4.shared.b16 "
                                 "{%0,%1,%2,%3}, [%4];"
                                 : "=r"(bf[2 * p][0]), "=r"(bf[2 * p][1]),
                                   "=r"(bf[2 * p + 1][0]), "=r"(bf[2 * p + 1][1])
                                 : "r"(bAddr + ((p * 16 * PB) << 2)));
                }
            } else {
                const unsigned* bp = smem + S * AW + buf * BW + bB0;
#pragma unroll
                for (int nt = 0; nt < 4; nt++) {
                    const unsigned* p = bp + ks * 8 * PB + nt * 8;
                    bf[nt][0] = p[0];
                    bf[nt][1] = p[4 * PB];
                }
            }
#pragma unroll
            for (int mt = 0; mt < MT; mt++)
#pragma unroll
                for (int nt = 0; nt < 4; nt++) {
                    asm volatile(
                        "mma.sync.aligned.m16n8k8.row.col.f32.tf32.tf32.f32 "
                        "{%0,%1,%2,%3}, {%4,%5,%6,%7}, {%8,%9}, {%0,%1,%2,%3};"
                        : "+f"(acc[mt][nt][0]), "+f"(acc[mt][nt][1]),
                          "+f"(acc[mt][nt][2]), "+f"(acc[mt][nt][3])
                        : "r"(af[mt][0]), "r"(af[mt][1]), "r"(af[mt][2]), "r"(af[mt][3]),
                          "r"(bf[nt][0]), "r"(bf[nt][1]));
                }
        }
    }

    // ---------------- epilogue ----------------
#pragma unroll
    for (int mt = 0; mt < MT; mt++) {
        int r0 = row0 + wm * (MT * 16) + mt * 16 + (lane >> 2);
#pragma unroll
        for (int nt = 0; nt < 4; nt++) {
            int c = col0 + wn * 32 + nt * 8 + (lane & 3) * 2;
            if (c < N) {
#pragma unroll
                for (int h = 0; h < 2; h++) {
                    int r = r0 + h * 8;
                    if (r < M) {
                        float v0 = acc[mt][nt][2 * h], v1 = acc[mt][nt][2 * h + 1];
                        if (EPI == 0 || EPI == 2 || EPI == 4)
                            *(float2*)(C + (size_t)r * N + c) = make_float2(v0, v1);
                        if (EPI == 3)
                            asm volatile("st.global.cs.v2.f32 [%0], {%1,%2};"
                                         :: "l"(C + (size_t)r * N + c), "f"(v0), "f"(v1)
                                         : "memory");
                        if (EPI == 1)
                            *(uint2*)((unsigned*)C + (size_t)r * N + c) =
                                make_uint2(f2tf(v0), f2tf(v1));
                        if (EPI == 2)
                            *(uint2*)(C2 + (size_t)r * N + c) =
                                make_uint2(f2tf(v0), f2tf(v1));
                    }
                }
            }
        }
    }
    if (EPI == 4) {
        // fused el/er: head-local col = (wn&1)*32 + nt*8 + (lane&3)*2 + j
        int head = (col0 >> 6) + (wn >> 1);
        const float* al = gb.AL[blockIdx.z] + head * 64;
        const float* ar = gb.AR[blockIdx.z] + head * 64;
        float alv[4][2], arv[4][2];
#pragma unroll
        for (int nt = 0; nt < 4; nt++) {
            int cc = (wn & 1) * 32 + nt * 8 + (lane & 3) * 2;
            alv[nt][0] = al[cc];     alv[nt][1] = al[cc + 1];
            arv[nt][0] = ar[cc];     arv[nt][1] = ar[cc + 1];
        }
        float* ELp = gb.EL[blockIdx.z];
        float* ERp = gb.ER[blockIdx.z];
#pragma unroll
        for (int mt = 0; mt < MT; mt++) {
            int r0 = row0 + wm * (MT * 16) + mt * 16 + (lane >> 2);
#pragma unroll
            for (int h = 0; h < 2; h++) {
                float ep = 0.f, rp = 0.f;
#pragma unroll
                for (int nt = 0; nt < 4; nt++) {
                    ep += acc[mt][nt][2 * h] * alv[nt][0] + acc[mt][nt][2 * h + 1] * alv[nt][1];
                    rp += acc[mt][nt][2 * h] * arv[nt][0] + acc[mt][nt][2 * h + 1] * arv[nt][1];
                }
                ep += __shfl_xor_sync(0xffffffffu, ep, 1);
                ep += __shfl_xor_sync(0xffffffffu, ep, 2);
                rp += __shfl_xor_sync(0xffffffffu, rp, 1);
                rp += __shfl_xor_sync(0xffffffffu, rp, 2);
                int r = r0 + h * 8;
                if ((lane & 3) == 0 && r < M) {
                    atomicAdd(&ELp[r * NHEAD + head], ep);
                    atomicAdd(&ERp[r * NHEAD + head], rp);
                }
            }
        }
    }
}

// ---------------- GAT kernels (grid.y = instance z) ----------------

__global__ void count_kernel(IP4 ed4) {
    int z = blockIdx.y;
    int i = blockIdx.x * blockDim.x + threadIdx.x;
    if (i >= NEDGE) return;
    atomicAdd(&g_cur[z][ed4.p[z][NEDGE + i]], 1);
}

__global__ void scan_kernel() {
    int z = blockIdx.x;
    int* cur = g_cur[z];
    int* off = g_off[z];
    __shared__ int part[1024];
    int t = threadIdx.x;
    int base = t * 10;
    int v[10];
    int s = 0;
#pragma unroll
    for (int j = 0; j < 10; j++) {
        int idx = base + j;
        int c = (idx < NNODES) ? cur[idx] : 0;
        v[j] = c;
        s += c;
    }
    part[t] = s;
    __syncthreads();
    for (int o = 1; o < 1024; o <<= 1) {
        int x = (t >= o) ? part[t - o] : 0;
        __syncthreads();
        part[t] += x;
        __syncthreads();
    }
    int run = (t > 0) ? part[t - 1] : 0;
#pragma unroll
    for (int j = 0; j < 10; j++) {
        int idx = base + j;
        if (idx < NNODES) {
            off[idx] = run;
            cur[idx] = run;
            run += v[j];
        }
    }
    if (t == 0) off[NNODES] = NEDGE;
}

__global__ void exp_scatter_kernel(IP4 ed4) {
    int z = blockIdx.y;
    int e = blockIdx.x * blockDim.x + threadIdx.x;
    if (e >= NEDGE) return;
    const int* ed = ed4.p[z];
    int s = ed[e], d = ed[NEDGE + e];
    float4 l0 = *(const float4*)&g_el[z][s * NHEAD];
    float4 l1 = *(const float4*)&g_el[z][s * NHEAD + 4];
    float4 r0 = *(const float4*)&g_er[z][d * NHEAD];
    float4 r1 = *(const float4*)&g_er[z][d * NHEAD + 4];
    float v[8] = {l0.x + r0.x, l0.y + r0.y, l0.z + r0.z, l0.w + r0.w,
                  l1.x + r1.x, l1.y + r1.y, l1.z + r1.z, l1.w + r1.w};
    float ex[8];
#pragma unroll
    for (int h = 0; h < 8; h++) {
        float t = v[h] > 0.f ? v[h] : 0.2f * v[h];
        ex[h] = __expf(t);
    }
    *(float4*)&g_ex[z][(size_t)e * NHEAD]     = make_float4(ex[0], ex[1], ex[2], ex[3]);
    *(float4*)&g_ex[z][(size_t)e * NHEAD + 4] = make_float4(ex[4], ex[5], ex[6], ex[7]);
#pragma unroll
    for (int h = 0; h < 8; h++) atomicAdd(&g_sm[z][d * NHEAD + h], ex[h]);
    int p = atomicAdd(&g_cur[z][d], 1);
    g_eid2[z][p] = make_int2(e, s);
}

// gather-aggregate: one warp per (dst node, 128-col strip); bias+ELU fused.
__global__ __launch_bounds__(256) void agg_kernel(FP4 bias4) {
    int z = blockIdx.y;
    int wid = blockIdx.x * 8 + (threadIdx.x >> 5);
    if (wid >= NNODES * 4) return;
    const float* bias = bias4.p[z];
    const float* __restrict__ feat = g_feat[z];
    const float* __restrict__ ex = g_ex[z];
    const int2* __restrict__ eid2 = g_eid2[z];
    int d = wid >> 2, strip = wid & 3;
    int lane = threadIdx.x & 31;
    int col = strip * 128 + lane * 4;
    int head = col >> 6;
    float rcp = 1.f / g_sm[z][d * NHEAD + head];

    float4 acc = make_float4(0.f, 0.f, 0.f, 0.f);
    int b = g_off[z][d], e_ = g_off[z][d + 1];
    if (b < e_) {
        int2 peA = eid2[b];
        int2 peB = (b + 1 < e_) ? eid2[b + 1] : peA;
        float axA = ex[(size_t)peA.x * NHEAD + head];
        for (int i = b; i < e_; i++) {
            int2 peC = (i + 2 < e_) ? eid2[i + 2] : peB;
            float axB = (i + 1 < e_) ? ex[(size_t)peB.x * NHEAD + head] : 0.f;
            float4 f = *(const float4*)(feat + (size_t)peA.y * DDIM + col);
            float a = axA * rcp;
            acc.x += f.x * a;
            acc.y += f.y * a;
            acc.z += f.z * a;
            acc.w += f.w * a;
            peA = peB; peB = peC; axA = axB;
        }
    }
    float4 bb = *(const float4*)(bias + col);
    float4 v;
    v.x = acc.x + bb.x; v.x = v.x > 0.f ? v.x : (__expf(v.x) - 1.f);
    v.y = acc.y + bb.y; v.y = v.y > 0.f ? v.y : (__expf(v.y) - 1.f);
    v.z = acc.z + bb.z; v.z = v.z > 0.f ? v.z : (__expf(v.z) - 1.f);
    v.w = acc.w + bb.w; v.w = v.w > 0.f ? v.w : (__expf(v.w) - 1.f);
    *(float4*)(g_z[z] + (size_t)d * DDIM + col) = v;
    *(uint4*)(&t_z[z][(size_t)d * DDIM + col]) =
        make_uint4(f2tf(v.x), f2tf(v.y), f2tf(v.z), f2tf(v.w));
}

// ---------------- semantic attention ----------------

__global__ void sem_score_kernel(FP4 b14, FP4 W24) {
    int z = blockIdx.y;
    int w = blockIdx.x * 8 + (threadIdx.x >> 5);
    int lane = threadIdx.x & 31;
    if (w >= NNODES) return;
    const float* b1 = b14.p[z];
    const float* W2 = W24.p[z];
    float t = 0.f;
#pragma unroll
    for (int q = 0; q < 4; q++) {
        int j = lane + 32 * q;
        t += tanhf(g_sc[z][(size_t)w * SEMH + j] + b1[j]) * W2[j];
    }
#pragma unroll
    for (int o = 16; o > 0; o >>= 1) t += __shfl_down_sync(0xffffffffu, t, o);
    if (lane == 0) g_w[z][w] = t;
}

__global__ void fuse_kernel() {
    int b = blockIdx.y;
    int i = blockIdx.x * blockDim.x + threadIdx.x;
    if (i >= NNODES * DDIM) return;
    int n = i >> 9;
    float a = g_w[2 * b][n], c = g_w[2 * b + 1][n];
    float m = fmaxf(a, c);
    float ea = __expf(a - m), eb = __expf(c - m);
    float be = ea / (ea + eb);
    t_fu[b][i] = f2tf(be * g_z[2 * b][i] + (1.f - be) * g_z[2 * b + 1][i]);
}

// ---------------- host orchestration ----------------

extern "C" void kernel_launch(void* const* d_in, const int* in_sizes, int n_in,
                              void* d_out, int out_size) {
    float *p_feat[4], *p_sc[4], *p_el[4], *p_er[4];
    unsigned *p_tx[2], *p_twhw[2], *p_tfc[2], *p_tpred[2], *p_tW1[2];
    unsigned *p_tW[4], *p_tz[4], *p_tfu[2], *p_th[2];
    float *p_el0, *p_er0, *p_sm0;
    {
        float* base;
        cudaGetSymbolAddress((void**)&base, g_feat);
        for (int z = 0; z < 4; z++) p_feat[z] = base + (size_t)z * NNODES * DDIM;
        cudaGetSymbolAddress((void**)&base, g_sc);
        for (int z = 0; z < 4; z++) p_sc[z] = base + (size_t)z * NNODES * SEMH;
        cudaGetSymbolAddress((void**)&p_el0, g_el);
        for (int z = 0; z < 4; z++) p_el[z] = p_el0 + (size_t)z * NNODES * NHEAD;
        cudaGetSymbolAddress((void**)&p_er0, g_er);
        for (int z = 0; z < 4; z++) p_er[z] = p_er0 + (size_t)z * NNODES * NHEAD;
        cudaGetSymbolAddress((void**)&p_sm0, g_sm);
        unsigned* ub;
        cudaGetSymbolAddress((void**)&ub, t_x);
        for (int b = 0; b < 2; b++) p_tx[b] = ub + (size_t)b * NNODES * FDIM;
        cudaGetSymbolAddress((void**)&ub, t_whw);
        for (int b = 0; b < 2; b++) p_twhw[b] = ub + (size_t)b * FDIM * FDIM;
        cudaGetSymbolAddress((void**)&ub, t_fc);
        for (int b = 0; b < 2; b++) p_tfc[b] = ub + (size_t)b * 2 * FDIM * DDIM;
        cudaGetSymbolAddress((void**)&ub, t_pred);
        for (int b = 0; b < 2; b++) p_tpred[b] = ub + (size_t)b * DDIM * OSZ;
        cudaGetSymbolAddress((void**)&ub, t_W1);
        for (int b = 0; b < 2; b++) p_tW1[b] = ub + (size_t)b * DDIM * SEMH;
        cudaGetSymbolAddress((void**)&ub, t_W);
        for (int z = 0; z < 4; z++) p_tW[z] = ub + (size_t)z * FDIM * DDIM;
        cudaGetSymbolAddress((void**)&ub, t_z);
        for (int z = 0; z < 4; z++) p_tz[z] = ub + (size_t)z * NNODES * DDIM;
        cudaGetSymbolAddress((void**)&ub, t_fu);
        for (int b = 0; b < 2; b++) p_tfu[b] = ub + (size_t)b * NNODES * DDIM;
        cudaGetSymbolAddress((void**)&ub, t_h);
        for (int b = 0; b < 2; b++) p_th[b] = ub + (size_t)b * NNODES * OSZ;
    }
    int* p_cur;
    cudaGetSymbolAddress((void**)&p_cur, g_cur);

    const float* hx = (const float*)d_in[0];
    const float* tx = (const float*)d_in[1];
    const float* w_h[2]  = {(const float*)d_in[2],  (const float*)d_in[11]};
    const float* fc[2]   = {(const float*)d_in[3],  (const float*)d_in[12]};
    const float* al[2]   = {(const float*)d_in[4],  (const float*)d_in[13]};
    const float* ar[2]   = {(const float*)d_in[5],  (const float*)d_in[14]};
    const float* bias[2] = {(const float*)d_in[6],  (const float*)d_in[15]};
    const float* W1[2]   = {(const float*)d_in[7],  (const float*)d_in[16]};
    const float* b1[2]   = {(const float*)d_in[8],  (const float*)d_in[17]};
    const float* W2[2]   = {(const float*)d_in[9],  (const float*)d_in[18]};
    const float* pred[2] = {(const float*)d_in[10], (const float*)d_in[19]};

    IP4 ed4 = {{(const int*)d_in[20], (const int*)d_in[21],
                (const int*)d_in[22], (const int*)d_in[23]}};
    FP4 bias4 = {{bias[0], bias[0] + DDIM, bias[1], bias[1] + DDIM}};
    FP4 b14   = {{b1[0], b1[0], b1[1], b1[1]}};
    FP4 W24   = {{W2[0], W2[0], W2[1], W2[1]}};

    float* out  = (float*)d_out;
    float* h1   = out;
    float* h2   = out + (size_t)NNODES * OSZ;
    float* prod = out + (size_t)2 * NNODES * OSZ;

    const int SM_NN4 = 4 * (128 * 20 + 16 * 136) * 4;   // 75776
    const int SM_NN2 = 4 * (64 * 20 + 16 * 136) * 4;    // 55296
    const int SM_NT  = 4 * (128 * 20 + 128 * 20) * 4;   // 81920
    cudaFuncSetAttribute(mma_gemm_async<4, false, 1>,
                         cudaFuncAttributeMaxDynamicSharedMemorySize, SM_NN4);
    cudaFuncSetAttribute(mma_gemm_async<4, false, 4>,
                         cudaFuncAttributeMaxDynamicSharedMemorySize, SM_NN4);
    cudaFuncSetAttribute(mma_gemm_async<2, false, 0>,
                         cudaFuncAttributeMaxDynamicSharedMemorySize, SM_NN2);
    cudaFuncSetAttribute(mma_gemm_async<2, false, 2>,
                         cudaFuncAttributeMaxDynamicSharedMemorySize, SM_NN2);
    cudaFuncSetAttribute(mma_gemm_async<4, true, 3>,
                         cudaFuncAttributeMaxDynamicSharedMemorySize, SM_NT);

    // 0) clear accumulators, CSR offsets, one-shot tf32 conversion
    cudaMemsetAsync(p_cur, 0, 4 * NNODES * sizeof(int), 0);
    cudaMemsetAsync(p_el0, 0, 4 * NNODES * NHEAD * sizeof(float), 0);
    cudaMemsetAsync(p_er0, 0, 4 * NNODES * NHEAD * sizeof(float), 0);
    cudaMemsetAsync(p_sm0, 0, 4 * NNODES * NHEAD * sizeof(float), 0);
    count_kernel<<<dim3((NEDGE + 255) / 256, 4), 256>>>(ed4);
    scan_kernel<<<4, 1024>>>();
    {
        CVT c = {};
        c.src[0] = hx;      c.dst[0] = p_tx[0];    c.n4[0] = NNODES * FDIM / 4;
        c.src[1] = tx;      c.dst[1] = p_tx[1];    c.n4[1] = NNODES * FDIM / 4;
        c.src[2] = w_h[0];  c.dst[2] = p_twhw[0];  c.n4[2] = FDIM * FDIM / 4;
        c.src[3] = w_h[1];  c.dst[3] = p_twhw[1];  c.n4[3] = FDIM * FDIM / 4;
        c.src[4] = fc[0];   c.dst[4] = p_tfc[0];   c.n4[4] = 2 * FDIM * DDIM / 4;
        c.src[5] = fc[1];   c.dst[5] = p_tfc[1];   c.n4[5] = 2 * FDIM * DDIM / 4;
        c.src[6] = pred[0]; c.dst[6] = p_tpred[0]; c.n4[6] = DDIM * OSZ / 4;
        c.src[7] = pred[1]; c.dst[7] = p_tpred[1]; c.n4[7] = DDIM * OSZ / 4;
        c.src[8] = W1[0];   c.dst[8] = p_tW1[0];   c.n4[8] = DDIM * SEMH / 4;
        c.src[9] = W1[1];   c.dst[9] = p_tW1[1];   c.n4[9] = DDIM * SEMH / 4;
        cvt_kernel<<<dim3(640, 10), 256>>>(c);
    }

    // 1) combined weights W[z] = w_h[b] @ fc[b][m]
    {
        GB gb = {};
        for (int z = 0; z < 4; z++) {
            gb.A[z] = p_twhw[z >> 1];
            gb.B[z] = p_tfc[z >> 1] + (size_t)(z & 1) * FDIM * DDIM;
            gb.C[z] = p_tW[z];
        }
        dim3 g(DDIM / 128, FDIM / 128, 4);
        mma_gemm_async<4, false, 1><<<g, 256, SM_NN4>>>(gb, FDIM, DDIM, FDIM);
    }
    // 2) feat = x @ W  (batched x4, fused el/er epilogue)
    {
        GB gb = {};
        for (int z = 0; z < 4; z++) {
            gb.A[z] = p_tx[z >> 1];
            gb.B[z] = p_tW[z];
            gb.C[z] = p_feat[z];
            gb.AL[z] = (z & 2) ? (al[1] + (z & 1) * NHEAD * 64) : (al[0] + (z & 1) * NHEAD * 64);
            gb.AR[z] = (z & 2) ? (ar[1] + (z & 1) * NHEAD * 64) : (ar[0] + (z & 1) * NHEAD * 64);
            gb.EL[z] = p_el[z];
            gb.ER[z] = p_er[z];
        }
        dim3 g(DDIM / 128, (NNODES + 127) / 128, 4);
        mma_gemm_async<4, false, 4><<<g, 256, SM_NN4>>>(gb, NNODES, DDIM, FDIM);
    }
    // 3) fused exp/sum/scatter + aggregate (x4)
    exp_scatter_kernel<<<dim3((NEDGE + 255) / 256, 4), 256>>>(ed4);
    agg_kernel<<<dim3((NNODES * 4 + 7) / 8, 4), 256>>>(bias4);

    // 4) semantic attention (async GEMM on tf32 z) + fuse (x2, tf32-out)
    {
        GB gb = {};
        for (int z = 0; z < 4; z++) {
            gb.A[z] = p_tz[z];
            gb.B[z] = p_tW1[z >> 1];
            gb.C[z] = p_sc[z];
        }
        dim3 g(1, (NNODES + 63) / 64, 4);
        mma_gemm_async<2, false, 0><<<g, 256, SM_NN2>>>(gb, NNODES, SEMH, DDIM);
    }
    sem_score_kernel<<<dim3((NNODES + 7) / 8, 4), 256>>>(b14, W24);
    fuse_kernel<<<dim3((NNODES * DDIM + 255) / 256, 2), 256>>>();

    // 5) prediction heads (batched x2, dual f32 + tf32 epilogue)
    {
        GB gb = {};
        gb.A[0] = p_tfu[0]; gb.B[0] = p_tpred[0]; gb.C[0] = h1; gb.C2[0] = p_th[0];
        gb.A[1] = p_tfu[1]; gb.B[1] = p_tpred[1]; gb.C[1] = h2; gb.C2[1] = p_th[1];
        dim3 g(1, (NNODES + 63) / 64, 2);
        mma_gemm_async<2, false, 2><<<g, 256, SM_NN2>>>(gb, NNODES, OSZ, DDIM);
    }
    // 6) prod = h1 @ h2^T (tf32 copies, streaming stores, ldmatrix A+B)
    {
        GB gb = {};
        gb.A[0] = p_th[0]; gb.B[0] = p_th[1]; gb.C[0] = prod;
        dim3 g((NNODES + 127) / 128, (NNODES + 127) / 128, 1);
        mma_gemm_async<4, true, 3><<<g, 256, SM_NT>>>(gb, NNODES, NNODES, OSZ);
    }
}

// round 13
// speedup vs baseline: 4.4111x; 1.0770x over previous
#include <cuda_runtime.h>
#include <cstdint>

#define NNODES 10000
#define FDIM   256
#define DDIM   512
#define NEDGE  160000
#define NHEAD  8
#define SEMH   128
#define OSZ    64

// ---------------- scratch (static device globals; no allocation) ----------------
__device__ float g_feat[4][NNODES * DDIM];
__device__ float g_z   [4][NNODES * DDIM];
__device__ float g_el  [4][NNODES * NHEAD];
__device__ float g_er  [4][NNODES * NHEAD];
__device__ float g_ex  [4][NEDGE * NHEAD];
__device__ float g_w   [4][NNODES];
__device__ int   g_off [4][NNODES + 1];
__device__ int   g_cur [4][NNODES];
__device__ int2  g_eid2[4][NEDGE];
// tf32-at-rest operands (bits stored as unsigned)
__device__ unsigned t_x   [2][NNODES * FDIM];
__device__ unsigned t_whw [2][FDIM * FDIM];
__device__ unsigned t_fc  [2][2 * FDIM * DDIM];
__device__ unsigned t_pred[2][DDIM * OSZ];
__device__ unsigned t_W1  [2][DDIM * SEMH];
__device__ unsigned t_W   [4][FDIM * DDIM];
__device__ unsigned t_z   [4][NNODES * DDIM];
__device__ unsigned t_fu  [2][NNODES * DDIM];
__device__ unsigned t_h   [2][NNODES * OSZ];

struct GB {
    const void* A[4]; const void* B[4]; void* C[4]; void* C2[4];
    const float* AL[4]; const float* AR[4]; float* EL[4]; float* ER[4];
    const float* B1[4]; const float* W2p[4]; float* WO[4];
};
struct IP4  { const int*   p[4]; };
struct FP4  { const float* p[4]; };
struct CVT  { const float* src[10]; unsigned* dst[10]; int n4[10]; };

__device__ __forceinline__ unsigned f2tf(float f) {
    unsigned r;
    asm("cvt.rna.tf32.f32 %0, %1;" : "=r"(r) : "f"(f));
    return r;
}

// ---------------- one-shot f32 -> tf32 conversion ----------
__global__ void cvt_kernel(CVT c) {
    int seg = blockIdx.y;
    int n4 = c.n4[seg];
    const float4* s = (const float4*)c.src[seg];
    uint4* d = (uint4*)c.dst[seg];
    for (int i = blockIdx.x * 256 + threadIdx.x; i < n4; i += gridDim.x * 256) {
        float4 v = s[i];
        d[i] = make_uint4(f2tf(v.x), f2tf(v.y), f2tf(v.z), f2tf(v.w));
    }
}

// ---------------- async tf32 MMA GEMM: cp.async 4-stage, z-batched -----------
// Block tile BM(=32*MT) x 128, K-tile 16. 256 threads = 8 warps 2(m) x 4(n).
// Pitched raw smem tiles; A via ldmatrix.x4 (conflict-free at pitch 20);
// B via ldmatrix.x4 (NT) or scalar LDS (NN).
// EPI: 0 f32 C; 1 tf32 C; 2 f32 C + tf32 C2; 3 f32 streaming;
//      4 f32 C + fused el/er; 5 fused semantic score (no C store).

template<int MT, bool TRANSB, int EPI>
__global__ __launch_bounds__(256, 2) void mma_gemm_async(GB gb, int M, int N, int K) {
    constexpr int S  = 4;
    constexpr int BM = 32 * MT;
    constexpr int PA = 20;
    constexpr int PB = TRANSB ? 20 : 136;
    constexpr int AW = BM * PA;
    constexpr int BW = TRANSB ? 128 * PB : 16 * PB;
    constexpr int AQ = BM / 64;
    extern __shared__ unsigned smem[];

    const unsigned* __restrict__ A = (const unsigned*)gb.A[blockIdx.z];
    const unsigned* __restrict__ B = (const unsigned*)gb.B[blockIdx.z];
    float* C = (float*)gb.C[blockIdx.z];
    unsigned* C2 = (unsigned*)gb.C2[blockIdx.z];

    int tid = threadIdx.x, warp = tid >> 5, lane = tid & 31;
    int wm = warp >> 2, wn = warp & 3;
    int row0 = blockIdx.y * BM, col0 = blockIdx.x * 128;
    int nk = K >> 4;
    unsigned sbase = (unsigned)__cvta_generic_to_shared(smem);

    auto issue = [&](int t) {
        int k0 = t * 16, buf = t & (S - 1);
#pragma unroll
        for (int j = 0; j < AQ; j++) {
            int i = tid + j * 256;
            int r = i >> 2, c4 = i & 3;
            int gr = row0 + r;
            int sz = 16;
            if (gr >= M) { sz = 0; gr = row0; }
            unsigned sd = sbase + ((buf * AW + r * PA + c4 * 4) << 2);
            asm volatile("cp.async.cg.shared.global [%0], [%1], 16, %2;"
                         :: "r"(sd), "l"(A + (size_t)gr * K + k0 + c4 * 4), "r"(sz));
        }
#pragma unroll
        for (int j = 0; j < 2; j++) {
            int i = tid + j * 256;
            const unsigned* src;
            int dstw, sz = 16;
            if (!TRANSB) {
                int k = i >> 5, c4 = i & 31;
                int gc = col0 + c4 * 4;
                if (gc >= N) { sz = 0; gc = col0; }
                src = B + (size_t)(k0 + k) * N + gc;
                dstw = k * PB + c4 * 4;
            } else {
                int n = i >> 2, c4 = i & 3;
                int gn = col0 + n;
                if (gn >= N) { sz = 0; gn = col0; }
                src = B + (size_t)gn * K + k0 + c4 * 4;
                dstw = n * PB + c4 * 4;
            }
            unsigned sd = sbase + ((S * AW + buf * BW + dstw) << 2);
            asm volatile("cp.async.cg.shared.global [%0], [%1], 16, %2;"
                         :: "r"(sd), "l"(src), "r"(sz));
        }
    };

    float acc[MT][4][4];
#pragma unroll
    for (int i = 0; i < MT; i++)
#pragma unroll
        for (int j = 0; j < 4; j++)
#pragma unroll
            for (int q = 0; q < 4; q++) acc[i][j][q] = 0.f;

#pragma unroll
    for (int t = 0; t < S - 1; t++) {
        if (t < nk) issue(t);
        asm volatile("cp.async.commit_group;");
    }

    const unsigned aLdm = ((wm * MT * 16 + (lane & 15)) * PA + (lane >> 4) * 4) << 2;
    const unsigned bLdm = TRANSB
        ? (((wn * 32 + (lane & 7) + ((lane >> 4) & 1) * 8) * PB + ((lane >> 3) & 1) * 4) << 2)
        : 0u;
    const int bB0 = (lane & 3) * PB + wn * 32 + (lane >> 2);

    for (int t = 0; t < nk; t++) {
        int buf = t & (S - 1);
        asm volatile("cp.async.wait_group %0;" :: "n"(S - 2));
        __syncthreads();
        if (t + S - 1 < nk) issue(t + S - 1);
        asm volatile("cp.async.commit_group;");

#pragma unroll
        for (int ks = 0; ks < 2; ks++) {
            unsigned af[MT][4];
            unsigned bf[4][2];
            unsigned aAddr = sbase + ((buf * AW) << 2) + aLdm + ((ks * 8) << 2);
#pragma unroll
            for (int mt = 0; mt < MT; mt++) {
                asm volatile("ldmatrix.sync.aligned.m8n8.x4.shared.b16 "
                             "{%0,%1,%2,%3}, [%4];"
                             : "=r"(af[mt][0]), "=r"(af[mt][1]),
                               "=r"(af[mt][2]), "=r"(af[mt][3])
                             : "r"(aAddr + ((mt * 16 * PA) << 2)));
            }
            if (TRANSB) {
                unsigned bAddr = sbase + ((S * AW + buf * BW) << 2) + bLdm + ((ks * 8) << 2);
#pragma unroll
                for (int p = 0; p < 2; p++) {
                    asm volatile("ldmatrix.sync.aligned.m8n8.x4.shared.b16 "
                                 "{%0,%1,%2,%3}, [%4];"
                                 : "=r"(bf[2 * p][0]), "=r"(bf[2 * p][1]),
                                   "=r"(bf[2 * p + 1][0]), "=r"(bf[2 * p + 1][1])
                                 : "r"(bAddr + ((p * 16 * PB) << 2)));
                }
            } else {
                const unsigned* bp = smem + S * AW + buf * BW + bB0;
#pragma unroll
                for (int nt = 0; nt < 4; nt++) {
                    const unsigned* p = bp + ks * 8 * PB + nt * 8;
                    bf[nt][0] = p[0];
                    bf[nt][1] = p[4 * PB];
                }
            }
#pragma unroll
            for (int mt = 0; mt < MT; mt++)
#pragma unroll
                for (int nt = 0; nt < 4; nt++) {
                    asm volatile(
                        "mma.sync.aligned.m16n8k8.row.col.f32.tf32.tf32.f32 "
                        "{%0,%1,%2,%3}, {%4,%5,%6,%7}, {%8,%9}, {%0,%1,%2,%3};"
                        : "+f"(acc[mt][nt][0]), "+f"(acc[mt][nt][1]),
                          "+f"(acc[mt][nt][2]), "+f"(acc[mt][nt][3])
                        : "r"(af[mt][0]), "r"(af[mt][1]), "r"(af[mt][2]), "r"(af[mt][3]),
                          "r"(bf[nt][0]), "r"(bf[nt][1]));
                }
        }
    }

    // ---------------- epilogue ----------------
    if (EPI != 5) {
#pragma unroll
        for (int mt = 0; mt < MT; mt++) {
            int r0 = row0 + wm * (MT * 16) + mt * 16 + (lane >> 2);
#pragma unroll
            for (int nt = 0; nt < 4; nt++) {
                int c = col0 + wn * 32 + nt * 8 + (lane & 3) * 2;
                if (c < N) {
#pragma unroll
                    for (int h = 0; h < 2; h++) {
                        int r = r0 + h * 8;
                        if (r < M) {
                            float v0 = acc[mt][nt][2 * h], v1 = acc[mt][nt][2 * h + 1];
                            if (EPI == 0 || EPI == 2 || EPI == 4)
                                *(float2*)(C + (size_t)r * N + c) = make_float2(v0, v1);
                            if (EPI == 3)
                                asm volatile("st.global.cs.v2.f32 [%0], {%1,%2};"
                                             :: "l"(C + (size_t)r * N + c), "f"(v0), "f"(v1)
                                             : "memory");
                            if (EPI == 1)
                                *(uint2*)((unsigned*)C + (size_t)r * N + c) =
                                    make_uint2(f2tf(v0), f2tf(v1));
                            if (EPI == 2)
                                *(uint2*)(C2 + (size_t)r * N + c) =
                                    make_uint2(f2tf(v0), f2tf(v1));
                        }
                    }
                }
            }
        }
    }
    if (EPI == 4) {
        int head = (col0 >> 6) + (wn >> 1);
        const float* al = gb.AL[blockIdx.z] + head * 64;
        const float* ar = gb.AR[blockIdx.z] + head * 64;
        float alv[4][2], arv[4][2];
#pragma unroll
        for (int nt = 0; nt < 4; nt++) {
            int cc = (wn & 1) * 32 + nt * 8 + (lane & 3) * 2;
            alv[nt][0] = al[cc];     alv[nt][1] = al[cc + 1];
            arv[nt][0] = ar[cc];     arv[nt][1] = ar[cc + 1];
        }
        float* ELp = gb.EL[blockIdx.z];
        float* ERp = gb.ER[blockIdx.z];
#pragma unroll
        for (int mt = 0; mt < MT; mt++) {
            int r0 = row0 + wm * (MT * 16) + mt * 16 + (lane >> 2);
#pragma unroll
            for (int h = 0; h < 2; h++) {
                float ep = 0.f, rp = 0.f;
#pragma unroll
                for (int nt = 0; nt < 4; nt++) {
                    ep += acc[mt][nt][2 * h] * alv[nt][0] + acc[mt][nt][2 * h + 1] * alv[nt][1];
                    rp += acc[mt][nt][2 * h] * arv[nt][0] + acc[mt][nt][2 * h + 1] * arv[nt][1];
                }
                ep += __shfl_xor_sync(0xffffffffu, ep, 1);
                ep += __shfl_xor_sync(0xffffffffu, ep, 2);
                rp += __shfl_xor_sync(0xffffffffu, rp, 1);
                rp += __shfl_xor_sync(0xffffffffu, rp, 2);
                int r = r0 + h * 8;
                if ((lane & 3) == 0 && r < M) {
                    atomicAdd(&ELp[r * NHEAD + head], ep);
                    atomicAdd(&ERp[r * NHEAD + head], rp);
                }
            }
        }
    }
    if (EPI == 5) {
        // fused semantic score: w[r] = sum_c tanh(sc[r,c]+b1[c])*W2[c]; N==128.
        const float* b1 = gb.B1[blockIdx.z];
        const float* W2 = gb.W2p[blockIdx.z];
        float b1v[4][2], w2v[4][2];
#pragma unroll
        for (int nt = 0; nt < 4; nt++) {
            int cc = wn * 32 + nt * 8 + (lane & 3) * 2;
            b1v[nt][0] = b1[cc];     b1v[nt][1] = b1[cc + 1];
            w2v[nt][0] = W2[cc];     w2v[nt][1] = W2[cc + 1];
        }
        float* wout = gb.WO[blockIdx.z];
#pragma unroll
        for (int mt = 0; mt < MT; mt++) {
            int r0 = row0 + wm * (MT * 16) + mt * 16 + (lane >> 2);
#pragma unroll
            for (int h = 0; h < 2; h++) {
                float s = 0.f;
#pragma unroll
                for (int nt = 0; nt < 4; nt++) {
                    s += tanhf(acc[mt][nt][2 * h]     + b1v[nt][0]) * w2v[nt][0];
                    s += tanhf(acc[mt][nt][2 * h + 1] + b1v[nt][1]) * w2v[nt][1];
                }
                s += __shfl_xor_sync(0xffffffffu, s, 1);
                s += __shfl_xor_sync(0xffffffffu, s, 2);
                int r = r0 + h * 8;
                if ((lane & 3) == 0 && r < M) atomicAdd(&wout[r], s);
            }
        }
    }
}

// ---------------- GAT kernels (grid.y = instance z) ----------------

__global__ void count_kernel(IP4 ed4) {
    int z = blockIdx.y;
    int i = blockIdx.x * blockDim.x + threadIdx.x;
    if (i >= NEDGE) return;
    atomicAdd(&g_cur[z][ed4.p[z][NEDGE + i]], 1);
}

__global__ void scan_kernel() {
    int z = blockIdx.x;
    int* cur = g_cur[z];
    int* off = g_off[z];
    __shared__ int part[1024];
    int t = threadIdx.x;
    int base = t * 10;
    int v[10];
    int s = 0;
#pragma unroll
    for (int j = 0; j < 10; j++) {
        int idx = base + j;
        int c = (idx < NNODES) ? cur[idx] : 0;
        v[j] = c;
        s += c;
    }
    part[t] = s;
    __syncthreads();
    for (int o = 1; o < 1024; o <<= 1) {
        int x = (t >= o) ? part[t - o] : 0;
        __syncthreads();
        part[t] += x;
        __syncthreads();
    }
    int run = (t > 0) ? part[t - 1] : 0;
#pragma unroll
    for (int j = 0; j < 10; j++) {
        int idx = base + j;
        if (idx < NNODES) {
            off[idx] = run;
            cur[idx] = run;
            run += v[j];
        }
    }
    if (t == 0) off[NNODES] = NEDGE;
}

// leaky_relu + exp + CSR scatter (softmax sum now computed inside agg)
__global__ void exp_scatter_kernel(IP4 ed4) {
    int z = blockIdx.y;
    int e = blockIdx.x * blockDim.x + threadIdx.x;
    if (e >= NEDGE) return;
    const int* ed = ed4.p[z];
    int s = ed[e], d = ed[NEDGE + e];
    float4 l0 = *(const float4*)&g_el[z][s * NHEAD];
    float4 l1 = *(const float4*)&g_el[z][s * NHEAD + 4];
    float4 r0 = *(const float4*)&g_er[z][d * NHEAD];
    float4 r1 = *(const float4*)&g_er[z][d * NHEAD + 4];
    float v[8] = {l0.x + r0.x, l0.y + r0.y, l0.z + r0.z, l0.w + r0.w,
                  l1.x + r1.x, l1.y + r1.y, l1.z + r1.z, l1.w + r1.w};
    float ex[8];
#pragma unroll
    for (int h = 0; h < 8; h++) {
        float t = v[h] > 0.f ? v[h] : 0.2f * v[h];
        ex[h] = __expf(t);
    }
    *(float4*)&g_ex[z][(size_t)e * NHEAD]     = make_float4(ex[0], ex[1], ex[2], ex[3]);
    *(float4*)&g_ex[z][(size_t)e * NHEAD + 4] = make_float4(ex[4], ex[5], ex[6], ex[7]);
    int p = atomicAdd(&g_cur[z][d], 1);
    g_eid2[z][p] = make_int2(e, s);
}

// gather-aggregate: one warp per (dst node, 128-col strip); softmax sum
// accumulated in-loop, normalized at the end; bias+ELU fused; dual epilogue.
__global__ __launch_bounds__(256) void agg_kernel(FP4 bias4) {
    int z = blockIdx.y;
    int wid = blockIdx.x * 8 + (threadIdx.x >> 5);
    if (wid >= NNODES * 4) return;
    const float* bias = bias4.p[z];
    const float* __restrict__ feat = g_feat[z];
    const float* __restrict__ ex = g_ex[z];
    const int2* __restrict__ eid2 = g_eid2[z];
    int d = wid >> 2, strip = wid & 3;
    int lane = threadIdx.x & 31;
    int col = strip * 128 + lane * 4;
    int head = col >> 6;

    float4 acc = make_float4(0.f, 0.f, 0.f, 0.f);
    float sum_ax = 0.f;
    int b = g_off[z][d], e_ = g_off[z][d + 1];
    if (b < e_) {
        int2 peA = eid2[b];
        int2 peB = (b + 1 < e_) ? eid2[b + 1] : peA;
        float axA = ex[(size_t)peA.x * NHEAD + head];
        for (int i = b; i < e_; i++) {
            int2 peC = (i + 2 < e_) ? eid2[i + 2] : peB;
            float axB = (i + 1 < e_) ? ex[(size_t)peB.x * NHEAD + head] : 0.f;
            float4 f = *(const float4*)(feat + (size_t)peA.y * DDIM + col);
            acc.x += f.x * axA;
            acc.y += f.y * axA;
            acc.z += f.z * axA;
            acc.w += f.w * axA;
            sum_ax += axA;
            peA = peB; peB = peC; axA = axB;
        }
        float rcp = 1.f / sum_ax;
        acc.x *= rcp; acc.y *= rcp; acc.z *= rcp; acc.w *= rcp;
    }
    float4 bb = *(const float4*)(bias + col);
    float4 v;
    v.x = acc.x + bb.x; v.x = v.x > 0.f ? v.x : (__expf(v.x) - 1.f);
    v.y = acc.y + bb.y; v.y = v.y > 0.f ? v.y : (__expf(v.y) - 1.f);
    v.z = acc.z + bb.z; v.z = v.z > 0.f ? v.z : (__expf(v.z) - 1.f);
    v.w = acc.w + bb.w; v.w = v.w > 0.f ? v.w : (__expf(v.w) - 1.f);
    *(float4*)(g_z[z] + (size_t)d * DDIM + col) = v;
    *(uint4*)(&t_z[z][(size_t)d * DDIM + col]) =
        make_uint4(f2tf(v.x), f2tf(v.y), f2tf(v.z), f2tf(v.w));
}

// ---------------- fuse ----------------

__global__ void fuse_kernel() {
    int b = blockIdx.y;
    int i = blockIdx.x * blockDim.x + threadIdx.x;
    if (i >= NNODES * DDIM) return;
    int n = i >> 9;
    float a = g_w[2 * b][n], c = g_w[2 * b + 1][n];
    float m = fmaxf(a, c);
    float ea = __expf(a - m), eb = __expf(c - m);
    float be = ea / (ea + eb);
    t_fu[b][i] = f2tf(be * g_z[2 * b][i] + (1.f - be) * g_z[2 * b + 1][i]);
}

// ---------------- host orchestration ----------------

extern "C" void kernel_launch(void* const* d_in, const int* in_sizes, int n_in,
                              void* d_out, int out_size) {
    float *p_feat[4], *p_el[4], *p_er[4], *p_w[4];
    unsigned *p_tx[2], *p_twhw[2], *p_tfc[2], *p_tpred[2], *p_tW1[2];
    unsigned *p_tW[4], *p_tz[4], *p_tfu[2], *p_th[2];
    float *p_el0, *p_er0, *p_w0;
    {
        float* base;
        cudaGetSymbolAddress((void**)&base, g_feat);
        for (int z = 0; z < 4; z++) p_feat[z] = base + (size_t)z * NNODES * DDIM;
        cudaGetSymbolAddress((void**)&p_el0, g_el);
        for (int z = 0; z < 4; z++) p_el[z] = p_el0 + (size_t)z * NNODES * NHEAD;
        cudaGetSymbolAddress((void**)&p_er0, g_er);
        for (int z = 0; z < 4; z++) p_er[z] = p_er0 + (size_t)z * NNODES * NHEAD;
        cudaGetSymbolAddress((void**)&p_w0, g_w);
        for (int z = 0; z < 4; z++) p_w[z] = p_w0 + (size_t)z * NNODES;
        unsigned* ub;
        cudaGetSymbolAddress((void**)&ub, t_x);
        for (int b = 0; b < 2; b++) p_tx[b] = ub + (size_t)b * NNODES * FDIM;
        cudaGetSymbolAddress((void**)&ub, t_whw);
        for (int b = 0; b < 2; b++) p_twhw[b] = ub + (size_t)b * FDIM * FDIM;
        cudaGetSymbolAddress((void**)&ub, t_fc);
        for (int b = 0; b < 2; b++) p_tfc[b] = ub + (size_t)b * 2 * FDIM * DDIM;
        cudaGetSymbolAddress((void**)&ub, t_pred);
        for (int b = 0; b < 2; b++) p_tpred[b] = ub + (size_t)b * DDIM * OSZ;
        cudaGetSymbolAddress((void**)&ub, t_W1);
        for (int b = 0; b < 2; b++) p_tW1[b] = ub + (size_t)b * DDIM * SEMH;
        cudaGetSymbolAddress((void**)&ub, t_W);
        for (int z = 0; z < 4; z++) p_tW[z] = ub + (size_t)z * FDIM * DDIM;
        cudaGetSymbolAddress((void**)&ub, t_z);
        for (int z = 0; z < 4; z++) p_tz[z] = ub + (size_t)z * NNODES * DDIM;
        cudaGetSymbolAddress((void**)&ub, t_fu);
        for (int b = 0; b < 2; b++) p_tfu[b] = ub + (size_t)b * NNODES * DDIM;
        cudaGetSymbolAddress((void**)&ub, t_h);
        for (int b = 0; b < 2; b++) p_th[b] = ub + (size_t)b * NNODES * OSZ;
    }
    int* p_cur;
    cudaGetSymbolAddress((void**)&p_cur, g_cur);

    const float* hx = (const float*)d_in[0];
    const float* tx = (const float*)d_in[1];
    const float* w_h[2]  = {(const float*)d_in[2],  (const float*)d_in[11]};
    const float* fc[2]   = {(const float*)d_in[3],  (const float*)d_in[12]};
    const float* al[2]   = {(const float*)d_in[4],  (const float*)d_in[13]};
    const float* ar[2]   = {(const float*)d_in[5],  (const float*)d_in[14]};
    const float* bias[2] = {(const float*)d_in[6],  (const float*)d_in[15]};
    const float* W1[2]   = {(const float*)d_in[7],  (const float*)d_in[16]};
    const float* b1[2]   = {(const float*)d_in[8],  (const float*)d_in[17]};
    const float* W2[2]   = {(const float*)d_in[9],  (const float*)d_in[18]};
    const float* pred[2] = {(const float*)d_in[10], (const float*)d_in[19]};

    IP4 ed4 = {{(const int*)d_in[20], (const int*)d_in[21],
                (const int*)d_in[22], (const int*)d_in[23]}};
    FP4 bias4 = {{bias[0], bias[0] + DDIM, bias[1], bias[1] + DDIM}};

    float* out  = (float*)d_out;
    float* h1   = out;
    float* h2   = out + (size_t)NNODES * OSZ;
    float* prod = out + (size_t)2 * NNODES * OSZ;

    const int SM_NN4 = 4 * (128 * 20 + 16 * 136) * 4;   // 75776
    const int SM_NN2 = 4 * (64 * 20 + 16 * 136) * 4;    // 55296
    const int SM_NT  = 4 * (128 * 20 + 128 * 20) * 4;   // 81920
    cudaFuncSetAttribute(mma_gemm_async<4, false, 1>,
                         cudaFuncAttributeMaxDynamicSharedMemorySize, SM_NN4);
    cudaFuncSetAttribute(mma_gemm_async<4, false, 4>,
                         cudaFuncAttributeMaxDynamicSharedMemorySize, SM_NN4);
    cudaFuncSetAttribute(mma_gemm_async<2, false, 5>,
                         cudaFuncAttributeMaxDynamicSharedMemorySize, SM_NN2);
    cudaFuncSetAttribute(mma_gemm_async<2, false, 2>,
                         cudaFuncAttributeMaxDynamicSharedMemorySize, SM_NN2);
    cudaFuncSetAttribute(mma_gemm_async<4, true, 3>,
                         cudaFuncAttributeMaxDynamicSharedMemorySize, SM_NT);

    // 0) clear accumulators, CSR offsets, one-shot tf32 conversion
    cudaMemsetAsync(p_cur, 0, 4 * NNODES * sizeof(int), 0);
    cudaMemsetAsync(p_el0, 0, 4 * NNODES * NHEAD * sizeof(float), 0);
    cudaMemsetAsync(p_er0, 0, 4 * NNODES * NHEAD * sizeof(float), 0);
    cudaMemsetAsync(p_w0,  0, 4 * NNODES * sizeof(float), 0);
    count_kernel<<<dim3((NEDGE + 255) / 256, 4), 256>>>(ed4);
    scan_kernel<<<4, 1024>>>();
    {
        CVT c = {};
        c.src[0] = hx;      c.dst[0] = p_tx[0];    c.n4[0] = NNODES * FDIM / 4;
        c.src[1] = tx;      c.dst[1] = p_tx[1];    c.n4[1] = NNODES * FDIM / 4;
        c.src[2] = w_h[0];  c.dst[2] = p_twhw[0];  c.n4[2] = FDIM * FDIM / 4;
        c.src[3] = w_h[1];  c.dst[3] = p_twhw[1];  c.n4[3] = FDIM * FDIM / 4;
        c.src[4] = fc[0];   c.dst[4] = p_tfc[0];   c.n4[4] = 2 * FDIM * DDIM / 4;
        c.src[5] = fc[1];   c.dst[5] = p_tfc[1];   c.n4[5] = 2 * FDIM * DDIM / 4;
        c.src[6] = pred[0]; c.dst[6] = p_tpred[0]; c.n4[6] = DDIM * OSZ / 4;
        c.src[7] = pred[1]; c.dst[7] = p_tpred[1]; c.n4[7] = DDIM * OSZ / 4;
        c.src[8] = W1[0];   c.dst[8] = p_tW1[0];   c.n4[8] = DDIM * SEMH / 4;
        c.src[9] = W1[1];   c.dst[9] = p_tW1[1];   c.n4[9] = DDIM * SEMH / 4;
        cvt_kernel<<<dim3(640, 10), 256>>>(c);
    }

    // 1) combined weights W[z] = w_h[b] @ fc[b][m]
    {
        GB gb = {};
        for (int z = 0; z < 4; z++) {
            gb.A[z] = p_twhw[z >> 1];
            gb.B[z] = p_tfc[z >> 1] + (size_t)(z & 1) * FDIM * DDIM;
            gb.C[z] = p_tW[z];
        }
        dim3 g(DDIM / 128, FDIM / 128, 4);
        mma_gemm_async<4, false, 1><<<g, 256, SM_NN4>>>(gb, FDIM, DDIM, FDIM);
    }
    // 2) feat = x @ W  (batched x4, fused el/er epilogue)
    {
        GB gb = {};
        for (int z = 0; z < 4; z++) {
            gb.A[z] = p_tx[z >> 1];
            gb.B[z] = p_tW[z];
            gb.C[z] = p_feat[z];
            gb.AL[z] = (z & 2) ? (al[1] + (z & 1) * NHEAD * 64) : (al[0] + (z & 1) * NHEAD * 64);
            gb.AR[z] = (z & 2) ? (ar[1] + (z & 1) * NHEAD * 64) : (ar[0] + (z & 1) * NHEAD * 64);
            gb.EL[z] = p_el[z];
            gb.ER[z] = p_er[z];
        }
        dim3 g(DDIM / 128, (NNODES + 127) / 128, 4);
        mma_gemm_async<4, false, 4><<<g, 256, SM_NN4>>>(gb, NNODES, DDIM, FDIM);
    }
    // 3) fused exp/scatter + aggregate (x4)
    exp_scatter_kernel<<<dim3((NEDGE + 255) / 256, 4), 256>>>(ed4);
    agg_kernel<<<dim3((NNODES * 4 + 7) / 8, 4), 256>>>(bias4);

    // 4) semantic attention GEMM with fused score epilogue (x4) + fuse (x2)
    {
        GB gb = {};
        for (int z = 0; z < 4; z++) {
            gb.A[z] = p_tz[z];
            gb.B[z] = p_tW1[z >> 1];
            gb.B1[z] = b1[z >> 1];
            gb.W2p[z] = W2[z >> 1];
            gb.WO[z] = p_w[z];
        }
        dim3 g(1, (NNODES + 63) / 64, 4);
        mma_gemm_async<2, false, 5><<<g, 256, SM_NN2>>>(gb, NNODES, SEMH, DDIM);
    }
    fuse_kernel<<<dim3((NNODES * DDIM + 255) / 256, 2), 256>>>();

    // 5) prediction heads (batched x2, dual f32 + tf32 epilogue)
    {
        GB gb = {};
        gb.A[0] = p_tfu[0]; gb.B[0] = p_tpred[0]; gb.C[0] = h1; gb.C2[0] = p_th[0];
        gb.A[1] = p_tfu[1]; gb.B[1] = p_tpred[1]; gb.C[1] = h2; gb.C2[1] = p_th[1];
        dim3 g(1, (NNODES + 63) / 64, 2);
        mma_gemm_async<2, false, 2><<<g, 256, SM_NN2>>>(gb, NNODES, OSZ, DDIM);
    }
    // 6) prod = h1 @ h2^T (tf32 copies, streaming stores, ldmatrix A+B)
    {
        GB gb = {};
        gb.A[0] = p_th[0]; gb.B[0] = p_th[1]; gb.C[0] = prod;
        dim3 g((NNODES + 127) / 128, (NNODES + 127) / 128, 1);
        mma_gemm_async<4, true, 3><<<g, 256, SM_NT>>>(gb, NNODES, NNODES, OSZ);
    }
}

// round 14
// speedup vs baseline: 4.6613x; 1.0567x over previous
#include <cuda_runtime.h>
#include <cstdint>

#define NNODES 10000
#define FDIM   256
#define DDIM   512
#define NEDGE  160000
#define NHEAD  8
#define SEMH   128
#define OSZ    64

// ---------------- scratch (static device globals; no allocation) ----------------
__device__ float g_feat[4][NNODES * DDIM];
__device__ float g_z   [4][NNODES * DDIM];
__device__ int   g_off [4][NNODES + 1];
__device__ int   g_eid [4][NEDGE];

// one contiguous zero-initialized accumulator region (single memset):
//   [0, 4N)                cur (int)
//   [4N, 4N+32N)           el  (float)
//   [4N+32N, 4N+64N)       er  (float)
//   [4N+64N, 4N+68N)       w   (float)
#define ZW_CUR 0
#define ZW_EL  (4 * NNODES)
#define ZW_ER  (ZW_EL + 4 * NNODES * NHEAD)
#define ZW_W   (ZW_ER + 4 * NNODES * NHEAD)
#define ZW_TOT (ZW_W + 4 * NNODES)
__device__ unsigned g_zbuf[ZW_TOT];
#define G_CUR(z) ((int*)g_zbuf + (z) * NNODES)
#define G_EL(z)  ((float*)g_zbuf + ZW_EL + (z) * NNODES * NHEAD)
#define G_ER(z)  ((float*)g_zbuf + ZW_ER + (z) * NNODES * NHEAD)
#define G_W(z)   ((float*)g_zbuf + ZW_W + (z) * NNODES)

// tf32-at-rest operands (bits stored as unsigned)
__device__ unsigned t_x   [2][NNODES * FDIM];
__device__ unsigned t_whw [2][FDIM * FDIM];
__device__ unsigned t_fc  [2][2 * FDIM * DDIM];
__device__ unsigned t_pred[2][DDIM * OSZ];
__device__ unsigned t_W1  [2][DDIM * SEMH];
__device__ unsigned t_W   [4][FDIM * DDIM];
__device__ unsigned t_z   [4][NNODES * DDIM];
__device__ unsigned t_fu  [2][NNODES * DDIM];
__device__ unsigned t_h   [2][NNODES * OSZ];

struct GB {
    const void* A[4]; const void* B[4]; void* C[4]; void* C2[4];
    const float* AL[4]; const float* AR[4]; float* EL[4]; float* ER[4];
    const float* B1[4]; const float* W2p[4]; float* WO[4];
};
struct IP4  { const int*   p[4]; };
struct FP4  { const float* p[4]; };
struct CVT  { const float* src[10]; unsigned* dst[10]; int n4[10]; };

__device__ __forceinline__ unsigned f2tf(float f) {
    unsigned r;
    asm("cvt.rna.tf32.f32 %0, %1;" : "=r"(r) : "f"(f));
    return r;
}

// ---------------- one-shot f32 -> tf32 conversion ----------
__global__ void cvt_kernel(CVT c) {
    int seg = blockIdx.y;
    int n4 = c.n4[seg];
    const float4* s = (const float4*)c.src[seg];
    uint4* d = (uint4*)c.dst[seg];
    for (int i = blockIdx.x * 256 + threadIdx.x; i < n4; i += gridDim.x * 256) {
        float4 v = s[i];
        d[i] = make_uint4(f2tf(v.x), f2tf(v.y), f2tf(v.z), f2tf(v.w));
    }
}

// ---------------- async tf32 MMA GEMM: cp.async 4-stage, z-batched -----------
// Block tile BM(=32*MT) x 128, K-tile 16. 256 threads = 8 warps 2(m) x 4(n).
// Pitched raw smem tiles; A via ldmatrix.x4 (conflict-free at pitch 20);
// B via ldmatrix.x4 (NT) or scalar LDS (NN).
// EPI: 0 f32 C; 1 tf32 C; 2 f32 C + tf32 C2; 3 f32 streaming;
//      4 f32 C + fused el/er; 5 fused semantic score (no C store).

template<int MT, bool TRANSB, int EPI>
__global__ __launch_bounds__(256, 2) void mma_gemm_async(GB gb, int M, int N, int K) {
    constexpr int S  = 4;
    constexpr int BM = 32 * MT;
    constexpr int PA = 20;
    constexpr int PB = TRANSB ? 20 : 136;
    constexpr int AW = BM * PA;
    constexpr int BW = TRANSB ? 128 * PB : 16 * PB;
    constexpr int AQ = BM / 64;
    extern __shared__ unsigned smem[];

    const unsigned* __restrict__ A = (const unsigned*)gb.A[blockIdx.z];
    const unsigned* __restrict__ B = (const unsigned*)gb.B[blockIdx.z];
    float* C = (float*)gb.C[blockIdx.z];
    unsigned* C2 = (unsigned*)gb.C2[blockIdx.z];

    int tid = threadIdx.x, warp = tid >> 5, lane = tid & 31;
    int wm = warp >> 2, wn = warp & 3;
    int row0 = blockIdx.y * BM, col0 = blockIdx.x * 128;
    int nk = K >> 4;
    unsigned sbase = (unsigned)__cvta_generic_to_shared(smem);

    auto issue = [&](int t) {
        int k0 = t * 16, buf = t & (S - 1);
#pragma unroll
        for (int j = 0; j < AQ; j++) {
            int i = tid + j * 256;
            int r = i >> 2, c4 = i & 3;
            int gr = row0 + r;
            int sz = 16;
            if (gr >= M) { sz = 0; gr = row0; }
            unsigned sd = sbase + ((buf * AW + r * PA + c4 * 4) << 2);
            asm volatile("cp.async.cg.shared.global [%0], [%1], 16, %2;"
                         :: "r"(sd), "l"(A + (size_t)gr * K + k0 + c4 * 4), "r"(sz));
        }
#pragma unroll
        for (int j = 0; j < 2; j++) {
            int i = tid + j * 256;
            const unsigned* src;
            int dstw, sz = 16;
            if (!TRANSB) {
                int k = i >> 5, c4 = i & 31;
                int gc = col0 + c4 * 4;
                if (gc >= N) { sz = 0; gc = col0; }
                src = B + (size_t)(k0 + k) * N + gc;
                dstw = k * PB + c4 * 4;
            } else {
                int n = i >> 2, c4 = i & 3;
                int gn = col0 + n;
                if (gn >= N) { sz = 0; gn = col0; }
                src = B + (size_t)gn * K + k0 + c4 * 4;
                dstw = n * PB + c4 * 4;
            }
            unsigned sd = sbase + ((S * AW + buf * BW + dstw) << 2);
            asm volatile("cp.async.cg.shared.global [%0], [%1], 16, %2;"
                         :: "r"(sd), "l"(src), "r"(sz));
        }
    };

    float acc[MT][4][4];
#pragma unroll
    for (int i = 0; i < MT; i++)
#pragma unroll
        for (int j = 0; j < 4; j++)
#pragma unroll
            for (int q = 0; q < 4; q++) acc[i][j][q] = 0.f;

#pragma unroll
    for (int t = 0; t < S - 1; t++) {
        if (t < nk) issue(t);
        asm volatile("cp.async.commit_group;");
    }

    const unsigned aLdm = ((wm * MT * 16 + (lane & 15)) * PA + (lane >> 4) * 4) << 2;
    const unsigned bLdm = TRANSB
        ? (((wn * 32 + (lane & 7) + ((lane >> 4) & 1) * 8) * PB + ((lane >> 3) & 1) * 4) << 2)
        : 0u;
    const int bB0 = (lane & 3) * PB + wn * 32 + (lane >> 2);

    for (int t = 0; t < nk; t++) {
        int buf = t & (S - 1);
        asm volatile("cp.async.wait_group %0;" :: "n"(S - 2));
        __syncthreads();
        if (t + S - 1 < nk) issue(t + S - 1);
        asm volatile("cp.async.commit_group;");

#pragma unroll
        for (int ks = 0; ks < 2; ks++) {
            unsigned af[MT][4];
            unsigned bf[4][2];
            unsigned aAddr = sbase + ((buf * AW) << 2) + aLdm + ((ks * 8) << 2);
#pragma unroll
            for (int mt = 0; mt < MT; mt++) {
                asm volatile("ldmatrix.sync.aligned.m8n8.x4.shared.b16 "
                             "{%0,%1,%2,%3}, [%4];"
                             : "=r"(af[mt][0]), "=r"(af[mt][1]),
                               "=r"(af[mt][2]), "=r"(af[mt][3])
                             : "r"(aAddr + ((mt * 16 * PA) << 2)));
            }
            if (TRANSB) {
                unsigned bAddr = sbase + ((S * AW + buf * BW) << 2) + bLdm + ((ks * 8) << 2);
#pragma unroll
                for (int p = 0; p < 2; p++) {
                    asm volatile("ldmatrix.sync.aligned.m8n8.x4.shared.b16 "
                                 "{%0,%1,%2,%3}, [%4];"
                                 : "=r"(bf[2 * p][0]), "=r"(bf[2 * p][1]),
                                   "=r"(bf[2 * p + 1][0]), "=r"(bf[2 * p + 1][1])
                                 : "r"(bAddr + ((p * 16 * PB) << 2)));
                }
            } else {
                const unsigned* bp = smem + S * AW + buf * BW + bB0;
#pragma unroll
                for (int nt = 0; nt < 4; nt++) {
                    const unsigned* p = bp + ks * 8 * PB + nt * 8;
                    bf[nt][0] = p[0];
                    bf[nt][1] = p[4 * PB];
                }
            }
#pragma unroll
            for (int mt = 0; mt < MT; mt++)
#pragma unroll
                for (int nt = 0; nt < 4; nt++) {
                    asm volatile(
                        "mma.sync.aligned.m16n8k8.row.col.f32.tf32.tf32.f32 "
                        "{%0,%1,%2,%3}, {%4,%5,%6,%7}, {%8,%9}, {%0,%1,%2,%3};"
                        : "+f"(acc[mt][nt][0]), "+f"(acc[mt][nt][1]),
                          "+f"(acc[mt][nt][2]), "+f"(acc[mt][nt][3])
                        : "r"(af[mt][0]), "r"(af[mt][1]), "r"(af[mt][2]), "r"(af[mt][3]),
                          "r"(bf[nt][0]), "r"(bf[nt][1]));
                }
        }
    }

    // ---------------- epilogue ----------------
    if (EPI != 5) {
#pragma unroll
        for (int mt = 0; mt < MT; mt++) {
            int r0 = row0 + wm * (MT * 16) + mt * 16 + (lane >> 2);
#pragma unroll
            for (int nt = 0; nt < 4; nt++) {
                int c = col0 + wn * 32 + nt * 8 + (lane & 3) * 2;
                if (c < N) {
#pragma unroll
                    for (int h = 0; h < 2; h++) {
                        int r = r0 + h * 8;
                        if (r < M) {
                            float v0 = acc[mt][nt][2 * h], v1 = acc[mt][nt][2 * h + 1];
                            if (EPI == 0 || EPI == 2 || EPI == 4)
                                *(float2*)(C + (size_t)r * N + c) = make_float2(v0, v1);
                            if (EPI == 3)
                                asm volatile("st.global.cs.v2.f32 [%0], {%1,%2};"
                                             :: "l"(C + (size_t)r * N + c), "f"(v0), "f"(v1)
                                             : "memory");
                            if (EPI == 1)
                                *(uint2*)((unsigned*)C + (size_t)r * N + c) =
                                    make_uint2(f2tf(v0), f2tf(v1));
                            if (EPI == 2)
                                *(uint2*)(C2 + (size_t)r * N + c) =
                                    make_uint2(f2tf(v0), f2tf(v1));
                        }
                    }
                }
            }
        }
    }
    if (EPI == 4) {
        int head = (col0 >> 6) + (wn >> 1);
        const float* al = gb.AL[blockIdx.z] + head * 64;
        const float* ar = gb.AR[blockIdx.z] + head * 64;
        float alv[4][2], arv[4][2];
#pragma unroll
        for (int nt = 0; nt < 4; nt++) {
            int cc = (wn & 1) * 32 + nt * 8 + (lane & 3) * 2;
            alv[nt][0] = al[cc];     alv[nt][1] = al[cc + 1];
            arv[nt][0] = ar[cc];     arv[nt][1] = ar[cc + 1];
        }
        float* ELp = gb.EL[blockIdx.z];
        float* ERp = gb.ER[blockIdx.z];
#pragma unroll
        for (int mt = 0; mt < MT; mt++) {
            int r0 = row0 + wm * (MT * 16) + mt * 16 + (lane >> 2);
#pragma unroll
            for (int h = 0; h < 2; h++) {
                float ep = 0.f, rp = 0.f;
#pragma unroll
                for (int nt = 0; nt < 4; nt++) {
                    ep += acc[mt][nt][2 * h] * alv[nt][0] + acc[mt][nt][2 * h + 1] * alv[nt][1];
                    rp += acc[mt][nt][2 * h] * arv[nt][0] + acc[mt][nt][2 * h + 1] * arv[nt][1];
                }
                ep += __shfl_xor_sync(0xffffffffu, ep, 1);
                ep += __shfl_xor_sync(0xffffffffu, ep, 2);
                rp += __shfl_xor_sync(0xffffffffu, rp, 1);
                rp += __shfl_xor_sync(0xffffffffu, rp, 2);
                int r = r0 + h * 8;
                if ((lane & 3) == 0 && r < M) {
                    atomicAdd(&ELp[r * NHEAD + head], ep);
                    atomicAdd(&ERp[r * NHEAD + head], rp);
                }
            }
        }
    }
    if (EPI == 5) {
        const float* b1 = gb.B1[blockIdx.z];
        const float* W2 = gb.W2p[blockIdx.z];
        float b1v[4][2], w2v[4][2];
#pragma unroll
        for (int nt = 0; nt < 4; nt++) {
            int cc = wn * 32 + nt * 8 + (lane & 3) * 2;
            b1v[nt][0] = b1[cc];     b1v[nt][1] = b1[cc + 1];
            w2v[nt][0] = W2[cc];     w2v[nt][1] = W2[cc + 1];
        }
        float* wout = gb.WO[blockIdx.z];
#pragma unroll
        for (int mt = 0; mt < MT; mt++) {
            int r0 = row0 + wm * (MT * 16) + mt * 16 + (lane >> 2);
#pragma unroll
            for (int h = 0; h < 2; h++) {
                float s = 0.f;
#pragma unroll
                for (int nt = 0; nt < 4; nt++) {
                    s += tanhf(acc[mt][nt][2 * h]     + b1v[nt][0]) * w2v[nt][0];
                    s += tanhf(acc[mt][nt][2 * h + 1] + b1v[nt][1]) * w2v[nt][1];
                }
                s += __shfl_xor_sync(0xffffffffu, s, 1);
                s += __shfl_xor_sync(0xffffffffu, s, 2);
                int r = r0 + h * 8;
                if ((lane & 3) == 0 && r < M) atomicAdd(&wout[r], s);
            }
        }
    }
}

// ---------------- GAT kernels (grid.y = instance z) ----------------

__global__ void count_kernel(IP4 ed4) {
    int z = blockIdx.y;
    int i = blockIdx.x * blockDim.x + threadIdx.x;
    if (i >= NEDGE) return;
    atomicAdd(&G_CUR(z)[ed4.p[z][NEDGE + i]], 1);
}

__global__ void scan_kernel() {
    int z = blockIdx.x;
    int* cur = G_CUR(z);
    int* off = g_off[z];
    __shared__ int part[1024];
    int t = threadIdx.x;
    int base = t * 10;
    int v[10];
    int s = 0;
#pragma unroll
    for (int j = 0; j < 10; j++) {
        int idx = base + j;
        int c = (idx < NNODES) ? cur[idx] : 0;
        v[j] = c;
        s += c;
    }
    part[t] = s;
    __syncthreads();
    for (int o = 1; o < 1024; o <<= 1) {
        int x = (t >= o) ? part[t - o] : 0;
        __syncthreads();
        part[t] += x;
        __syncthreads();
    }
    int run = (t > 0) ? part[t - 1] : 0;
#pragma unroll
    for (int j = 0; j < 10; j++) {
        int idx = base + j;
        if (idx < NNODES) {
            off[idx] = run;
            cur[idx] = run;
            run += v[j];
        }
    }
    if (t == 0) off[NNODES] = NEDGE;
}

// pure CSR scatter: eid[pos] = src (exp now computed inline in agg)
__global__ void scatter_kernel(IP4 ed4) {
    int z = blockIdx.y;
    int i = blockIdx.x * blockDim.x + threadIdx.x;
    if (i >= NEDGE) return;
    const int* ed = ed4.p[z];
    int d = ed[NEDGE + i];
    int p = atomicAdd(&G_CUR(z)[d], 1);
    g_eid[z][p] = ed[i];
}

// gather-aggregate: one warp per (dst node, 128-col strip); softmax exp
// computed inline from el/er (er warp-uniform, hoisted), normalized at end;
// bias+ELU fused; dual f32 + tf32 epilogue.
__global__ __launch_bounds__(256) void agg_kernel(FP4 bias4) {
    int z = blockIdx.y;
    int wid = blockIdx.x * 8 + (threadIdx.x >> 5);
    if (wid >= NNODES * 4) return;
    const float* bias = bias4.p[z];
    const float* __restrict__ feat = g_feat[z];
    const float* __restrict__ el = G_EL(z);
    const int* __restrict__ eid = g_eid[z];
    int d = wid >> 2, strip = wid & 3;
    int lane = threadIdx.x & 31;
    int col = strip * 128 + lane * 4;
    int head = col >> 6;
    float erv = G_ER(z)[d * NHEAD + head];

    float4 acc = make_float4(0.f, 0.f, 0.f, 0.f);
    float sum_ax = 0.f;
    int b = g_off[z][d], e_ = g_off[z][d + 1];
    if (b < e_) {
        int sA = eid[b];
        int sB = (b + 1 < e_) ? eid[b + 1] : sA;
        float elA = el[sA * NHEAD + head];
        for (int i = b; i < e_; i++) {
            int sC = (i + 2 < e_) ? eid[i + 2] : sB;
            float elB = (i + 1 < e_) ? el[sB * NHEAD + head] : 0.f;
            float v = elA + erv;
            v = v > 0.f ? v : 0.2f * v;
            float ax = __expf(v);
            float4 f = *(const float4*)(feat + (size_t)sA * DDIM + col);
            acc.x += f.x * ax;
            acc.y += f.y * ax;
            acc.z += f.z * ax;
            acc.w += f.w * ax;
            sum_ax += ax;
            sA = sB; sB = sC; elA = elB;
        }
        float rcp = 1.f / sum_ax;
        acc.x *= rcp; acc.y *= rcp; acc.z *= rcp; acc.w *= rcp;
    }
    float4 bb = *(const float4*)(bias + col);
    float4 v;
    v.x = acc.x + bb.x; v.x = v.x > 0.f ? v.x : (__expf(v.x) - 1.f);
    v.y = acc.y + bb.y; v.y = v.y > 0.f ? v.y : (__expf(v.y) - 1.f);
    v.z = acc.z + bb.z; v.z = v.z > 0.f ? v.z : (__expf(v.z) - 1.f);
    v.w = acc.w + bb.w; v.w = v.w > 0.f ? v.w : (__expf(v.w) - 1.f);
    *(float4*)(g_z[z] + (size_t)d * DDIM + col) = v;
    *(uint4*)(&t_z[z][(size_t)d * DDIM + col]) =
        make_uint4(f2tf(v.x), f2tf(v.y), f2tf(v.z), f2tf(v.w));
}

// ---------------- fuse ----------------

__global__ void fuse_kernel() {
    int b = blockIdx.y;
    int i = blockIdx.x * blockDim.x + threadIdx.x;
    if (i >= NNODES * DDIM) return;
    int n = i >> 9;
    float a = G_W(2 * b)[n], c = G_W(2 * b + 1)[n];
    float m = fmaxf(a, c);
    float ea = __expf(a - m), eb = __expf(c - m);
    float be = ea / (ea + eb);
    t_fu[b][i] = f2tf(be * g_z[2 * b][i] + (1.f - be) * g_z[2 * b + 1][i]);
}

// ---------------- host orchestration ----------------

extern "C" void kernel_launch(void* const* d_in, const int* in_sizes, int n_in,
                              void* d_out, int out_size) {
    float *p_feat[4];
    unsigned *p_tx[2], *p_twhw[2], *p_tfc[2], *p_tpred[2], *p_tW1[2];
    unsigned *p_tW[4], *p_tz[4], *p_tfu[2], *p_th[2];
    unsigned* p_zbuf;
    {
        float* base;
        cudaGetSymbolAddress((void**)&base, g_feat);
        for (int z = 0; z < 4; z++) p_feat[z] = base + (size_t)z * NNODES * DDIM;
        cudaGetSymbolAddress((void**)&p_zbuf, g_zbuf);
        unsigned* ub;
        cudaGetSymbolAddress((void**)&ub, t_x);
        for (int b = 0; b < 2; b++) p_tx[b] = ub + (size_t)b * NNODES * FDIM;
        cudaGetSymbolAddress((void**)&ub, t_whw);
        for (int b = 0; b < 2; b++) p_twhw[b] = ub + (size_t)b * FDIM * FDIM;
        cudaGetSymbolAddress((void**)&ub, t_fc);
        for (int b = 0; b < 2; b++) p_tfc[b] = ub + (size_t)b * 2 * FDIM * DDIM;
        cudaGetSymbolAddress((void**)&ub, t_pred);
        for (int b = 0; b < 2; b++) p_tpred[b] = ub + (size_t)b * DDIM * OSZ;
        cudaGetSymbolAddress((void**)&ub, t_W1);
        for (int b = 0; b < 2; b++) p_tW1[b] = ub + (size_t)b * DDIM * SEMH;
        cudaGetSymbolAddress((void**)&ub, t_W);
        for (int z = 0; z < 4; z++) p_tW[z] = ub + (size_t)z * FDIM * DDIM;
        cudaGetSymbolAddress((void**)&ub, t_z);
        for (int z = 0; z < 4; z++) p_tz[z] = ub + (size_t)z * NNODES * DDIM;
        cudaGetSymbolAddress((void**)&ub, t_fu);
        for (int b = 0; b < 2; b++) p_tfu[b] = ub + (size_t)b * NNODES * DDIM;
        cudaGetSymbolAddress((void**)&ub, t_h);
        for (int b = 0; b < 2; b++) p_th[b] = ub + (size_t)b * NNODES * OSZ;
    }
    float* p_el[4];
    float* p_er[4];
    float* p_w[4];
    for (int z = 0; z < 4; z++) {
        p_el[z] = (float*)p_zbuf + ZW_EL + (size_t)z * NNODES * NHEAD;
        p_er[z] = (float*)p_zbuf + ZW_ER + (size_t)z * NNODES * NHEAD;
        p_w[z]  = (float*)p_zbuf + ZW_W  + (size_t)z * NNODES;
    }

    const float* hx = (const float*)d_in[0];
    const float* tx = (const float*)d_in[1];
    const float* w_h[2]  = {(const float*)d_in[2],  (const float*)d_in[11]};
    const float* fc[2]   = {(const float*)d_in[3],  (const float*)d_in[12]};
    const float* al[2]   = {(const float*)d_in[4],  (const float*)d_in[13]};
    const float* ar[2]   = {(const float*)d_in[5],  (const float*)d_in[14]};
    const float* bias[2] = {(const float*)d_in[6],  (const float*)d_in[15]};
    const float* W1[2]   = {(const float*)d_in[7],  (const float*)d_in[16]};
    const float* b1[2]   = {(const float*)d_in[8],  (const float*)d_in[17]};
    const float* W2[2]   = {(const float*)d_in[9],  (const float*)d_in[18]};
    const float* pred[2] = {(const float*)d_in[10], (const float*)d_in[19]};

    IP4 ed4 = {{(const int*)d_in[20], (const int*)d_in[21],
                (const int*)d_in[22], (const int*)d_in[23]}};
    FP4 bias4 = {{bias[0], bias[0] + DDIM, bias[1], bias[1] + DDIM}};

    float* out  = (float*)d_out;
    float* h1   = out;
    float* h2   = out + (size_t)NNODES * OSZ;
    float* prod = out + (size_t)2 * NNODES * OSZ;

    const int SM_NN4 = 4 * (128 * 20 + 16 * 136) * 4;   // 75776
    const int SM_NN2 = 4 * (64 * 20 + 16 * 136) * 4;    // 55296
    const int SM_NT  = 4 * (128 * 20 + 128 * 20) * 4;   // 81920
    cudaFuncSetAttribute(mma_gemm_async<4, false, 1>,
                         cudaFuncAttributeMaxDynamicSharedMemorySize, SM_NN4);
    cudaFuncSetAttribute(mma_gemm_async<4, false, 4>,
                         cudaFuncAttributeMaxDynamicSharedMemorySize, SM_NN4);
    cudaFuncSetAttribute(mma_gemm_async<2, false, 5>,
                         cudaFuncAttributeMaxDynamicSharedMemorySize, SM_NN2);
    cudaFuncSetAttribute(mma_gemm_async<2, false, 2>,
                         cudaFuncAttributeMaxDynamicSharedMemorySize, SM_NN2);
    cudaFuncSetAttribute(mma_gemm_async<4, true, 3>,
                         cudaFuncAttributeMaxDynamicSharedMemorySize, SM_NT);

    // 0) single clear of all accumulators (cur/el/er/w), CSR build, tf32 cvt
    cudaMemsetAsync(p_zbuf, 0, ZW_TOT * sizeof(unsigned), 0);
    count_kernel<<<dim3((NEDGE + 255) / 256, 4), 256>>>(ed4);
    scan_kernel<<<4, 1024>>>();
    scatter_kernel<<<dim3((NEDGE + 255) / 256, 4), 256>>>(ed4);
    {
        CVT c = {};
        c.src[0] = hx;      c.dst[0] = p_tx[0];    c.n4[0] = NNODES * FDIM / 4;
        c.src[1] = tx;      c.dst[1] = p_tx[1];    c.n4[1] = NNODES * FDIM / 4;
        c.src[2] = w_h[0];  c.dst[2] = p_twhw[0];  c.n4[2] = FDIM * FDIM / 4;
        c.src[3] = w_h[1];  c.dst[3] = p_twhw[1];  c.n4[3] = FDIM * FDIM / 4;
        c.src[4] = fc[0];   c.dst[4] = p_tfc[0];   c.n4[4] = 2 * FDIM * DDIM / 4;
        c.src[5] = fc[1];   c.dst[5] = p_tfc[1];   c.n4[5] = 2 * FDIM * DDIM / 4;
        c.src[6] = pred[0]; c.dst[6] = p_tpred[0]; c.n4[6] = DDIM * OSZ / 4;
        c.src[7] = pred[1]; c.dst[7] = p_tpred[1]; c.n4[7] = DDIM * OSZ / 4;
        c.src[8] = W1[0];   c.dst[8] = p_tW1[0];   c.n4[8] = DDIM * SEMH / 4;
        c.src[9] = W1[1];   c.dst[9] = p_tW1[1];   c.n4[9] = DDIM * SEMH / 4;
        cvt_kernel<<<dim3(640, 10), 256>>>(c);
    }

    // 1) combined weights W[z] = w_h[b] @ fc[b][m]
    {
        GB gb = {};
        for (int z = 0; z < 4; z++) {
            gb.A[z] = p_twhw[z >> 1];
            gb.B[z] = p_tfc[z >> 1] + (size_t)(z & 1) * FDIM * DDIM;
            gb.C[z] = p_tW[z];
        }
        dim3 g(DDIM / 128, FDIM / 128, 4);
        mma_gemm_async<4, false, 1><<<g, 256, SM_NN4>>>(gb, FDIM, DDIM, FDIM);
    }
    // 2) feat = x @ W  (batched x4, fused el/er epilogue)
    {
        GB gb = {};
        for (int z = 0; z < 4; z++) {
            gb.A[z] = p_tx[z >> 1];
            gb.B[z] = p_tW[z];
            gb.C[z] = p_feat[z];
            gb.AL[z] = (z & 2) ? (al[1] + (z & 1) * NHEAD * 64) : (al[0] + (z & 1) * NHEAD * 64);
            gb.AR[z] = (z & 2) ? (ar[1] + (z & 1) * NHEAD * 64) : (ar[0] + (z & 1) * NHEAD * 64);
            gb.EL[z] = p_el[z];
            gb.ER[z] = p_er[z];
        }
        dim3 g(DDIM / 128, (NNODES + 127) / 128, 4);
        mma_gemm_async<4, false, 4><<<g, 256, SM_NN4>>>(gb, NNODES, DDIM, FDIM);
    }
    // 3) aggregate (x4; softmax exp inline)
    agg_kernel<<<dim3((NNODES * 4 + 7) / 8, 4), 256>>>(bias4);

    // 4) semantic attention GEMM with fused score epilogue (x4) + fuse (x2)
    {
        GB gb = {};
        for (int z = 0; z < 4; z++) {
            gb.A[z] = p_tz[z];
            gb.B[z] = p_tW1[z >> 1];
            gb.B1[z] = b1[z >> 1];
            gb.W2p[z] = W2[z >> 1];
            gb.WO[z] = p_w[z];
        }
        dim3 g(1, (NNODES + 63) / 64, 4);
        mma_gemm_async<2, false, 5><<<g, 256, SM_NN2>>>(gb, NNODES, SEMH, DDIM);
    }
    fuse_kernel<<<dim3((NNODES * DDIM + 255) / 256, 2), 256>>>();

    // 5) prediction heads (batched x2, dual f32 + tf32 epilogue)
    {
        GB gb = {};
        gb.A[0] = p_tfu[0]; gb.B[0] = p_tpred[0]; gb.C[0] = h1; gb.C2[0] = p_th[0];
        gb.A[1] = p_tfu[1]; gb.B[1] = p_tpred[1]; gb.C[1] = h2; gb.C2[1] = p_th[1];
        dim3 g(1, (NNODES + 63) / 64, 2);
        mma_gemm_async<2, false, 2><<<g, 256, SM_NN2>>>(gb, NNODES, OSZ, DDIM);
    }
    // 6) prod = h1 @ h2^T (tf32 copies, streaming stores, ldmatrix A+B)
    {
        GB gb = {};
        gb.A[0] = p_th[0]; gb.B[0] = p_th[1]; gb.C[0] = prod;
        dim3 g((NNODES + 127) / 128, (NNODES + 127) / 128, 1);
        mma_gemm_async<4, true, 3><<<g, 256, SM_NT>>>(gb, NNODES, NNODES, OSZ);
    }
}

// round 15
// speedup vs baseline: 4.8147x; 1.0329x over previous
#include <cuda_runtime.h>
#include <cstdint>

#define NNODES 10000
#define FDIM   256
#define DDIM   512
#define NEDGE  160000
#define NHEAD  8
#define SEMH   128
#define OSZ    64

// ---------------- scratch (static device globals; no allocation) ----------------
__device__ float g_feat[4][NNODES * DDIM];
__device__ float g_z   [4][NNODES * DDIM];
__device__ int   g_off [4][NNODES + 1];
__device__ int   g_eid [4][NEDGE];

// one contiguous zero-initialized accumulator region (single memset)
#define ZW_CUR 0
#define ZW_EL  (4 * NNODES)
#define ZW_ER  (ZW_EL + 4 * NNODES * NHEAD)
#define ZW_W   (ZW_ER + 4 * NNODES * NHEAD)
#define ZW_TOT (ZW_W + 4 * NNODES)
__device__ unsigned g_zbuf[ZW_TOT];
#define G_CUR(z) ((int*)g_zbuf + (z) * NNODES)
#define G_EL(z)  ((float*)g_zbuf + ZW_EL + (z) * NNODES * NHEAD)
#define G_ER(z)  ((float*)g_zbuf + ZW_ER + (z) * NNODES * NHEAD)
#define G_W(z)   ((float*)g_zbuf + ZW_W + (z) * NNODES)

// tf32-at-rest operands (bits stored as unsigned)
__device__ unsigned t_x   [2][NNODES * FDIM];
__device__ unsigned t_whw [2][FDIM * FDIM];
__device__ unsigned t_fc  [2][2 * FDIM * DDIM];
__device__ unsigned t_pred[2][DDIM * OSZ];
__device__ unsigned t_W1  [2][DDIM * SEMH];
__device__ unsigned t_W   [4][FDIM * DDIM];
__device__ unsigned t_z   [4][NNODES * DDIM];
__device__ unsigned t_h   [2][NNODES * OSZ];

struct GB {
    const void* A[4]; const void* B[4]; void* C[4]; void* C2[4];
    const float* AL[4]; const float* AR[4]; float* EL[4]; float* ER[4];
    const float* B1[4]; const float* W2p[4]; float* WO[4];
};
struct PG {
    const float* z0[2]; const float* z1[2]; const float* w0[2]; const float* w1[2];
    const unsigned* B[2]; float* C[2]; unsigned* C2[2];
};
struct IP4  { const int*   p[4]; };
struct FP4  { const float* p[4]; };
struct CVT  { const float* src[10]; unsigned* dst[10]; int n4[10]; };

__device__ __forceinline__ unsigned f2tf(float f) {
    unsigned r;
    asm("cvt.rna.tf32.f32 %0, %1;" : "=r"(r) : "f"(f));
    return r;
}

// ---------------- one-shot f32 -> tf32 conversion ----------
__global__ void cvt_kernel(CVT c) {
    int seg = blockIdx.y;
    int n4 = c.n4[seg];
    const float4* s = (const float4*)c.src[seg];
    uint4* d = (uint4*)c.dst[seg];
    for (int i = blockIdx.x * 256 + threadIdx.x; i < n4; i += gridDim.x * 256) {
        float4 v = s[i];
        d[i] = make_uint4(f2tf(v.x), f2tf(v.y), f2tf(v.z), f2tf(v.w));
    }
}

// ---------------- async tf32 MMA GEMM: cp.async 4-stage, z-batched -----------
// EPI: 0 f32 C; 1 tf32 C; 2 f32 C + tf32 C2; 3 f32 streaming;
//      4 f32 C + fused el/er; 5 fused semantic score (no C store).

template<int MT, bool TRANSB, int EPI>
__global__ __launch_bounds__(256, 2) void mma_gemm_async(GB gb, int M, int N, int K) {
    constexpr int S  = 4;
    constexpr int BM = 32 * MT;
    constexpr int PA = 20;
    constexpr int PB = TRANSB ? 20 : 136;
    constexpr int AW = BM * PA;
    constexpr int BW = TRANSB ? 128 * PB : 16 * PB;
    constexpr int AQ = BM / 64;
    extern __shared__ unsigned smem[];

    const unsigned* __restrict__ A = (const unsigned*)gb.A[blockIdx.z];
    const unsigned* __restrict__ B = (const unsigned*)gb.B[blockIdx.z];
    float* C = (float*)gb.C[blockIdx.z];
    unsigned* C2 = (unsigned*)gb.C2[blockIdx.z];

    int tid = threadIdx.x, warp = tid >> 5, lane = tid & 31;
    int wm = warp >> 2, wn = warp & 3;
    int row0 = blockIdx.y * BM, col0 = blockIdx.x * 128;
    int nk = K >> 4;
    unsigned sbase = (unsigned)__cvta_generic_to_shared(smem);

    auto issue = [&](int t) {
        int k0 = t * 16, buf = t & (S - 1);
#pragma unroll
        for (int j = 0; j < AQ; j++) {
            int i = tid + j * 256;
            int r = i >> 2, c4 = i & 3;
            int gr = row0 + r;
            int sz = 16;
            if (gr >= M) { sz = 0; gr = row0; }
            unsigned sd = sbase + ((buf * AW + r * PA + c4 * 4) << 2);
            asm volatile("cp.async.cg.shared.global [%0], [%1], 16, %2;"
                         :: "r"(sd), "l"(A + (size_t)gr * K + k0 + c4 * 4), "r"(sz));
        }
#pragma unroll
        for (int j = 0; j < 2; j++) {
            int i = tid + j * 256;
            const unsigned* src;
            int dstw, sz = 16;
            if (!TRANSB) {
                int k = i >> 5, c4 = i & 31;
                int gc = col0 + c4 * 4;
                if (gc >= N) { sz = 0; gc = col0; }
                src = B + (size_t)(k0 + k) * N + gc;
                dstw = k * PB + c4 * 4;
            } else {
                int n = i >> 2, c4 = i & 3;
                int gn = col0 + n;
                if (gn >= N) { sz = 0; gn = col0; }
                src = B + (size_t)gn * K + k0 + c4 * 4;
                dstw = n * PB + c4 * 4;
            }
            unsigned sd = sbase + ((S * AW + buf * BW + dstw) << 2);
            asm volatile("cp.async.cg.shared.global [%0], [%1], 16, %2;"
                         :: "r"(sd), "l"(src), "r"(sz));
        }
    };

    float acc[MT][4][4];
#pragma unroll
    for (int i = 0; i < MT; i++)
#pragma unroll
        for (int j = 0; j < 4; j++)
#pragma unroll
            for (int q = 0; q < 4; q++) acc[i][j][q] = 0.f;

#pragma unroll
    for (int t = 0; t < S - 1; t++) {
        if (t < nk) issue(t);
        asm volatile("cp.async.commit_group;");
    }

    const unsigned aLdm = ((wm * MT * 16 + (lane & 15)) * PA + (lane >> 4) * 4) << 2;
    const unsigned bLdm = TRANSB
        ? (((wn * 32 + (lane & 7) + ((lane >> 4) & 1) * 8) * PB + ((lane >> 3) & 1) * 4) << 2)
        : 0u;
    const int bB0 = (lane & 3) * PB + wn * 32 + (lane >> 2);

    for (int t = 0; t < nk; t++) {
        int buf = t & (S - 1);
        asm volatile("cp.async.wait_group %0;" :: "n"(S - 2));
        __syncthreads();
        if (t + S - 1 < nk) issue(t + S - 1);
        asm volatile("cp.async.commit_group;");

#pragma unroll
        for (int ks = 0; ks < 2; ks++) {
            unsigned af[MT][4];
            unsigned bf[4][2];
            unsigned aAddr = sbase + ((buf * AW) << 2) + aLdm + ((ks * 8) << 2);
#pragma unroll
            for (int mt = 0; mt < MT; mt++) {
                asm volatile("ldmatrix.sync.aligned.m8n8.x4.shared.b16 "
                             "{%0,%1,%2,%3}, [%4];"
                             : "=r"(af[mt][0]), "=r"(af[mt][1]),
                               "=r"(af[mt][2]), "=r"(af[mt][3])
                             : "r"(aAddr + ((mt * 16 * PA) << 2)));
            }
            if (TRANSB) {
                unsigned bAddr = sbase + ((S * AW + buf * BW) << 2) + bLdm + ((ks * 8) << 2);
#pragma unroll
                for (int p = 0; p < 2; p++) {
                    asm volatile("ldmatrix.sync.aligned.m8n8.x4.shared.b16 "
                                 "{%0,%1,%2,%3}, [%4];"
                                 : "=r"(bf[2 * p][0]), "=r"(bf[2 * p][1]),
                                   "=r"(bf[2 * p + 1][0]), "=r"(bf[2 * p + 1][1])
                                 : "r"(bAddr + ((p * 16 * PB) << 2)));
                }
            } else {
                const unsigned* bp = smem + S * AW + buf * BW + bB0;
#pragma unroll
                for (int nt = 0; nt < 4; nt++) {
                    const unsigned* p = bp + ks * 8 * PB + nt * 8;
                    bf[nt][0] = p[0];
                    bf[nt][1] = p[4 * PB];
                }
            }
#pragma unroll
            for (int mt = 0; mt < MT; mt++)
#pragma unroll
                for (int nt = 0; nt < 4; nt++) {
                    asm volatile(
                        "mma.sync.aligned.m16n8k8.row.col.f32.tf32.tf32.f32 "
                        "{%0,%1,%2,%3}, {%4,%5,%6,%7}, {%8,%9}, {%0,%1,%2,%3};"
                        : "+f"(acc[mt][nt][0]), "+f"(acc[mt][nt][1]),
                          "+f"(acc[mt][nt][2]), "+f"(acc[mt][nt][3])
                        : "r"(af[mt][0]), "r"(af[mt][1]), "r"(af[mt][2]), "r"(af[mt][3]),
                          "r"(bf[nt][0]), "r"(bf[nt][1]));
                }
        }
    }

    // ---------------- epilogue ----------------
    if (EPI != 5) {
#pragma unroll
        for (int mt = 0; mt < MT; mt++) {
            int r0 = row0 + wm * (MT * 16) + mt * 16 + (lane >> 2);
#pragma unroll
            for (int nt = 0; nt < 4; nt++) {
                int c = col0 + wn * 32 + nt * 8 + (lane & 3) * 2;
                if (c < N) {
#pragma unroll
                    for (int h = 0; h < 2; h++) {
                        int r = r0 + h * 8;
                        if (r < M) {
                            float v0 = acc[mt][nt][2 * h], v1 = acc[mt][nt][2 * h + 1];
                            if (EPI == 0 || EPI == 2 || EPI == 4)
                                *(float2*)(C + (size_t)r * N + c) = make_float2(v0, v1);
                            if (EPI == 3)
                                asm volatile("st.global.cs.v2.f32 [%0], {%1,%2};"
                                             :: "l"(C + (size_t)r * N + c), "f"(v0), "f"(v1)
                                             : "memory");
                            if (EPI == 1)
                                *(uint2*)((unsigned*)C + (size_t)r * N + c) =
                                    make_uint2(f2tf(v0), f2tf(v1));
                            if (EPI == 2)
                                *(uint2*)(C2 + (size_t)r * N + c) =
                                    make_uint2(f2tf(v0), f2tf(v1));
                        }
                    }
                }
            }
        }
    }
    if (EPI == 4) {
        int head = (col0 >> 6) + (wn >> 1);
        const float* al = gb.AL[blockIdx.z] + head * 64;
        const float* ar = gb.AR[blockIdx.z] + head * 64;
        float alv[4][2], arv[4][2];
#pragma unroll
        for (int nt = 0; nt < 4; nt++) {
            int cc = (wn & 1) * 32 + nt * 8 + (lane & 3) * 2;
            alv[nt][0] = al[cc];     alv[nt][1] = al[cc + 1];
            arv[nt][0] = ar[cc];     arv[nt][1] = ar[cc + 1];
        }
        float* ELp = gb.EL[blockIdx.z];
        float* ERp = gb.ER[blockIdx.z];
#pragma unroll
        for (int mt = 0; mt < MT; mt++) {
            int r0 = row0 + wm * (MT * 16) + mt * 16 + (lane >> 2);
#pragma unroll
            for (int h = 0; h < 2; h++) {
                float ep = 0.f, rp = 0.f;
#pragma unroll
                for (int nt = 0; nt < 4; nt++) {
                    ep += acc[mt][nt][2 * h] * alv[nt][0] + acc[mt][nt][2 * h + 1] * alv[nt][1];
                    rp += acc[mt][nt][2 * h] * arv[nt][0] + acc[mt][nt][2 * h + 1] * arv[nt][1];
                }
                ep += __shfl_xor_sync(0xffffffffu, ep, 1);
                ep += __shfl_xor_sync(0xffffffffu, ep, 2);
                rp += __shfl_xor_sync(0xffffffffu, rp, 1);
                rp += __shfl_xor_sync(0xffffffffu, rp, 2);
                int r = r0 + h * 8;
                if ((lane & 3) == 0 && r < M) {
                    atomicAdd(&ELp[r * NHEAD + head], ep);
                    atomicAdd(&ERp[r * NHEAD + head], rp);
                }
            }
        }
    }
    if (EPI == 5) {
        const float* b1 = gb.B1[blockIdx.z];
        const float* W2 = gb.W2p[blockIdx.z];
        float b1v[4][2], w2v[4][2];
#pragma unroll
        for (int nt = 0; nt < 4; nt++) {
            int cc = wn * 32 + nt * 8 + (lane & 3) * 2;
            b1v[nt][0] = b1[cc];     b1v[nt][1] = b1[cc + 1];
            w2v[nt][0] = W2[cc];     w2v[nt][1] = W2[cc + 1];
        }
        float* wout = gb.WO[blockIdx.z];
#pragma unroll
        for (int mt = 0; mt < MT; mt++) {
            int r0 = row0 + wm * (MT * 16) + mt * 16 + (lane >> 2);
#pragma unroll
            for (int h = 0; h < 2; h++) {
                float s = 0.f;
#pragma unroll
                for (int nt = 0; nt < 4; nt++) {
                    s += tanhf(acc[mt][nt][2 * h]     + b1v[nt][0]) * w2v[nt][0];
                    s += tanhf(acc[mt][nt][2 * h + 1] + b1v[nt][1]) * w2v[nt][1];
                }
                s += __shfl_xor_sync(0xffffffffu, s, 1);
                s += __shfl_xor_sync(0xffffffffu, s, 2);
                int r = r0 + h * 8;
                if ((lane & 3) == 0 && r < M) atomicAdd(&wout[r], s);
            }
        }
    }
}

// ---------------- pred GEMM with fused metapath fusion in A-staging ----------
// h = fuse(z0, z1, w0, w1) @ pred.  BM=64 x 128-col tile, K-tile 16, 2-buffer
// register staging; beta per row precomputed once into smem (same formula as
// the old fuse kernel -> bit-identical). Epilogue: f32 C + tf32 C2.
__global__ __launch_bounds__(256, 2) void pred_fused_kernel(PG pg, int M, int N, int K) {
    constexpr int PA = 20;
    constexpr int PB = 136;
    __shared__ unsigned sA[2][64 * PA];
    __shared__ unsigned sB[2][16 * PB];
    __shared__ float sbe[64];

    int b = blockIdx.z;
    const float* __restrict__ Z0 = pg.z0[b];
    const float* __restrict__ Z1 = pg.z1[b];
    const unsigned* __restrict__ B = pg.B[b];
    float* C = pg.C[b];
    unsigned* C2 = pg.C2[b];

    int tid = threadIdx.x, warp = tid >> 5, lane = tid & 31;
    int wm = warp >> 2, wn = warp & 3;
    int row0 = blockIdx.y * 64, col0 = 0;
    int nk = K >> 4;

    if (tid < 64) {
        int r = row0 + tid;
        float be = 0.f;
        if (r < M) {
            float a = pg.w0[b][r], c = pg.w1[b][r];
            float m = fmaxf(a, c);
            float ea = __expf(a - m), eb = __expf(c - m);
            be = ea / (ea + eb);
        }
        sbe[tid] = be;
    }
    __syncthreads();

    float4 r0v, r1v;
    uint4 rbv[2];
    auto loadT = [&](int k0) {
        int r = tid >> 2, c4 = tid & 3;
        int gr = row0 + r;
        r0v = make_float4(0.f, 0.f, 0.f, 0.f);
        r1v = r0v;
        if (gr < M) {
            r0v = *(const float4*)(Z0 + (size_t)gr * K + k0 + c4 * 4);
            r1v = *(const float4*)(Z1 + (size_t)gr * K + k0 + c4 * 4);
        }
#pragma unroll
        for (int j = 0; j < 2; j++) {
            int i = tid + j * 256;
            int k = i >> 5, c4b = i & 31;
            int gc = col0 + c4b * 4;
            rbv[j] = make_uint4(0, 0, 0, 0);
            if (gc < N) rbv[j] = *(const uint4*)(B + (size_t)(k0 + k) * N + gc);
        }
    };
    auto storeT = [&](int buf) {
        int r = tid >> 2, c4 = tid & 3;
        float be = sbe[r], ne = 1.f - be;
        uint4 u = make_uint4(f2tf(be * r0v.x + ne * r1v.x),
                             f2tf(be * r0v.y + ne * r1v.y),
                             f2tf(be * r0v.z + ne * r1v.z),
                             f2tf(be * r0v.w + ne * r1v.w));
        *(uint4*)&sA[buf][r * PA + c4 * 4] = u;
#pragma unroll
        for (int j = 0; j < 2; j++) {
            int i = tid + j * 256;
            int k = i >> 5, c4b = i & 31;
            *(uint4*)&sB[buf][k * PB + c4b * 4] = rbv[j];
        }
    };

    float acc[2][4][4];
#pragma unroll
    for (int i = 0; i < 2; i++)
#pragma unroll
        for (int j = 0; j < 4; j++)
#pragma unroll
            for (int q = 0; q < 4; q++) acc[i][j][q] = 0.f;

    unsigned sbaseA = (unsigned)__cvta_generic_to_shared(&sA[0][0]);
    const unsigned aLdm = ((wm * 32 + (lane & 15)) * PA + (lane >> 4) * 4) << 2;
    const int bB0 = (lane & 3) * PB + wn * 32 + (lane >> 2);

    loadT(0);
    storeT(0);
    __syncthreads();

    for (int t = 0; t < nk; t++) {
        int buf = t & 1;
        if (t + 1 < nk) loadT((t + 1) * 16);

#pragma unroll
        for (int ks = 0; ks < 2; ks++) {
            unsigned af[2][4];
            unsigned bf[4][2];
            unsigned aAddr = sbaseA + ((buf * 64 * PA) << 2) + aLdm + ((ks * 8) << 2);
#pragma unroll
            for (int mt = 0; mt < 2; mt++) {
                asm volatile("ldmatrix.sync.aligned.m8n8.x4.shared.b16 "
                             "{%0,%1,%2,%3}, [%4];"
                             : "=r"(af[mt][0]), "=r"(af[mt][1]),
                               "=r"(af[mt][2]), "=r"(af[mt][3])
                             : "r"(aAddr + ((mt * 16 * PA) << 2)));
            }
            const unsigned* bp = &sB[buf][bB0];
#pragma unroll
            for (int nt = 0; nt < 4; nt++) {
                const unsigned* p = bp + ks * 8 * PB + nt * 8;
                bf[nt][0] = p[0];
                bf[nt][1] = p[4 * PB];
            }
#pragma unroll
            for (int mt = 0; mt < 2; mt++)
#pragma unroll
                for (int nt = 0; nt < 4; nt++) {
                    asm volatile(
                        "mma.sync.aligned.m16n8k8.row.col.f32.tf32.tf32.f32 "
                        "{%0,%1,%2,%3}, {%4,%5,%6,%7}, {%8,%9}, {%0,%1,%2,%3};"
                        : "+f"(acc[mt][nt][0]), "+f"(acc[mt][nt][1]),
                          "+f"(acc[mt][nt][2]), "+f"(acc[mt][nt][3])
                        : "r"(af[mt][0]), "r"(af[mt][1]), "r"(af[mt][2]), "r"(af[mt][3]),
                          "r"(bf[nt][0]), "r"(bf[nt][1]));
                }
        }
        if (t + 1 < nk) storeT(buf ^ 1);
        __syncthreads();
    }

#pragma unroll
    for (int mt = 0; mt < 2; mt++) {
        int r0 = row0 + wm * 32 + mt * 16 + (lane >> 2);
#pragma unroll
        for (int nt = 0; nt < 4; nt++) {
            int c = col0 + wn * 32 + nt * 8 + (lane & 3) * 2;
            if (c < N) {
#pragma unroll
                for (int h = 0; h < 2; h++) {
                    int r = r0 + h * 8;
                    if (r < M) {
                        float v0 = acc[mt][nt][2 * h], v1 = acc[mt][nt][2 * h + 1];
                        *(float2*)(C + (size_t)r * N + c) = make_float2(v0, v1);
                        *(uint2*)(C2 + (size_t)r * N + c) =
                            make_uint2(f2tf(v0), f2tf(v1));
                    }
                }
            }
        }
    }
}

// ---------------- GAT kernels (grid.y = instance z) ----------------

__global__ void count_kernel(IP4 ed4) {
    int z = blockIdx.y;
    int i = blockIdx.x * blockDim.x + threadIdx.x;
    if (i >= NEDGE) return;
    atomicAdd(&G_CUR(z)[ed4.p[z][NEDGE + i]], 1);
}

__global__ void scan_kernel() {
    int z = blockIdx.x;
    int* cur = G_CUR(z);
    int* off = g_off[z];
    __shared__ int part[1024];
    int t = threadIdx.x;
    int base = t * 10;
    int v[10];
    int s = 0;
#pragma unroll
    for (int j = 0; j < 10; j++) {
        int idx = base + j;
        int c = (idx < NNODES) ? cur[idx] : 0;
        v[j] = c;
        s += c;
    }
    part[t] = s;
    __syncthreads();
    for (int o = 1; o < 1024; o <<= 1) {
        int x = (t >= o) ? part[t - o] : 0;
        __syncthreads();
        part[t] += x;
        __syncthreads();
    }
    int run = (t > 0) ? part[t - 1] : 0;
#pragma unroll
    for (int j = 0; j < 10; j++) {
        int idx = base + j;
        if (idx < NNODES) {
            off[idx] = run;
            cur[idx] = run;
            run += v[j];
        }
    }
    if (t == 0) off[NNODES] = NEDGE;
}

__global__ void scatter_kernel(IP4 ed4) {
    int z = blockIdx.y;
    int i = blockIdx.x * blockDim.x + threadIdx.x;
    if (i >= NEDGE) return;
    const int* ed = ed4.p[z];
    int d = ed[NEDGE + i];
    int p = atomicAdd(&G_CUR(z)[d], 1);
    g_eid[z][p] = ed[i];
}

// gather-aggregate with inline softmax exp + end normalization; bias+ELU fused.
__global__ __launch_bounds__(256) void agg_kernel(FP4 bias4) {
    int z = blockIdx.y;
    int wid = blockIdx.x * 8 + (threadIdx.x >> 5);
    if (wid >= NNODES * 4) return;
    const float* bias = bias4.p[z];
    const float* __restrict__ feat = g_feat[z];
    const float* __restrict__ el = G_EL(z);
    const int* __restrict__ eid = g_eid[z];
    int d = wid >> 2, strip = wid & 3;
    int lane = threadIdx.x & 31;
    int col = strip * 128 + lane * 4;
    int head = col >> 6;
    float erv = G_ER(z)[d * NHEAD + head];

    float4 acc = make_float4(0.f, 0.f, 0.f, 0.f);
    float sum_ax = 0.f;
    int b = g_off[z][d], e_ = g_off[z][d + 1];
    if (b < e_) {
        int sA = eid[b];
        int sB = (b + 1 < e_) ? eid[b + 1] : sA;
        float elA = el[sA * NHEAD + head];
        for (int i = b; i < e_; i++) {
            int sC = (i + 2 < e_) ? eid[i + 2] : sB;
            float elB = (i + 1 < e_) ? el[sB * NHEAD + head] : 0.f;
            float v = elA + erv;
            v = v > 0.f ? v : 0.2f * v;
            float ax = __expf(v);
            float4 f = *(const float4*)(feat + (size_t)sA * DDIM + col);
            acc.x += f.x * ax;
            acc.y += f.y * ax;
            acc.z += f.z * ax;
            acc.w += f.w * ax;
            sum_ax += ax;
            sA = sB; sB = sC; elA = elB;
        }
        float rcp = 1.f / sum_ax;
        acc.x *= rcp; acc.y *= rcp; acc.z *= rcp; acc.w *= rcp;
    }
    float4 bb = *(const float4*)(bias + col);
    float4 v;
    v.x = acc.x + bb.x; v.x = v.x > 0.f ? v.x : (__expf(v.x) - 1.f);
    v.y = acc.y + bb.y; v.y = v.y > 0.f ? v.y : (__expf(v.y) - 1.f);
    v.z = acc.z + bb.z; v.z = v.z > 0.f ? v.z : (__expf(v.z) - 1.f);
    v.w = acc.w + bb.w; v.w = v.w > 0.f ? v.w : (__expf(v.w) - 1.f);
    *(float4*)(g_z[z] + (size_t)d * DDIM + col) = v;
    *(uint4*)(&t_z[z][(size_t)d * DDIM + col]) =
        make_uint4(f2tf(v.x), f2tf(v.y), f2tf(v.z), f2tf(v.w));
}

// ---------------- host orchestration ----------------

extern "C" void kernel_launch(void* const* d_in, const int* in_sizes, int n_in,
                              void* d_out, int out_size) {
    float *p_feat[4], *p_gz[4];
    unsigned *p_tx[2], *p_twhw[2], *p_tfc[2], *p_tpred[2], *p_tW1[2];
    unsigned *p_tW[4], *p_tz[4], *p_th[2];
    unsigned* p_zbuf;
    {
        float* base;
        cudaGetSymbolAddress((void**)&base, g_feat);
        for (int z = 0; z < 4; z++) p_feat[z] = base + (size_t)z * NNODES * DDIM;
        cudaGetSymbolAddress((void**)&base, g_z);
        for (int z = 0; z < 4; z++) p_gz[z] = base + (size_t)z * NNODES * DDIM;
        cudaGetSymbolAddress((void**)&p_zbuf, g_zbuf);
        unsigned* ub;
        cudaGetSymbolAddress((void**)&ub, t_x);
        for (int b = 0; b < 2; b++) p_tx[b] = ub + (size_t)b * NNODES * FDIM;
        cudaGetSymbolAddress((void**)&ub, t_whw);
        for (int b = 0; b < 2; b++) p_twhw[b] = ub + (size_t)b * FDIM * FDIM;
        cudaGetSymbolAddress((void**)&ub, t_fc);
        for (int b = 0; b < 2; b++) p_tfc[b] = ub + (size_t)b * 2 * FDIM * DDIM;
        cudaGetSymbolAddress((void**)&ub, t_pred);
        for (int b = 0; b < 2; b++) p_tpred[b] = ub + (size_t)b * DDIM * OSZ;
        cudaGetSymbolAddress((void**)&ub, t_W1);
        for (int b = 0; b < 2; b++) p_tW1[b] = ub + (size_t)b * DDIM * SEMH;
        cudaGetSymbolAddress((void**)&ub, t_W);
        for (int z = 0; z < 4; z++) p_tW[z] = ub + (size_t)z * FDIM * DDIM;
        cudaGetSymbolAddress((void**)&ub, t_z);
        for (int z = 0; z < 4; z++) p_tz[z] = ub + (size_t)z * NNODES * DDIM;
        cudaGetSymbolAddress((void**)&ub, t_h);
        for (int b = 0; b < 2; b++) p_th[b] = ub + (size_t)b * NNODES * OSZ;
    }
    float* p_el[4];
    float* p_er[4];
    float* p_w[4];
    for (int z = 0; z < 4; z++) {
        p_el[z] = (float*)p_zbuf + ZW_EL + (size_t)z * NNODES * NHEAD;
        p_er[z] = (float*)p_zbuf + ZW_ER + (size_t)z * NNODES * NHEAD;
        p_w[z]  = (float*)p_zbuf + ZW_W  + (size_t)z * NNODES;
    }

    const float* hx = (const float*)d_in[0];
    const float* tx = (const float*)d_in[1];
    const float* w_h[2]  = {(const float*)d_in[2],  (const float*)d_in[11]};
    const float* fc[2]   = {(const float*)d_in[3],  (const float*)d_in[12]};
    const float* al[2]   = {(const float*)d_in[4],  (const float*)d_in[13]};
    const float* ar[2]   = {(const float*)d_in[5],  (const float*)d_in[14]};
    const float* bias[2] = {(const float*)d_in[6],  (const float*)d_in[15]};
    const float* W1[2]   = {(const float*)d_in[7],  (const float*)d_in[16]};
    const float* b1[2]   = {(const float*)d_in[8],  (const float*)d_in[17]};
    const float* W2[2]   = {(const float*)d_in[9],  (const float*)d_in[18]};
    const float* pred[2] = {(const float*)d_in[10], (const float*)d_in[19]};

    IP4 ed4 = {{(const int*)d_in[20], (const int*)d_in[21],
                (const int*)d_in[22], (const int*)d_in[23]}};
    FP4 bias4 = {{bias[0], bias[0] + DDIM, bias[1], bias[1] + DDIM}};

    float* out  = (float*)d_out;
    float* h1   = out;
    float* h2   = out + (size_t)NNODES * OSZ;
    float* prod = out + (size_t)2 * NNODES * OSZ;

    const int SM_NN4 = 4 * (128 * 20 + 16 * 136) * 4;   // 75776
    const int SM_NT  = 4 * (128 * 20 + 128 * 20) * 4;   // 81920
    cudaFuncSetAttribute(mma_gemm_async<4, false, 1>,
                         cudaFuncAttributeMaxDynamicSharedMemorySize, SM_NN4);
    cudaFuncSetAttribute(mma_gemm_async<4, false, 4>,
                         cudaFuncAttributeMaxDynamicSharedMemorySize, SM_NN4);
    cudaFuncSetAttribute(mma_gemm_async<4, false, 5>,
                         cudaFuncAttributeMaxDynamicSharedMemorySize, SM_NN4);
    cudaFuncSetAttribute(mma_gemm_async<4, true, 3>,
                         cudaFuncAttributeMaxDynamicSharedMemorySize, SM_NT);

    // 0) single clear of accumulators; CSR build; one-shot tf32 conversion
    cudaMemsetAsync(p_zbuf, 0, ZW_TOT * sizeof(unsigned), 0);
    count_kernel<<<dim3((NEDGE + 255) / 256, 4), 256>>>(ed4);
    scan_kernel<<<4, 1024>>>();
    scatter_kernel<<<dim3((NEDGE + 255) / 256, 4), 256>>>(ed4);
    {
        CVT c = {};
        c.src[0] = hx;      c.dst[0] = p_tx[0];    c.n4[0] = NNODES * FDIM / 4;
        c.src[1] = tx;      c.dst[1] = p_tx[1];    c.n4[1] = NNODES * FDIM / 4;
        c.src[2] = w_h[0];  c.dst[2] = p_twhw[0];  c.n4[2] = FDIM * FDIM / 4;
        c.src[3] = w_h[1];  c.dst[3] = p_twhw[1];  c.n4[3] = FDIM * FDIM / 4;
        c.src[4] = fc[0];   c.dst[4] = p_tfc[0];   c.n4[4] = 2 * FDIM * DDIM / 4;
        c.src[5] = fc[1];   c.dst[5] = p_tfc[1];   c.n4[5] = 2 * FDIM * DDIM / 4;
        c.src[6] = pred[0]; c.dst[6] = p_tpred[0]; c.n4[6] = DDIM * OSZ / 4;
        c.src[7] = pred[1]; c.dst[7] = p_tpred[1]; c.n4[7] = DDIM * OSZ / 4;
        c.src[8] = W1[0];   c.dst[8] = p_tW1[0];   c.n4[8] = DDIM * SEMH / 4;
        c.src[9] = W1[1];   c.dst[9] = p_tW1[1];   c.n4[9] = DDIM * SEMH / 4;
        cvt_kernel<<<dim3(640, 10), 256>>>(c);
    }

    // 1) combined weights W[z] = w_h[b] @ fc[b][m]
    {
        GB gb = {};
        for (int z = 0; z < 4; z++) {
            gb.A[z] = p_twhw[z >> 1];
            gb.B[z] = p_tfc[z >> 1] + (size_t)(z & 1) * FDIM * DDIM;
            gb.C[z] = p_tW[z];
        }
        dim3 g(DDIM / 128, FDIM / 128, 4);
        mma_gemm_async<4, false, 1><<<g, 256, SM_NN4>>>(gb, FDIM, DDIM, FDIM);
    }
    // 2) feat = x @ W  (batched x4, fused el/er epilogue)
    {
        GB gb = {};
        for (int z = 0; z < 4; z++) {
            gb.A[z] = p_tx[z >> 1];
            gb.B[z] = p_tW[z];
            gb.C[z] = p_feat[z];
            gb.AL[z] = (z & 2) ? (al[1] + (z & 1) * NHEAD * 64) : (al[0] + (z & 1) * NHEAD * 64);
            gb.AR[z] = (z & 2) ? (ar[1] + (z & 1) * NHEAD * 64) : (ar[0] + (z & 1) * NHEAD * 64);
            gb.EL[z] = p_el[z];
            gb.ER[z] = p_er[z];
        }
        dim3 g(DDIM / 128, (NNODES + 127) / 128, 4);
        mma_gemm_async<4, false, 4><<<g, 256, SM_NN4>>>(gb, NNODES, DDIM, FDIM);
    }
    // 3) aggregate (x4; softmax exp inline)
    agg_kernel<<<dim3((NNODES * 4 + 7) / 8, 4), 256>>>(bias4);

    // 4) semantic attention GEMM with fused score epilogue (x4, BM=128)
    {
        GB gb = {};
        for (int z = 0; z < 4; z++) {
            gb.A[z] = p_tz[z];
            gb.B[z] = p_tW1[z >> 1];
            gb.B1[z] = b1[z >> 1];
            gb.W2p[z] = W2[z >> 1];
            gb.WO[z] = p_w[z];
        }
        dim3 g(1, (NNODES + 127) / 128, 4);
        mma_gemm_async<4, false, 5><<<g, 256, SM_NN4>>>(gb, NNODES, SEMH, DDIM);
    }

    // 5) prediction heads with fused metapath fusion (batched x2)
    {
        PG pg = {};
        for (int b = 0; b < 2; b++) {
            pg.z0[b] = p_gz[2 * b];
            pg.z1[b] = p_gz[2 * b + 1];
            pg.w0[b] = p_w[2 * b];
            pg.w1[b] = p_w[2 * b + 1];
            pg.B[b]  = p_tpred[b];
            pg.C[b]  = (b == 0) ? h1 : h2;
            pg.C2[b] = p_th[b];
        }
        dim3 g(1, (NNODES + 63) / 64, 2);
        pred_fused_kernel<<<g, 256>>>(pg, NNODES, OSZ, DDIM);
    }
    // 6) prod = h1 @ h2^T (tf32 copies, streaming stores, ldmatrix A+B)
    {
        GB gb = {};
        gb.A[0] = p_th[0]; gb.B[0] = p_th[1]; gb.C[0] = prod;
        dim3 g((NNODES + 127) / 128, (NNODES + 127) / 128, 1);
        mma_gemm_async<4, true, 3><<<g, 256, SM_NT>>>(gb, NNODES, NNODES, OSZ);
    }
}

// round 16
// speedup vs baseline: 4.9763x; 1.0336x over previous
#include <cuda_runtime.h>
#include <cstdint>

#define NNODES 10000
#define FDIM   256
#define DDIM   512
#define NEDGE  160000
#define NHEAD  8
#define SEMH   128
#define OSZ    64

// ---------------- scratch (static device globals; no allocation) ----------------
__device__ float g_feat[4][NNODES * DDIM];
__device__ float g_z   [4][NNODES * DDIM];
__device__ int   g_off [4][NNODES + 1];
__device__ int   g_eid [4][NEDGE];

// one contiguous zero-initialized accumulator region (single memset)
#define ZW_CUR 0
#define ZW_EL  (4 * NNODES)
#define ZW_ER  (ZW_EL + 4 * NNODES * NHEAD)
#define ZW_W   (ZW_ER + 4 * NNODES * NHEAD)
#define ZW_TOT (ZW_W + 4 * NNODES)
__device__ unsigned g_zbuf[ZW_TOT];
#define G_CUR(z) ((int*)g_zbuf + (z) * NNODES)
#define G_EL(z)  ((float*)g_zbuf + ZW_EL + (z) * NNODES * NHEAD)
#define G_ER(z)  ((float*)g_zbuf + ZW_ER + (z) * NNODES * NHEAD)
#define G_W(z)   ((float*)g_zbuf + ZW_W + (z) * NNODES)

// tf32-at-rest operands (bits stored as unsigned)
__device__ unsigned t_x   [2][NNODES * FDIM];
__device__ unsigned t_whw [2][FDIM * FDIM];
__device__ unsigned t_fc  [2][2 * FDIM * DDIM];
__device__ unsigned t_pred[2][DDIM * OSZ];
__device__ unsigned t_W1  [2][DDIM * SEMH];
__device__ unsigned t_W   [4][FDIM * DDIM];
__device__ unsigned t_z   [4][NNODES * DDIM];
__device__ unsigned t_h   [2][NNODES * OSZ];

struct GB {
    const void* A[4]; const void* B[4]; void* C[4]; void* C2[4];
    const float* AL[4]; const float* AR[4]; float* EL[4]; float* ER[4];
    const float* B1[4]; const float* W2p[4]; float* WO[4];
};
struct PG {
    const float* z0[2]; const float* z1[2]; const float* w0[2]; const float* w1[2];
    const unsigned* B[2]; float* C[2]; unsigned* C2[2];
};
struct IP4  { const int*   p[4]; };
struct FP4  { const float* p[4]; };
struct CVT  { const float* src[10]; unsigned* dst[10]; int n4[10]; };

__device__ __forceinline__ unsigned f2tf(float f) {
    unsigned r;
    asm("cvt.rna.tf32.f32 %0, %1;" : "=r"(r) : "f"(f));
    return r;
}

// ---------------- one-shot f32 -> tf32 conversion ----------
__global__ void cvt_kernel(CVT c) {
    int seg = blockIdx.y;
    int n4 = c.n4[seg];
    const float4* s = (const float4*)c.src[seg];
    uint4* d = (uint4*)c.dst[seg];
    for (int i = blockIdx.x * 256 + threadIdx.x; i < n4; i += gridDim.x * 256) {
        float4 v = s[i];
        d[i] = make_uint4(f2tf(v.x), f2tf(v.y), f2tf(v.z), f2tf(v.w));
    }
}

// ---------------- async tf32 MMA GEMM: cp.async 4-stage, z-batched -----------
// EPI: 0 f32 C; 1 tf32 C; 2 f32 C + tf32 C2; 3 f32 streaming;
//      4 f32 C + fused el/er; 5 fused semantic score (no C store).

template<int MT, bool TRANSB, int EPI>
__global__ __launch_bounds__(256, 2) void mma_gemm_async(GB gb, int M, int N, int K) {
    constexpr int S  = 4;
    constexpr int BM = 32 * MT;
    constexpr int PA = 20;
    constexpr int PB = TRANSB ? 20 : 136;
    constexpr int AW = BM * PA;
    constexpr int BW = TRANSB ? 128 * PB : 16 * PB;
    constexpr int AQ = BM / 64;
    extern __shared__ unsigned smem[];

    const unsigned* __restrict__ A = (const unsigned*)gb.A[blockIdx.z];
    const unsigned* __restrict__ B = (const unsigned*)gb.B[blockIdx.z];
    float* C = (float*)gb.C[blockIdx.z];
    unsigned* C2 = (unsigned*)gb.C2[blockIdx.z];

    int tid = threadIdx.x, warp = tid >> 5, lane = tid & 31;
    int wm = warp >> 2, wn = warp & 3;
    int row0 = blockIdx.y * BM, col0 = blockIdx.x * 128;
    int nk = K >> 4;
    unsigned sbase = (unsigned)__cvta_generic_to_shared(smem);

    auto issue = [&](int t) {
        int k0 = t * 16, buf = t & (S - 1);
#pragma unroll
        for (int j = 0; j < AQ; j++) {
            int i = tid + j * 256;
            int r = i >> 2, c4 = i & 3;
            int gr = row0 + r;
            int sz = 16;
            if (gr >= M) { sz = 0; gr = row0; }
            unsigned sd = sbase + ((buf * AW + r * PA + c4 * 4) << 2);
            asm volatile("cp.async.cg.shared.global [%0], [%1], 16, %2;"
                         :: "r"(sd), "l"(A + (size_t)gr * K + k0 + c4 * 4), "r"(sz));
        }
#pragma unroll
        for (int j = 0; j < 2; j++) {
            int i = tid + j * 256;
            const unsigned* src;
            int dstw, sz = 16;
            if (!TRANSB) {
                int k = i >> 5, c4 = i & 31;
                int gc = col0 + c4 * 4;
                if (gc >= N) { sz = 0; gc = col0; }
                src = B + (size_t)(k0 + k) * N + gc;
                dstw = k * PB + c4 * 4;
            } else {
                int n = i >> 2, c4 = i & 3;
                int gn = col0 + n;
                if (gn >= N) { sz = 0; gn = col0; }
                src = B + (size_t)gn * K + k0 + c4 * 4;
                dstw = n * PB + c4 * 4;
            }
            unsigned sd = sbase + ((S * AW + buf * BW + dstw) << 2);
            asm volatile("cp.async.cg.shared.global [%0], [%1], 16, %2;"
                         :: "r"(sd), "l"(src), "r"(sz));
        }
    };

    float acc[MT][4][4];
#pragma unroll
    for (int i = 0; i < MT; i++)
#pragma unroll
        for (int j = 0; j < 4; j++)
#pragma unroll
            for (int q = 0; q < 4; q++) acc[i][j][q] = 0.f;

#pragma unroll
    for (int t = 0; t < S - 1; t++) {
        if (t < nk) issue(t);
        asm volatile("cp.async.commit_group;");
    }

    const unsigned aLdm = ((wm * MT * 16 + (lane & 15)) * PA + (lane >> 4) * 4) << 2;
    const unsigned bLdm = TRANSB
        ? (((wn * 32 + (lane & 7) + ((lane >> 4) & 1) * 8) * PB + ((lane >> 3) & 1) * 4) << 2)
        : 0u;
    const int bB0 = (lane & 3) * PB + wn * 32 + (lane >> 2);

    for (int t = 0; t < nk; t++) {
        int buf = t & (S - 1);
        asm volatile("cp.async.wait_group %0;" :: "n"(S - 2));
        __syncthreads();
        if (t + S - 1 < nk) issue(t + S - 1);
        asm volatile("cp.async.commit_group;");

#pragma unroll
        for (int ks = 0; ks < 2; ks++) {
            unsigned af[MT][4];
            unsigned bf[4][2];
            unsigned aAddr = sbase + ((buf * AW) << 2) + aLdm + ((ks * 8) << 2);
#pragma unroll
            for (int mt = 0; mt < MT; mt++) {
                asm volatile("ldmatrix.sync.aligned.m8n8.x4.shared.b16 "
                             "{%0,%1,%2,%3}, [%4];"
                             : "=r"(af[mt][0]), "=r"(af[mt][1]),
                               "=r"(af[mt][2]), "=r"(af[mt][3])
                             : "r"(aAddr + ((mt * 16 * PA) << 2)));
            }
            if (TRANSB) {
                unsigned bAddr = sbase + ((S * AW + buf * BW) << 2) + bLdm + ((ks * 8) << 2);
#pragma unroll
                for (int p = 0; p < 2; p++) {
                    asm volatile("ldmatrix.sync.aligned.m8n8.x4.shared.b16 "
                                 "{%0,%1,%2,%3}, [%4];"
                                 : "=r"(bf[2 * p][0]), "=r"(bf[2 * p][1]),
                                   "=r"(bf[2 * p + 1][0]), "=r"(bf[2 * p + 1][1])
                                 : "r"(bAddr + ((p * 16 * PB) << 2)));
                }
            } else {
                const unsigned* bp = smem + S * AW + buf * BW + bB0;
#pragma unroll
                for (int nt = 0; nt < 4; nt++) {
                    const unsigned* p = bp + ks * 8 * PB + nt * 8;
                    bf[nt][0] = p[0];
                    bf[nt][1] = p[4 * PB];
                }
            }
#pragma unroll
            for (int mt = 0; mt < MT; mt++)
#pragma unroll
                for (int nt = 0; nt < 4; nt++) {
                    asm volatile(
                        "mma.sync.aligned.m16n8k8.row.col.f32.tf32.tf32.f32 "
                        "{%0,%1,%2,%3}, {%4,%5,%6,%7}, {%8,%9}, {%0,%1,%2,%3};"
                        : "+f"(acc[mt][nt][0]), "+f"(acc[mt][nt][1]),
                          "+f"(acc[mt][nt][2]), "+f"(acc[mt][nt][3])
                        : "r"(af[mt][0]), "r"(af[mt][1]), "r"(af[mt][2]), "r"(af[mt][3]),
                          "r"(bf[nt][0]), "r"(bf[nt][1]));
                }
        }
    }

    // ---------------- epilogue ----------------
    if (EPI != 5) {
#pragma unroll
        for (int mt = 0; mt < MT; mt++) {
            int r0 = row0 + wm * (MT * 16) + mt * 16 + (lane >> 2);
#pragma unroll
            for (int nt = 0; nt < 4; nt++) {
                int c = col0 + wn * 32 + nt * 8 + (lane & 3) * 2;
                if (c < N) {
#pragma unroll
                    for (int h = 0; h < 2; h++) {
                        int r = r0 + h * 8;
                        if (r < M) {
                            float v0 = acc[mt][nt][2 * h], v1 = acc[mt][nt][2 * h + 1];
                            if (EPI == 0 || EPI == 2 || EPI == 4)
                                *(float2*)(C + (size_t)r * N + c) = make_float2(v0, v1);
                            if (EPI == 3)
                                asm volatile("st.global.cs.v2.f32 [%0], {%1,%2};"
                                             :: "l"(C + (size_t)r * N + c), "f"(v0), "f"(v1)
                                             : "memory");
                            if (EPI == 1)
                                *(uint2*)((unsigned*)C + (size_t)r * N + c) =
                                    make_uint2(f2tf(v0), f2tf(v1));
                            if (EPI == 2)
                                *(uint2*)(C2 + (size_t)r * N + c) =
                                    make_uint2(f2tf(v0), f2tf(v1));
                        }
                    }
                }
            }
        }
    }
    if (EPI == 4) {
        int head = (col0 >> 6) + (wn >> 1);
        const float* al = gb.AL[blockIdx.z] + head * 64;
        const float* ar = gb.AR[blockIdx.z] + head * 64;
        float alv[4][2], arv[4][2];
#pragma unroll
        for (int nt = 0; nt < 4; nt++) {
            int cc = (wn & 1) * 32 + nt * 8 + (lane & 3) * 2;
            alv[nt][0] = al[cc];     alv[nt][1] = al[cc + 1];
            arv[nt][0] = ar[cc];     arv[nt][1] = ar[cc + 1];
        }
        float* ELp = gb.EL[blockIdx.z];
        float* ERp = gb.ER[blockIdx.z];
#pragma unroll
        for (int mt = 0; mt < MT; mt++) {
            int r0 = row0 + wm * (MT * 16) + mt * 16 + (lane >> 2);
#pragma unroll
            for (int h = 0; h < 2; h++) {
                float ep = 0.f, rp = 0.f;
#pragma unroll
                for (int nt = 0; nt < 4; nt++) {
                    ep += acc[mt][nt][2 * h] * alv[nt][0] + acc[mt][nt][2 * h + 1] * alv[nt][1];
                    rp += acc[mt][nt][2 * h] * arv[nt][0] + acc[mt][nt][2 * h + 1] * arv[nt][1];
                }
                ep += __shfl_xor_sync(0xffffffffu, ep, 1);
                ep += __shfl_xor_sync(0xffffffffu, ep, 2);
                rp += __shfl_xor_sync(0xffffffffu, rp, 1);
                rp += __shfl_xor_sync(0xffffffffu, rp, 2);
                int r = r0 + h * 8;
                if ((lane & 3) == 0 && r < M) {
                    atomicAdd(&ELp[r * NHEAD + head], ep);
                    atomicAdd(&ERp[r * NHEAD + head], rp);
                }
            }
        }
    }
    if (EPI == 5) {
        const float* b1 = gb.B1[blockIdx.z];
        const float* W2 = gb.W2p[blockIdx.z];
        float b1v[4][2], w2v[4][2];
#pragma unroll
        for (int nt = 0; nt < 4; nt++) {
            int cc = wn * 32 + nt * 8 + (lane & 3) * 2;
            b1v[nt][0] = b1[cc];     b1v[nt][1] = b1[cc + 1];
            w2v[nt][0] = W2[cc];     w2v[nt][1] = W2[cc + 1];
        }
        float* wout = gb.WO[blockIdx.z];
#pragma unroll
        for (int mt = 0; mt < MT; mt++) {
            int r0 = row0 + wm * (MT * 16) + mt * 16 + (lane >> 2);
#pragma unroll
            for (int h = 0; h < 2; h++) {
                float s = 0.f;
#pragma unroll
                for (int nt = 0; nt < 4; nt++) {
                    s += tanhf(acc[mt][nt][2 * h]     + b1v[nt][0]) * w2v[nt][0];
                    s += tanhf(acc[mt][nt][2 * h + 1] + b1v[nt][1]) * w2v[nt][1];
                }
                s += __shfl_xor_sync(0xffffffffu, s, 1);
                s += __shfl_xor_sync(0xffffffffu, s, 2);
                int r = r0 + h * 8;
                if ((lane & 3) == 0 && r < M) atomicAdd(&wout[r], s);
            }
        }
    }
}

// ---------------- pred GEMM with fused metapath fusion in A-staging ----------
__global__ __launch_bounds__(256, 2) void pred_fused_kernel(PG pg, int M, int N, int K) {
    constexpr int PA = 20;
    constexpr int PB = 136;
    __shared__ unsigned sA[2][64 * PA];
    __shared__ unsigned sB[2][16 * PB];
    __shared__ float sbe[64];

    int b = blockIdx.z;
    const float* __restrict__ Z0 = pg.z0[b];
    const float* __restrict__ Z1 = pg.z1[b];
    const unsigned* __restrict__ B = pg.B[b];
    float* C = pg.C[b];
    unsigned* C2 = pg.C2[b];

    int tid = threadIdx.x, warp = tid >> 5, lane = tid & 31;
    int wm = warp >> 2, wn = warp & 3;
    int row0 = blockIdx.y * 64, col0 = 0;
    int nk = K >> 4;

    if (tid < 64) {
        int r = row0 + tid;
        float be = 0.f;
        if (r < M) {
            float a = pg.w0[b][r], c = pg.w1[b][r];
            float m = fmaxf(a, c);
            float ea = __expf(a - m), eb = __expf(c - m);
            be = ea / (ea + eb);
        }
        sbe[tid] = be;
    }
    __syncthreads();

    float4 r0v, r1v;
    uint4 rbv[2];
    auto loadT = [&](int k0) {
        int r = tid >> 2, c4 = tid & 3;
        int gr = row0 + r;
        r0v = make_float4(0.f, 0.f, 0.f, 0.f);
        r1v = r0v;
        if (gr < M) {
            r0v = *(const float4*)(Z0 + (size_t)gr * K + k0 + c4 * 4);
            r1v = *(const float4*)(Z1 + (size_t)gr * K + k0 + c4 * 4);
        }
#pragma unroll
        for (int j = 0; j < 2; j++) {
            int i = tid + j * 256;
            int k = i >> 5, c4b = i & 31;
            int gc = col0 + c4b * 4;
            rbv[j] = make_uint4(0, 0, 0, 0);
            if (gc < N) rbv[j] = *(const uint4*)(B + (size_t)(k0 + k) * N + gc);
        }
    };
    auto storeT = [&](int buf) {
        int r = tid >> 2, c4 = tid & 3;
        float be = sbe[r], ne = 1.f - be;
        uint4 u = make_uint4(f2tf(be * r0v.x + ne * r1v.x),
                             f2tf(be * r0v.y + ne * r1v.y),
                             f2tf(be * r0v.z + ne * r1v.z),
                             f2tf(be * r0v.w + ne * r1v.w));
        *(uint4*)&sA[buf][r * PA + c4 * 4] = u;
#pragma unroll
        for (int j = 0; j < 2; j++) {
            int i = tid + j * 256;
            int k = i >> 5, c4b = i & 31;
            *(uint4*)&sB[buf][k * PB + c4b * 4] = rbv[j];
        }
    };

    float acc[2][4][4];
#pragma unroll
    for (int i = 0; i < 2; i++)
#pragma unroll
        for (int j = 0; j < 4; j++)
#pragma unroll
            for (int q = 0; q < 4; q++) acc[i][j][q] = 0.f;

    unsigned sbaseA = (unsigned)__cvta_generic_to_shared(&sA[0][0]);
    const unsigned aLdm = ((wm * 32 + (lane & 15)) * PA + (lane >> 4) * 4) << 2;
    const int bB0 = (lane & 3) * PB + wn * 32 + (lane >> 2);

    loadT(0);
    storeT(0);
    __syncthreads();

    for (int t = 0; t < nk; t++) {
        int buf = t & 1;
        if (t + 1 < nk) loadT((t + 1) * 16);

#pragma unroll
        for (int ks = 0; ks < 2; ks++) {
            unsigned af[2][4];
            unsigned bf[4][2];
            unsigned aAddr = sbaseA + ((buf * 64 * PA) << 2) + aLdm + ((ks * 8) << 2);
#pragma unroll
            for (int mt = 0; mt < 2; mt++) {
                asm volatile("ldmatrix.sync.aligned.m8n8.x4.shared.b16 "
                             "{%0,%1,%2,%3}, [%4];"
                             : "=r"(af[mt][0]), "=r"(af[mt][1]),
                               "=r"(af[mt][2]), "=r"(af[mt][3])
                             : "r"(aAddr + ((mt * 16 * PA) << 2)));
            }
            const unsigned* bp = &sB[buf][bB0];
#pragma unroll
            for (int nt = 0; nt < 4; nt++) {
                const unsigned* p = bp + ks * 8 * PB + nt * 8;
                bf[nt][0] = p[0];
                bf[nt][1] = p[4 * PB];
            }
#pragma unroll
            for (int mt = 0; mt < 2; mt++)
#pragma unroll
                for (int nt = 0; nt < 4; nt++) {
                    asm volatile(
                        "mma.sync.aligned.m16n8k8.row.col.f32.tf32.tf32.f32 "
                        "{%0,%1,%2,%3}, {%4,%5,%6,%7}, {%8,%9}, {%0,%1,%2,%3};"
                        : "+f"(acc[mt][nt][0]), "+f"(acc[mt][nt][1]),
                          "+f"(acc[mt][nt][2]), "+f"(acc[mt][nt][3])
                        : "r"(af[mt][0]), "r"(af[mt][1]), "r"(af[mt][2]), "r"(af[mt][3]),
                          "r"(bf[nt][0]), "r"(bf[nt][1]));
                }
        }
        if (t + 1 < nk) storeT(buf ^ 1);
        __syncthreads();
    }

#pragma unroll
    for (int mt = 0; mt < 2; mt++) {
        int r0 = row0 + wm * 32 + mt * 16 + (lane >> 2);
#pragma unroll
        for (int nt = 0; nt < 4; nt++) {
            int c = col0 + wn * 32 + nt * 8 + (lane & 3) * 2;
            if (c < N) {
#pragma unroll
                for (int h = 0; h < 2; h++) {
                    int r = r0 + h * 8;
                    if (r < M) {
                        float v0 = acc[mt][nt][2 * h], v1 = acc[mt][nt][2 * h + 1];
                        *(float2*)(C + (size_t)r * N + c) = make_float2(v0, v1);
                        *(uint2*)(C2 + (size_t)r * N + c) =
                            make_uint2(f2tf(v0), f2tf(v1));
                    }
                }
            }
        }
    }
}

// ---------------- GAT kernels (grid.y = instance z) ----------------

__global__ void count_kernel(IP4 ed4) {
    int z = blockIdx.y;
    int i = blockIdx.x * blockDim.x + threadIdx.x;
    if (i >= NEDGE) return;
    atomicAdd(&G_CUR(z)[ed4.p[z][NEDGE + i]], 1);
}

__global__ void scan_kernel() {
    int z = blockIdx.x;
    int* cur = G_CUR(z);
    int* off = g_off[z];
    __shared__ int part[1024];
    int t = threadIdx.x;
    int base = t * 10;
    int v[10];
    int s = 0;
#pragma unroll
    for (int j = 0; j < 10; j++) {
        int idx = base + j;
        int c = (idx < NNODES) ? cur[idx] : 0;
        v[j] = c;
        s += c;
    }
    part[t] = s;
    __syncthreads();
    for (int o = 1; o < 1024; o <<= 1) {
        int x = (t >= o) ? part[t - o] : 0;
        __syncthreads();
        part[t] += x;
        __syncthreads();
    }
    int run = (t > 0) ? part[t - 1] : 0;
#pragma unroll
    for (int j = 0; j < 10; j++) {
        int idx = base + j;
        if (idx < NNODES) {
            off[idx] = run;
            cur[idx] = run;
            run += v[j];
        }
    }
    if (t == 0) off[NNODES] = NEDGE;
}

__global__ void scatter_kernel(IP4 ed4) {
    int z = blockIdx.y;
    int i = blockIdx.x * blockDim.x + threadIdx.x;
    if (i >= NEDGE) return;
    const int* ed = ed4.p[z];
    int d = ed[NEDGE + i];
    int p = atomicAdd(&G_CUR(z)[d], 1);
    g_eid[z][p] = ed[i];
}

// gather-aggregate with inline softmax exp + end normalization; bias+ELU fused.
__global__ __launch_bounds__(256) void agg_kernel(FP4 bias4) {
    int z = blockIdx.y;
    int wid = blockIdx.x * 8 + (threadIdx.x >> 5);
    if (wid >= NNODES * 4) return;
    const float* bias = bias4.p[z];
    const float* __restrict__ feat = g_feat[z];
    const float* __restrict__ el = G_EL(z);
    const int* __restrict__ eid = g_eid[z];
    int d = wid >> 2, strip = wid & 3;
    int lane = threadIdx.x & 31;
    int col = strip * 128 + lane * 4;
    int head = col >> 6;
    float erv = G_ER(z)[d * NHEAD + head];

    float4 acc = make_float4(0.f, 0.f, 0.f, 0.f);
    float sum_ax = 0.f;
    int b = g_off[z][d], e_ = g_off[z][d + 1];
    if (b < e_) {
        int sA = eid[b];
        int sB = (b + 1 < e_) ? eid[b + 1] : sA;
        float elA = el[sA * NHEAD + head];
        for (int i = b; i < e_; i++) {
            int sC = (i + 2 < e_) ? eid[i + 2] : sB;
            float elB = (i + 1 < e_) ? el[sB * NHEAD + head] : 0.f;
            float v = elA + erv;
            v = v > 0.f ? v : 0.2f * v;
            float ax = __expf(v);
            float4 f = *(const float4*)(feat + (size_t)sA * DDIM + col);
            acc.x += f.x * ax;
            acc.y += f.y * ax;
            acc.z += f.z * ax;
            acc.w += f.w * ax;
            sum_ax += ax;
            sA = sB; sB = sC; elA = elB;
        }
        float rcp = 1.f / sum_ax;
        acc.x *= rcp; acc.y *= rcp; acc.z *= rcp; acc.w *= rcp;
    }
    float4 bb = *(const float4*)(bias + col);
    float4 v;
    v.x = acc.x + bb.x; v.x = v.x > 0.f ? v.x : (__expf(v.x) - 1.f);
    v.y = acc.y + bb.y; v.y = v.y > 0.f ? v.y : (__expf(v.y) - 1.f);
    v.z = acc.z + bb.z; v.z = v.z > 0.f ? v.z : (__expf(v.z) - 1.f);
    v.w = acc.w + bb.w; v.w = v.w > 0.f ? v.w : (__expf(v.w) - 1.f);
    *(float4*)(g_z[z] + (size_t)d * DDIM + col) = v;
    *(uint4*)(&t_z[z][(size_t)d * DDIM + col]) =
        make_uint4(f2tf(v.x), f2tf(v.y), f2tf(v.z), f2tf(v.w));
}

// ---------------- host orchestration ----------------

extern "C" void kernel_launch(void* const* d_in, const int* in_sizes, int n_in,
                              void* d_out, int out_size) {
    // side stream + fork/join events (created once, on the uncaptured
    // correctness call; reused by the capture call — capture-legal pattern)
    static cudaStream_t s_csr = nullptr;
    static cudaEvent_t ev_fork = nullptr, ev_join = nullptr;
    if (!s_csr) {
        cudaStreamCreateWithFlags(&s_csr, cudaStreamNonBlocking);
        cudaEventCreateWithFlags(&ev_fork, cudaEventDisableTiming);
        cudaEventCreateWithFlags(&ev_join, cudaEventDisableTiming);
    }

    float *p_feat[4], *p_gz[4];
    unsigned *p_tx[2], *p_twhw[2], *p_tfc[2], *p_tpred[2], *p_tW1[2];
    unsigned *p_tW[4], *p_tz[4], *p_th[2];
    unsigned* p_zbuf;
    {
        float* base;
        cudaGetSymbolAddress((void**)&base, g_feat);
        for (int z = 0; z < 4; z++) p_feat[z] = base + (size_t)z * NNODES * DDIM;
        cudaGetSymbolAddress((void**)&base, g_z);
        for (int z = 0; z < 4; z++) p_gz[z] = base + (size_t)z * NNODES * DDIM;
        cudaGetSymbolAddress((void**)&p_zbuf, g_zbuf);
        unsigned* ub;
        cudaGetSymbolAddress((void**)&ub, t_x);
        for (int b = 0; b < 2; b++) p_tx[b] = ub + (size_t)b * NNODES * FDIM;
        cudaGetSymbolAddress((void**)&ub, t_whw);
        for (int b = 0; b < 2; b++) p_twhw[b] = ub + (size_t)b * FDIM * FDIM;
        cudaGetSymbolAddress((void**)&ub, t_fc);
        for (int b = 0; b < 2; b++) p_tfc[b] = ub + (size_t)b * 2 * FDIM * DDIM;
        cudaGetSymbolAddress((void**)&ub, t_pred);
        for (int b = 0; b < 2; b++) p_tpred[b] = ub + (size_t)b * DDIM * OSZ;
        cudaGetSymbolAddress((void**)&ub, t_W1);
        for (int b = 0; b < 2; b++) p_tW1[b] = ub + (size_t)b * DDIM * SEMH;
        cudaGetSymbolAddress((void**)&ub, t_W);
        for (int z = 0; z < 4; z++) p_tW[z] = ub + (size_t)z * FDIM * DDIM;
        cudaGetSymbolAddress((void**)&ub, t_z);
        for (int z = 0; z < 4; z++) p_tz[z] = ub + (size_t)z * NNODES * DDIM;
        cudaGetSymbolAddress((void**)&ub, t_h);
        for (int b = 0; b < 2; b++) p_th[b] = ub + (size_t)b * NNODES * OSZ;
    }
    float* p_el[4];
    float* p_er[4];
    float* p_w[4];
    for (int z = 0; z < 4; z++) {
        p_el[z] = (float*)p_zbuf + ZW_EL + (size_t)z * NNODES * NHEAD;
        p_er[z] = (float*)p_zbuf + ZW_ER + (size_t)z * NNODES * NHEAD;
        p_w[z]  = (float*)p_zbuf + ZW_W  + (size_t)z * NNODES;
    }

    const float* hx = (const float*)d_in[0];
    const float* tx = (const float*)d_in[1];
    const float* w_h[2]  = {(const float*)d_in[2],  (const float*)d_in[11]};
    const float* fc[2]   = {(const float*)d_in[3],  (const float*)d_in[12]};
    const float* al[2]   = {(const float*)d_in[4],  (const float*)d_in[13]};
    const float* ar[2]   = {(const float*)d_in[5],  (const float*)d_in[14]};
    const float* bias[2] = {(const float*)d_in[6],  (const float*)d_in[15]};
    const float* W1[2]   = {(const float*)d_in[7],  (const float*)d_in[16]};
    const float* b1[2]   = {(const float*)d_in[8],  (const float*)d_in[17]};
    const float* W2[2]   = {(const float*)d_in[9],  (const float*)d_in[18]};
    const float* pred[2] = {(const float*)d_in[10], (const float*)d_in[19]};

    IP4 ed4 = {{(const int*)d_in[20], (const int*)d_in[21],
                (const int*)d_in[22], (const int*)d_in[23]}};
    FP4 bias4 = {{bias[0], bias[0] + DDIM, bias[1], bias[1] + DDIM}};

    float* out  = (float*)d_out;
    float* h1   = out;
    float* h2   = out + (size_t)NNODES * OSZ;
    float* prod = out + (size_t)2 * NNODES * OSZ;

    const int SM_NN4 = 4 * (128 * 20 + 16 * 136) * 4;   // 75776
    const int SM_NT  = 4 * (128 * 20 + 128 * 20) * 4;   // 81920
    cudaFuncSetAttribute(mma_gemm_async<4, false, 1>,
                         cudaFuncAttributeMaxDynamicSharedMemorySize, SM_NN4);
    cudaFuncSetAttribute(mma_gemm_async<4, false, 4>,
                         cudaFuncAttributeMaxDynamicSharedMemorySize, SM_NN4);
    cudaFuncSetAttribute(mma_gemm_async<4, false, 5>,
                         cudaFuncAttributeMaxDynamicSharedMemorySize, SM_NN4);
    cudaFuncSetAttribute(mma_gemm_async<4, true, 3>,
                         cudaFuncAttributeMaxDynamicSharedMemorySize, SM_NT);

    // 0) clear accumulators, then FORK: CSR build on side stream,
    //    cvt + W-combine + feat GEMM on the main stream.
    cudaMemsetAsync(p_zbuf, 0, ZW_TOT * sizeof(unsigned), 0);
    cudaEventRecord(ev_fork, 0);
    cudaStreamWaitEvent(s_csr, ev_fork, 0);
    count_kernel<<<dim3((NEDGE + 255) / 256, 4), 256, 0, s_csr>>>(ed4);
    scan_kernel<<<4, 1024, 0, s_csr>>>();
    scatter_kernel<<<dim3((NEDGE + 255) / 256, 4), 256, 0, s_csr>>>(ed4);
    cudaEventRecord(ev_join, s_csr);

    {
        CVT c = {};
        c.src[0] = hx;      c.dst[0] = p_tx[0];    c.n4[0] = NNODES * FDIM / 4;
        c.src[1] = tx;      c.dst[1] = p_tx[1];    c.n4[1] = NNODES * FDIM / 4;
        c.src[2] = w_h[0];  c.dst[2] = p_twhw[0];  c.n4[2] = FDIM * FDIM / 4;
        c.src[3] = w_h[1];  c.dst[3] = p_twhw[1];  c.n4[3] = FDIM * FDIM / 4;
        c.src[4] = fc[0];   c.dst[4] = p_tfc[0];   c.n4[4] = 2 * FDIM * DDIM / 4;
        c.src[5] = fc[1];   c.dst[5] = p_tfc[1];   c.n4[5] = 2 * FDIM * DDIM / 4;
        c.src[6] = pred[0]; c.dst[6] = p_tpred[0]; c.n4[6] = DDIM * OSZ / 4;
        c.src[7] = pred[1]; c.dst[7] = p_tpred[1]; c.n4[7] = DDIM * OSZ / 4;
        c.src[8] = W1[0];   c.dst[8] = p_tW1[0];   c.n4[8] = DDIM * SEMH / 4;
        c.src[9] = W1[1];   c.dst[9] = p_tW1[1];   c.n4[9] = DDIM * SEMH / 4;
        cvt_kernel<<<dim3(640, 10), 256>>>(c);
    }

    // 1) combined weights W[z] = w_h[b] @ fc[b][m]
    {
        GB gb = {};
        for (int z = 0; z < 4; z++) {
            gb.A[z] = p_twhw[z >> 1];
            gb.B[z] = p_tfc[z >> 1] + (size_t)(z & 1) * FDIM * DDIM;
            gb.C[z] = p_tW[z];
        }
        dim3 g(DDIM / 128, FDIM / 128, 4);
        mma_gemm_async<4, false, 1><<<g, 256, SM_NN4>>>(gb, FDIM, DDIM, FDIM);
    }
    // 2) feat = x @ W  (batched x4, fused el/er epilogue)
    {
        GB gb = {};
        for (int z = 0; z < 4; z++) {
            gb.A[z] = p_tx[z >> 1];
            gb.B[z] = p_tW[z];
            gb.C[z] = p_feat[z];
            gb.AL[z] = (z & 2) ? (al[1] + (z & 1) * NHEAD * 64) : (al[0] + (z & 1) * NHEAD * 64);
            gb.AR[z] = (z & 2) ? (ar[1] + (z & 1) * NHEAD * 64) : (ar[0] + (z & 1) * NHEAD * 64);
            gb.EL[z] = p_el[z];
            gb.ER[z] = p_er[z];
        }
        dim3 g(DDIM / 128, (NNODES + 127) / 128, 4);
        mma_gemm_async<4, false, 4><<<g, 256, SM_NN4>>>(gb, NNODES, DDIM, FDIM);
    }

    // JOIN: CSR results needed from here on
    cudaStreamWaitEvent(0, ev_join, 0);

    // 3) aggregate (x4; softmax exp inline)
    agg_kernel<<<dim3((NNODES * 4 + 7) / 8, 4), 256>>>(bias4);

    // 4) semantic attention GEMM with fused score epilogue (x4, BM=128)
    {
        GB gb = {};
        for (int z = 0; z < 4; z++) {
            gb.A[z] = p_tz[z];
            gb.B[z] = p_tW1[z >> 1];
            gb.B1[z] = b1[z >> 1];
            gb.W2p[z] = W2[z >> 1];
            gb.WO[z] = p_w[z];
        }
        dim3 g(1, (NNODES + 127) / 128, 4);
        mma_gemm_async<4, false, 5><<<g, 256, SM_NN4>>>(gb, NNODES, SEMH, DDIM);
    }

    // 5) prediction heads with fused metapath fusion (batched x2)
    {
        PG pg = {};
        for (int b = 0; b < 2; b++) {
            pg.z0[b] = p_gz[2 * b];
            pg.z1[b] = p_gz[2 * b + 1];
            pg.w0[b] = p_w[2 * b];
            pg.w1[b] = p_w[2 * b + 1];
            pg.B[b]  = p_tpred[b];
            pg.C[b]  = (b == 0) ? h1 : h2;
            pg.C2[b] = p_th[b];
        }
        dim3 g(1, (NNODES + 63) / 64, 2);
        pred_fused_kernel<<<g, 256>>>(pg, NNODES, OSZ, DDIM);
    }
    // 6) prod = h1 @ h2^T (tf32 copies, streaming stores, ldmatrix A+B)
    {
        GB gb = {};
        gb.A[0] = p_th[0]; gb.B[0] = p_th[1]; gb.C[0] = prod;
        dim3 g((NNODES + 127) / 128, (NNODES + 127) / 128, 1);
        mma_gemm_async<4, true, 3><<<g, 256, SM_NT>>>(gb, NNODES, NNODES, OSZ);
    }
}